// round 12
// baseline (speedup 1.0000x reference)
#include <cuda_runtime.h>
#include <cuda_fp16.h>
#include <math.h>
#include <stdint.h>

#define HW 16384          // 64*256 pixels per (batch, channel) plane

// ---------------- scratch (static device globals; no allocation allowed) ----
__device__ __half g_Qh[4*128*HW];
__device__ __half g_Kh[4*128*HW];
__device__ __half g_Vh[4*128*HW];
__device__ __half g_Oh[4*128*HW];
__device__ __half g_Yh[4*256*HW];
__device__ __half g_Fh[(size_t)4*768*HW];
__device__ __half g_WPWh[256*768];
__device__ __half g_WOh[128*128];
__device__ __half g_WOUTh[128*256];
__device__ float g_WA [384*128], g_SgA[384], g_CA[384];
__device__ float g_WIN[256*128], g_SgI[256], g_CI[256];

#define QSCALE (0.17677669529663687f * 1.4426950408889634f)

// ---------------- small helpers --------------------------------------------
__device__ __forceinline__ uint32_t smem_u32(const void* p) {
    return (uint32_t)__cvta_generic_to_shared(p);
}
__device__ __forceinline__ void cp16(uint32_t dst, const void* src) {
    asm volatile("cp.async.cg.shared.global [%0], [%1], 16;\n" :: "r"(dst), "l"(src));
}
__device__ __forceinline__ void cp_commit() { asm volatile("cp.async.commit_group;\n"); }
__device__ __forceinline__ void cp_wait1()  { asm volatile("cp.async.wait_group 1;\n"); }

__device__ __forceinline__ void mma_tf32(float* c, const uint32_t* a, const uint32_t* b) {
    asm volatile("mma.sync.aligned.m16n8k8.row.col.f32.tf32.tf32.f32 "
        "{%0,%1,%2,%3}, {%4,%5,%6,%7}, {%8,%9}, {%0,%1,%2,%3};"
        : "+f"(c[0]), "+f"(c[1]), "+f"(c[2]), "+f"(c[3])
        : "r"(a[0]), "r"(a[1]), "r"(a[2]), "r"(a[3]), "r"(b[0]), "r"(b[1]));
}
__device__ __forceinline__ void mma_f16(float* c, const uint32_t* a, const uint32_t* b) {
    asm volatile("mma.sync.aligned.m16n8k16.row.col.f32.f16.f16.f32 "
        "{%0,%1,%2,%3}, {%4,%5,%6,%7}, {%8,%9}, {%0,%1,%2,%3};"
        : "+f"(c[0]), "+f"(c[1]), "+f"(c[2]), "+f"(c[3])
        : "r"(a[0]), "r"(a[1]), "r"(a[2]), "r"(a[3]), "r"(b[0]), "r"(b[1]));
}
__device__ __forceinline__ void ldsm4(uint32_t* r, uint32_t addr) {
    asm volatile("ldmatrix.sync.aligned.m8n8.x4.shared.b16 {%0,%1,%2,%3}, [%4];"
        : "=r"(r[0]), "=r"(r[1]), "=r"(r[2]), "=r"(r[3]) : "r"(addr));
}
__device__ __forceinline__ void ldsm2t(uint32_t* r, uint32_t addr) {
    asm volatile("ldmatrix.sync.aligned.m8n8.x2.trans.shared.b16 {%0,%1}, [%2];"
        : "=r"(r[0]), "=r"(r[1]) : "r"(addr));
}
__device__ __forceinline__ float fexp2(float x) {
    float r; asm("ex2.approx.ftz.f32 %0, %1;" : "=f"(r) : "f"(x)); return r;
}
__device__ __forceinline__ uint32_t packh2(float a, float b) {
    __half2 h = __floats2half2_rn(a, b);
    return *(uint32_t*)&h;
}

// ---------------- fold LN gamma/beta into GEMM weights ---------------------
__global__ void prep_kernel(const float* __restrict__ wq,  const float* __restrict__ bq,
                            const float* __restrict__ wkv, const float* __restrict__ bkv,
                            const float* __restrict__ an_g, const float* __restrict__ an_b,
                            const float* __restrict__ anc_g, const float* __restrict__ anc_b,
                            const float* __restrict__ w_in, const float* __restrict__ b_in,
                            const float* __restrict__ fn_g, const float* __restrict__ fn_b) {
    int r = blockIdx.x, t = threadIdx.x;   // 640 blocks x 128 threads
    __shared__ float red[2][4];
    float wl, gg, bb, extra;
    float *Wdst, *Sgd, *Cd;
    if (r < 128)      { wl = wq [r*128 + t];        gg = an_g[t];  bb = an_b[t];  extra = bq [r];
                        Wdst = g_WA  + r*128;        Sgd = g_SgA + r;  Cd = g_CA + r; }
    else if (r < 384) { int rr = r - 128;
                        wl = wkv[rr*128 + t];       gg = anc_g[t]; bb = anc_b[t]; extra = bkv[rr];
                        Wdst = g_WA  + r*128;        Sgd = g_SgA + r;  Cd = g_CA + r; }
    else              { int rr = r - 384;
                        wl = w_in[rr*128 + t];      gg = fn_g[t];  bb = fn_b[t];  extra = b_in[rr];
                        Wdst = g_WIN + rr*128;       Sgd = g_SgI + rr; Cd = g_CI + rr; }
    float wg = wl * gg;
    Wdst[t] = wg;
    float s1 = wg, s2 = wl * bb;
    #pragma unroll
    for (int off = 16; off; off >>= 1) {
        s1 += __shfl_down_sync(0xffffffffu, s1, off);
        s2 += __shfl_down_sync(0xffffffffu, s2, off);
    }
    if ((t & 31) == 0) { red[0][t >> 5] = s1; red[1][t >> 5] = s2; }
    __syncthreads();
    if (t == 0) {
        float a = red[0][0] + red[0][1] + red[0][2] + red[0][3];
        float b = red[1][0] + red[1][1] + red[1][2] + red[1][3];
        *Sgd = a; *Cd = b + extra;
    }
}

// ---------------- convert fp32 weights to fp16 ------------------------------
__global__ void convh_kernel(const float* __restrict__ W, __half* __restrict__ Wh, int n) {
    int i = blockIdx.x * 256 + threadIdx.x;
    if (i < n) Wh[i] = __float2half(W[i]);
}

// ---------------- tf32 GEMM, LN-fused (MODE 0: q/kv fp16 out; MODE 2: w_in) -
template<int K, int MODE, int BM, int BN>
__global__ void __launch_bounds__(256)
gemm_tc(const float* __restrict__ A, const float* __restrict__ B,
        float* __restrict__ O0, float* __restrict__ O1, float* __restrict__ O2,
        const float* __restrict__ Sg, const float* __restrict__ Cst,
        const float* __restrict__ X1, const float* __restrict__ X2, float eps) {
    constexpr int BK = 16, ST = 3;
    constexpr int KT = K / BK;
    constexpr int ASP = 20;
    constexpr int BSP = BN + 8;
    constexpr int ASZ = BM * ASP;
    constexpr int BSZ = BK * BSP;
    constexpr int NA = BM / 64;
    constexpr int NB = BN / 64;
    constexpr int WN = (BM == 128) ? 4 : 2;
    constexpr int SH = (BN == 64) ? 4 : 2;
    constexpr int RT = 16 / SH;
    extern __shared__ float smf[];
    float* As = smf;
    float* Bs = smf + ST * ASZ;
    __shared__ float sst[2][SH][BN];

    int tid = threadIdx.x, lane = tid & 31, wid = tid >> 5;
    int wm = wid / WN, wn = wid % WN;
    int n0 = blockIdx.x * BN, m0 = blockIdx.y * BM, u = blockIdx.z;
    const float* Ap = A + (size_t)m0 * K;
    const float* Bp;
    if (MODE == 0) Bp = (u < 2 ? X1 : X2) + (size_t)(u & 1) * 128 * HW + n0;
    else           Bp = B + (size_t)u * K * HW + n0;

    float acc[4][4][4];
    #pragma unroll
    for (int i = 0; i < 4; i++)
        #pragma unroll
        for (int j = 0; j < 4; j++)
            #pragma unroll
            for (int e = 0; e < 4; e++) acc[i][j][e] = 0.f;

    int ar[NA], ac[NA], br[NB], bc[NB];
    #pragma unroll
    for (int i = 0; i < NA; i++) {
        int idx = tid + i * 256;
        ar[i] = idx >> 2; ac[i] = (idx & 3) << 2;
    }
    #pragma unroll
    for (int i = 0; i < NB; i++) {
        int idx = tid + i * 256;
        br[i] = idx / (BN / 4); bc[i] = (idx % (BN / 4)) << 2;
    }
    int sc = tid % BN, sg = tid / BN;
    float s_sum = 0.f, s_sq = 0.f;
    int lm = lane >> 3;
    int loff = (((lane & 7) + (lm & 1) * 8)) * ASP + (lm >> 1) * 4;
    uint32_t as_base = smem_u32(As);

    #define PREFETCH(sidx, k0)                                                     \
        {   _Pragma("unroll")                                                      \
            for (int i = 0; i < NA; i++)                                           \
                cp16(smem_u32(&As[(sidx) * ASZ + ar[i] * ASP + ac[i]]),            \
                     Ap + (size_t)ar[i] * K + (k0) + ac[i]);                       \
            _Pragma("unroll")                                                      \
            for (int i = 0; i < NB; i++)                                           \
                cp16(smem_u32(&Bs[(sidx) * BSZ + br[i] * BSP + bc[i]]),            \
                     Bp + (size_t)((k0) + br[i]) * HW + bc[i]);                    \
        }

    PREFETCH(0, 0); cp_commit();
    if (KT > 1) PREFETCH(1, BK);
    cp_commit();

    for (int kt = 0; kt < KT; kt++) {
        cp_wait1();
        __syncthreads();
        int st = kt % ST;
        const float* bs = Bs + st * BSZ;
        #pragma unroll
        for (int rr = 0; rr < RT; rr++) {
            float v = bs[(sg * RT + rr) * BSP + sc];
            s_sum += v; s_sq += v * v;
        }
        uint32_t abase = as_base + (uint32_t)(st * ASZ + wm * 64 * ASP + loff) * 4;
        #pragma unroll
        for (int s8 = 0; s8 < 2; s8++) {
            uint32_t a[4][4], b[4][2];
            #pragma unroll
            for (int mt = 0; mt < 4; mt++)
                ldsm4(a[mt], abase + (uint32_t)(mt * 16 * ASP + s8 * 8) * 4);
            #pragma unroll
            for (int nt = 0; nt < 4; nt++) {
                const float* bp = bs + (s8 * 8 + (lane & 3)) * BSP
                                     + wn * 32 + nt * 8 + (lane >> 2);
                b[nt][0] = __float_as_uint(bp[0]);
                b[nt][1] = __float_as_uint(bp[4 * BSP]);
            }
            #pragma unroll
            for (int mt = 0; mt < 4; mt++)
                #pragma unroll
                for (int nt = 0; nt < 4; nt++)
                    mma_tf32(acc[mt][nt], a[mt], b[nt]);
        }
        if (kt + 2 < KT) PREFETCH((kt + 2) % ST, (kt + 2) * BK);
        cp_commit();
    }
    #undef PREFETCH

    sst[0][sg][sc] = s_sum;
    sst[1][sg][sc] = s_sq;
    __syncthreads();
    if (tid < BN) {
        float S = 0.f, SS = 0.f;
        #pragma unroll
        for (int g = 0; g < SH; g++) { S += sst[0][g][tid]; SS += sst[1][g][tid]; }
        float m = S * (1.f / 128.f);
        float var = SS * (1.f / 128.f) - m * m;
        sst[0][0][tid] = m;
        sst[1][0][tid] = rsqrtf(var + eps);
    }
    __syncthreads();

    #pragma unroll
    for (int mt = 0; mt < 4; mt++) {
        #pragma unroll
        for (int half = 0; half < 2; half++) {
            int row = m0 + wm * 64 + mt * 16 + (lane >> 2) + half * 8;
            float sgr = Sg[row], cstr = Cst[row];
            #pragma unroll
            for (int nt = 0; nt < 4; nt++) {
                #pragma unroll
                for (int e = 0; e < 2; e++) {
                    int pl = wn * 32 + nt * 8 + (lane & 3) * 2 + e;
                    int p = n0 + pl;
                    float v = acc[mt][nt][half * 2 + e];
                    float mv = sst[0][0][pl], rv = sst[1][0][pl];
                    v = rv * v + (cstr - mv * rv * sgr);
                    if (MODE == 0) {
                        if (row < 128)
                            ((__half*)O0)[((size_t)u * 128 + row) * HW + p] = __float2half(v * QSCALE);
                        else if (row < 256)
                            ((__half*)O1)[((size_t)(u ^ 2) * 128 + (row - 128)) * HW + p] = __float2half(v);
                        else
                            ((__half*)O2)[((size_t)(u ^ 2) * 128 + (row - 256)) * HW + p] = __float2half(v);
                    } else {
                        v = v / (1.f + __expf(-v));
                        ((__half*)O0)[((size_t)u * 256 + row) * HW + p] = __float2half(v);
                    }
                }
            }
        }
    }
}

// ---------------- generalized fp16 GEMM (MODE 1: wo; 3: w_pw; 4: w_out) -----
template<int K, int MODE, int BM, int BN>
__global__ void __launch_bounds__(256)
gemm_f16h(const __half* __restrict__ A, const __half* __restrict__ B,
          float* __restrict__ O0, __half* __restrict__ Yh,
          const float* __restrict__ X1, const float* __restrict__ X2,
          const float* __restrict__ bias) {
    constexpr int BK = 32, ST = 3;
    constexpr int KT = K / BK;
    constexpr int ASPH = 40;
    constexpr int BSPH = BN + 8;
    constexpr int ASZ = BM * ASPH;
    constexpr int BSZ = BK * BSPH;
    constexpr int NA = BM / 64;              // cp16 per thread for A
    constexpr int NB = BN / 64;              // cp16 per thread for B
    constexpr int WN = (BM == 128) ? 4 : 2;
    extern __shared__ __half smh[];
    __half* As = smh;
    __half* Bs = smh + ST * ASZ;

    int tid = threadIdx.x, lane = tid & 31, wid = tid >> 5;
    int wm = wid / WN, wn = wid % WN;
    int n0 = blockIdx.x * BN, u = blockIdx.z;
    const __half* Bp = B + (size_t)u * K * HW + n0;

    float acc[4][4][4];
    #pragma unroll
    for (int i = 0; i < 4; i++)
        #pragma unroll
        for (int j = 0; j < 4; j++)
            #pragma unroll
            for (int e = 0; e < 4; e++) acc[i][j][e] = 0.f;

    int aro[NA], aco[NA], brw[NB], bcl[NB];
    #pragma unroll
    for (int i = 0; i < NA; i++) {
        int idx = tid + i * 256;
        aro[i] = idx >> 2; aco[i] = (idx & 3) << 3;
    }
    #pragma unroll
    for (int i = 0; i < NB; i++) {
        int idx = tid + i * 256;
        brw[i] = idx / (BN / 8); bcl[i] = (idx % (BN / 8)) << 3;
    }

    int arow_l = lane & 15, acol_l = (lane >> 4) << 3;
    int brow_l = (lane & 7) + ((lane >> 3) & 1) * 8;
    uint32_t as_base = smem_u32(As);
    uint32_t bs_base = smem_u32(Bs);

    #define PF16(sidx, k0)                                                         \
        {   _Pragma("unroll")                                                      \
            for (int i = 0; i < NA; i++)                                           \
                cp16(smem_u32(&As[(sidx) * ASZ + aro[i] * ASPH + aco[i]]),         \
                     A + (size_t)aro[i] * K + (k0) + aco[i]);                      \
            _Pragma("unroll")                                                      \
            for (int i = 0; i < NB; i++)                                           \
                cp16(smem_u32(&Bs[(sidx) * BSZ + brw[i] * BSPH + bcl[i]]),         \
                     Bp + (size_t)((k0) + brw[i]) * HW + bcl[i]);                  \
        }

    PF16(0, 0); cp_commit();
    if (KT > 1) PF16(1, BK);
    cp_commit();

    for (int kt = 0; kt < KT; kt++) {
        cp_wait1();
        __syncthreads();
        int st = kt % ST;
        uint32_t abase = as_base + (uint32_t)(st * ASZ + (wm * 64 + arow_l) * ASPH + acol_l) * 2;
        uint32_t bbase = bs_base + (uint32_t)(st * BSZ + brow_l * BSPH + wn * 32) * 2;
        #pragma unroll
        for (int s16 = 0; s16 < 2; s16++) {
            uint32_t a[4][4], b[4][2];
            #pragma unroll
            for (int mt = 0; mt < 4; mt++)
                ldsm4(a[mt], abase + (uint32_t)(mt * 16 * ASPH + s16 * 16) * 2);
            #pragma unroll
            for (int nt = 0; nt < 4; nt++)
                ldsm2t(b[nt], bbase + (uint32_t)(s16 * 16 * BSPH + nt * 8) * 2);
            #pragma unroll
            for (int mt = 0; mt < 4; mt++)
                #pragma unroll
                for (int nt = 0; nt < 4; nt++)
                    mma_f16(acc[mt][nt], a[mt], b[nt]);
        }
        if (kt + 2 < KT) PF16((kt + 2) % ST, (kt + 2) * BK);
        cp_commit();
    }
    #undef PF16

    #pragma unroll
    for (int mt = 0; mt < 4; mt++) {
        #pragma unroll
        for (int half = 0; half < 2; half++) {
            int row = wm * 64 + mt * 16 + (lane >> 2) + half * 8;
            float br2 = bias[row];
            #pragma unroll
            for (int nt = 0; nt < 4; nt++) {
                #pragma unroll
                for (int e = 0; e < 2; e++) {
                    int p = n0 + wn * 32 + nt * 8 + (lane & 3) * 2 + e;
                    float v = acc[mt][nt][half * 2 + e];
                    if (MODE == 1) {
                        float res = ((u < 2 ? X1 : X2))[((size_t)(u & 1) * 128 + row) * HW + p];
                        size_t idx = ((size_t)u * 128 + row) * HW + p;
                        O0[idx] = v + br2 + res;
                    } else if (MODE == 3) {
                        v += br2;
                        v = v / (1.f + __expf(-v));
                        size_t idx = ((size_t)u * 256 + row) * HW + p;
                        Yh[idx] = __float2half(__half2float(Yh[idx]) + v);
                    } else {
                        size_t idx = ((size_t)u * 128 + row) * HW + p;
                        O0[idx] += v + br2;
                    }
                }
            }
        }
    }
}

// ---------------- fp16 flash attention (register-direct P reuse) -------------
#define AT2_QS 0
#define AT2_VS 10240
#define AT2_KT 20480
#define AT2_HALVES 28928
#define ATTN2_SMEM (AT2_HALVES * 2 + 256 * 4 + 32 * 4)

__global__ void __launch_bounds__(256, 2)
attn_f16(const __half* __restrict__ Q, const __half* __restrict__ K,
         const __half* __restrict__ V, __half* __restrict__ O) {
    int blk = blockIdx.x;                  // b*256 + n*64 + h
    int h = blk & 63, n = (blk >> 6) & 3, b = blk >> 8;
    size_t base = ((size_t)(b * 128 + n * 32) * 64 + h) * 256;
    extern __shared__ __half smh2[];
    __half* Qs = smh2 + AT2_QS;            // [i][d] pitch 40
    __half* Vs = smh2 + AT2_VS;            // [j][d] pitch 40
    __half* Kt = smh2 + AT2_KT;            // [d][j] pitch 264
    float* V2 = (float*)(smh2 + AT2_HALVES);
    float* Vsum = V2 + 256;
    int tid = threadIdx.x, lane = tid & 31, w = tid >> 5;

    #pragma unroll 4
    for (int dd = 0; dd < 32; dd++) {
        Qs[tid * 40 + dd] = Q[base + (size_t)dd * HW + tid];
        Vs[tid * 40 + dd] = V[base + (size_t)dd * HW + tid];
    }
    #pragma unroll
    for (int i = 0; i < 4; i++) {
        int idx = tid + i * 256;
        int row = idx >> 5, seg = idx & 31;
        *(uint4*)&Kt[row * 264 + seg * 8] =
            *(const uint4*)&K[base + (size_t)row * HW + seg * 8];
    }
    __syncthreads();
    {
        float s = 0.f;
        #pragma unroll 8
        for (int jj = 0; jj < 32; jj++) s += __half2float(Vs[(w * 32 + jj) * 40 + lane]);
        V2[w * 32 + lane] = s;
    }

    int i0 = w * 32;
    uint32_t qa[2][2][4];
    #pragma unroll
    for (int mt = 0; mt < 2; mt++)
        #pragma unroll
        for (int dk = 0; dk < 2; dk++)
            ldsm4(qa[mt][dk],
                  smem_u32(&Qs[(i0 + mt * 16 + (lane & 15)) * 40 + dk * 16 + ((lane >> 4) << 3)]));
    int brow = (lane & 7) + ((lane >> 3) & 1) * 8;

    float l0[2] = {0.f, 0.f}, l1[2] = {0.f, 0.f};
    float o[2][4][4];
    #pragma unroll
    for (int mt = 0; mt < 2; mt++)
        #pragma unroll
        for (int dt = 0; dt < 4; dt++)
            #pragma unroll
            for (int e = 0; e < 4; e++) o[mt][dt][e] = 0.f;

    for (int j0 = 0; j0 < 256; j0 += 16) {
        float s[2][2][4];
        #pragma unroll
        for (int mt = 0; mt < 2; mt++)
            #pragma unroll
            for (int jh = 0; jh < 2; jh++)
                #pragma unroll
                for (int e = 0; e < 4; e++) s[mt][jh][e] = 0.f;
        uint32_t bS[2][2][2];
        #pragma unroll
        for (int dk = 0; dk < 2; dk++)
            #pragma unroll
            for (int jh = 0; jh < 2; jh++)
                ldsm2t(bS[dk][jh], smem_u32(&Kt[(dk * 16 + brow) * 264 + j0 + jh * 8]));
        #pragma unroll
        for (int mt = 0; mt < 2; mt++)
            #pragma unroll
            for (int jh = 0; jh < 2; jh++)
                #pragma unroll
                for (int dk = 0; dk < 2; dk++)
                    mma_f16(s[mt][jh], qa[mt][dk], bS[dk][jh]);
        uint32_t pa[2][4];
        #pragma unroll
        for (int mt = 0; mt < 2; mt++) {
            float p00 = fexp2(s[mt][0][0]), p01 = fexp2(s[mt][0][1]);
            float p02 = fexp2(s[mt][0][2]), p03 = fexp2(s[mt][0][3]);
            float p10 = fexp2(s[mt][1][0]), p11 = fexp2(s[mt][1][1]);
            float p12 = fexp2(s[mt][1][2]), p13 = fexp2(s[mt][1][3]);
            l0[mt] += p00 + p01 + p10 + p11;
            l1[mt] += p02 + p03 + p12 + p13;
            pa[mt][0] = packh2(p00, p01);
            pa[mt][1] = packh2(p02, p03);
            pa[mt][2] = packh2(p10, p11);
            pa[mt][3] = packh2(p12, p13);
        }
        uint32_t bV[4][2];
        #pragma unroll
        for (int dt = 0; dt < 4; dt++)
            ldsm2t(bV[dt], smem_u32(&Vs[(j0 + brow) * 40 + dt * 8]));
        #pragma unroll
        for (int mt = 0; mt < 2; mt++)
            #pragma unroll
            for (int dt = 0; dt < 4; dt++)
                mma_f16(o[mt][dt], pa[mt], bV[dt]);
    }
    #pragma unroll
    for (int mt = 0; mt < 2; mt++) {
        l0[mt] += __shfl_xor_sync(0xffffffffu, l0[mt], 1);
        l0[mt] += __shfl_xor_sync(0xffffffffu, l0[mt], 2);
        l1[mt] += __shfl_xor_sync(0xffffffffu, l1[mt], 1);
        l1[mt] += __shfl_xor_sync(0xffffffffu, l1[mt], 2);
    }

    __syncthreads();
    float* Ow = (float*)smh2 + w * 32 * 36;     // reuse Qs/Vs region
    #pragma unroll
    for (int mt = 0; mt < 2; mt++)
        #pragma unroll
        for (int hf = 0; hf < 2; hf++) {
            float inv = 1.f / (hf == 0 ? l0[mt] : l1[mt]);
            int row = mt * 16 + (lane >> 2) + hf * 8;
            #pragma unroll
            for (int dt = 0; dt < 4; dt++) {
                Ow[row * 36 + dt * 8 + (lane & 3) * 2]     = o[mt][dt][hf * 2]     * inv;
                Ow[row * 36 + dt * 8 + (lane & 3) * 2 + 1] = o[mt][dt][hf * 2 + 1] * inv;
            }
        }
    if (tid < 32) {
        float s = 0.f;
        #pragma unroll
        for (int ww = 0; ww < 8; ww++) s += V2[ww * 32 + tid];
        Vsum[tid] = s;
    }
    __syncthreads();
    const float eps = 1e-6f;
    const float norm = 1.f / (1.f + 256.f * eps);
    #pragma unroll 4
    for (int d = 0; d < 32; d++) {
        float val = (Ow[lane * 36 + d] + eps * Vsum[d]) * norm;
        O[base + (size_t)d * HW + i0 + lane] = __float2half(val);
    }
}

// ---------------- depthwise 3x3 / 5x5 / 7x7: half in, half out --------------
__global__ void dw_kernel(const __half* __restrict__ Y,
                          const float* __restrict__ w3, const float* __restrict__ b3,
                          const float* __restrict__ w5, const float* __restrict__ b5,
                          const float* __restrict__ w7, const float* __restrict__ b7,
                          __half* __restrict__ F) {
    __shared__ float S[14][70];
    __shared__ float wgt[84];
    int z = blockIdx.z; int ch = z & 255; int u = z >> 8;
    int w0 = blockIdx.x * 64, h0 = blockIdx.y * 8;
    int tid = threadIdx.x;
    if (tid < 9)       wgt[tid] = w3[ch * 9 + tid];
    else if (tid < 34) wgt[tid] = w5[ch * 25 + tid - 9];
    else if (tid < 83) wgt[tid] = w7[ch * 49 + tid - 34];
    const __half* Yp = Y + ((size_t)u * 256 + ch) * HW;
    for (int i = tid; i < 980; i += 256) {
        int r = i / 70, c = i % 70;
        int gh = h0 - 3 + r, gw = w0 - 3 + c;
        float v = 0.f;
        if ((unsigned)gh < 64u && (unsigned)gw < 256u) v = __half2float(Yp[gh * 256 + gw]);
        S[r][c] = v;
    }
    __syncthreads();
    int tx = tid & 63, ty = tid >> 6;
    float bb3 = b3[ch], bb5 = b5[ch], bb7 = b7[ch];
    #pragma unroll
    for (int rr = 0; rr < 2; rr++) {
        int rc = ty + rr * 4 + 3, cc = tx + 3;
        float f3 = bb3, f5 = bb5, f7 = bb7;
        #pragma unroll
        for (int dy = -3; dy <= 3; dy++)
            #pragma unroll
            for (int dx = -3; dx <= 3; dx++) {
                float v = S[rc + dy][cc + dx];
                f7 += v * wgt[34 + (dy + 3) * 7 + (dx + 3)];
                if (dy >= -2 && dy <= 2 && dx >= -2 && dx <= 2)
                    f5 += v * wgt[9 + (dy + 2) * 5 + (dx + 2)];
                if (dy >= -1 && dy <= 1 && dx >= -1 && dx <= 1)
                    f3 += v * wgt[(dy + 1) * 3 + (dx + 1)];
            }
        size_t pix = (size_t)(h0 + ty + rr * 4) * 256 + (w0 + tx);
        size_t ob = (size_t)u * 768 * HW + pix;
        F[ob + (size_t) ch        * HW] = __float2half(f3);
        F[ob + (size_t)(256 + ch) * HW] = __float2half(f5);
        F[ob + (size_t)(512 + ch) * HW] = __float2half(f7);
    }
}

// ---------------- host launcher --------------------------------------------
extern "C" void kernel_launch(void* const* d_in, const int* in_sizes, int n_in,
                              void* d_out, int out_size) {
    const float* feats1 = (const float*)d_in[0];
    const float* feats2 = (const float*)d_in[1];
    const float* an_g  = (const float*)d_in[2];
    const float* an_b  = (const float*)d_in[3];
    const float* anc_g = (const float*)d_in[4];
    const float* anc_b = (const float*)d_in[5];
    const float* wq    = (const float*)d_in[6];
    const float* bq    = (const float*)d_in[7];
    const float* wkv   = (const float*)d_in[8];
    const float* bkv   = (const float*)d_in[9];
    const float* wo    = (const float*)d_in[10];
    const float* bo    = (const float*)d_in[11];
    const float* fn_g  = (const float*)d_in[12];
    const float* fn_b  = (const float*)d_in[13];
    const float* w_in  = (const float*)d_in[14];
    const float* b_in  = (const float*)d_in[15];
    const float* w_dw3 = (const float*)d_in[16];
    const float* b_dw3 = (const float*)d_in[17];
    const float* w_dw5 = (const float*)d_in[18];
    const float* b_dw5 = (const float*)d_in[19];
    const float* w_dw7 = (const float*)d_in[20];
    const float* b_dw7 = (const float*)d_in[21];
    const float* w_pw  = (const float*)d_in[22];
    const float* b_pw  = (const float*)d_in[23];
    const float* w_out = (const float*)d_in[24];
    const float* b_out = (const float*)d_in[25];
    float* dout = (float*)d_out;

    float *WA, *SgA, *CA, *WIN, *SgI, *CI;
    __half *Qh, *Kh, *Vh, *Oh, *Yh, *Fh, *WPWh, *WOh, *WOUTh;
    cudaGetSymbolAddress((void**)&Qh, g_Qh);
    cudaGetSymbolAddress((void**)&Kh, g_Kh);
    cudaGetSymbolAddress((void**)&Vh, g_Vh);
    cudaGetSymbolAddress((void**)&Oh, g_Oh);
    cudaGetSymbolAddress((void**)&Yh, g_Yh);
    cudaGetSymbolAddress((void**)&Fh, g_Fh);
    cudaGetSymbolAddress((void**)&WPWh, g_WPWh);
    cudaGetSymbolAddress((void**)&WOh, g_WOh);
    cudaGetSymbolAddress((void**)&WOUTh, g_WOUTh);
    cudaGetSymbolAddress((void**)&WA, g_WA);
    cudaGetSymbolAddress((void**)&SgA, g_SgA);
    cudaGetSymbolAddress((void**)&CA, g_CA);
    cudaGetSymbolAddress((void**)&WIN, g_WIN);
    cudaGetSymbolAddress((void**)&SgI, g_SgI);
    cudaGetSymbolAddress((void**)&CI, g_CI);

    const int smA  = 3 * (128 * 20 + 16 * 136) * 4;   // tf32 BM=128/BN=128
    const int smB  = 3 * (256 * 20 + 16 * 72)  * 4;   // tf32 BM=256/BN=64
    const int smH3 = 3 * (256 * 40 + 32 * 72)  * 2;   // f16 BM=256/BN=64: 75264
    const int smH1 = 3 * (128 * 40 + 32 * 136) * 2;   // f16 BM=128/BN=128: 56832
    cudaFuncSetAttribute((const void*)gemm_tc<128, 0, 128, 128>, cudaFuncAttributeMaxDynamicSharedMemorySize, smA);
    cudaFuncSetAttribute((const void*)gemm_tc<128, 2, 256, 64>,  cudaFuncAttributeMaxDynamicSharedMemorySize, smB);
    cudaFuncSetAttribute((const void*)gemm_f16h<128, 1, 128, 128>, cudaFuncAttributeMaxDynamicSharedMemorySize, smH1);
    cudaFuncSetAttribute((const void*)gemm_f16h<768, 3, 256, 64>,  cudaFuncAttributeMaxDynamicSharedMemorySize, smH3);
    cudaFuncSetAttribute((const void*)gemm_f16h<256, 4, 128, 128>, cudaFuncAttributeMaxDynamicSharedMemorySize, smH1);
    cudaFuncSetAttribute((const void*)attn_f16, cudaFuncAttributeMaxDynamicSharedMemorySize, ATTN2_SMEM);

    // 1. weight prep + fp16 conversions
    prep_kernel<<<640, 128>>>(wq, bq, wkv, bkv, an_g, an_b, anc_g, anc_b,
                              w_in, b_in, fn_g, fn_b);
    convh_kernel<<<768, 256>>>(w_pw, WPWh, 256 * 768);
    convh_kernel<<<64, 256>>>(wo, WOh, 128 * 128);
    convh_kernel<<<128, 256>>>(w_out, WOUTh, 128 * 256);
    // 2. fused LN + q/kv projection -> fp16 Q (pre-scaled), K, V
    gemm_tc<128, 0, 128, 128><<<dim3(128, 3, 4), 256, smA>>>(WA, nullptr,
                                                             (float*)Qh, (float*)Kh, (float*)Vh,
                                                             SgA, CA, feats1, feats2, 1e-6f);
    // 3. fp16 flash attention -> fp16 O
    attn_f16<<<1024, 256, ATTN2_SMEM>>>(Qh, Kh, Vh, Oh);
    // 4. fp16 output projection + residual(feats) -> d_out (fp32)
    gemm_f16h<128, 1, 128, 128><<<dim3(128, 1, 4), 256, smH1>>>(WOh, Oh, dout, nullptr,
                                                                feats1, feats2, bo);
    // 5. fused LN + w_in + SiLU -> Yh (fp16)
    gemm_tc<128, 2, 256, 64><<<dim3(256, 1, 4), 256, smB>>>(WIN, dout, (float*)Yh, nullptr, nullptr,
                                                            SgI, CI, nullptr, nullptr, 1e-5f);
    // 6. depthwise 3/5/7 (fp16 in) -> Fh (fp16)
    dw_kernel<<<dim3(4, 8, 1024), 256>>>(Yh, w_dw3, b_dw3, w_dw5, b_dw5, w_dw7, b_dw7, Fh);
    // 7. fp16 pointwise GEMM + SiLU, Yh += (fp16 RMW)
    gemm_f16h<768, 3, 256, 64><<<dim3(256, 1, 4), 256, smH3>>>(WPWh, Fh, nullptr, Yh,
                                                               nullptr, nullptr, b_pw);
    // 8. fp16 w_out GEMM, dout +=
    gemm_f16h<256, 4, 128, 128><<<dim3(128, 1, 4), 256, smH1>>>(WOUTh, Yh, dout, nullptr,
                                                                nullptr, nullptr, b_out);
}

// round 13
// speedup vs baseline: 1.2082x; 1.2082x over previous
#include <cuda_runtime.h>
#include <cuda_fp16.h>
#include <math.h>
#include <stdint.h>

#define HW 16384          // 64*256 pixels per (batch, channel) plane

// ---------------- scratch (static device globals; no allocation allowed) ----
__device__ __half g_Qh[4*128*HW];
__device__ __half g_Kh[4*128*HW];
__device__ __half g_Vh[4*128*HW];
__device__ __half g_Oh[4*128*HW];
__device__ float g_Y [4*256*HW];
__device__ __half g_Fh[(size_t)4*768*HW];
__device__ __half g_WPWh[256*768];
__device__ __half g_WOh[128*128];
__device__ float g_WA [384*128], g_SgA[384], g_CA[384];
__device__ float g_WIN[256*128], g_SgI[256], g_CI[256];

#define QSCALE (0.17677669529663687f * 1.4426950408889634f)

// ---------------- small helpers --------------------------------------------
__device__ __forceinline__ uint32_t smem_u32(const void* p) {
    return (uint32_t)__cvta_generic_to_shared(p);
}
__device__ __forceinline__ void cp16(uint32_t dst, const void* src) {
    asm volatile("cp.async.cg.shared.global [%0], [%1], 16;\n" :: "r"(dst), "l"(src));
}
__device__ __forceinline__ void cp_commit() { asm volatile("cp.async.commit_group;\n"); }
__device__ __forceinline__ void cp_wait1()  { asm volatile("cp.async.wait_group 1;\n"); }

__device__ __forceinline__ void mma_tf32(float* c, const uint32_t* a, const uint32_t* b) {
    asm volatile("mma.sync.aligned.m16n8k8.row.col.f32.tf32.tf32.f32 "
        "{%0,%1,%2,%3}, {%4,%5,%6,%7}, {%8,%9}, {%0,%1,%2,%3};"
        : "+f"(c[0]), "+f"(c[1]), "+f"(c[2]), "+f"(c[3])
        : "r"(a[0]), "r"(a[1]), "r"(a[2]), "r"(a[3]), "r"(b[0]), "r"(b[1]));
}
__device__ __forceinline__ void mma_f16(float* c, const uint32_t* a, const uint32_t* b) {
    asm volatile("mma.sync.aligned.m16n8k16.row.col.f32.f16.f16.f32 "
        "{%0,%1,%2,%3}, {%4,%5,%6,%7}, {%8,%9}, {%0,%1,%2,%3};"
        : "+f"(c[0]), "+f"(c[1]), "+f"(c[2]), "+f"(c[3])
        : "r"(a[0]), "r"(a[1]), "r"(a[2]), "r"(a[3]), "r"(b[0]), "r"(b[1]));
}
__device__ __forceinline__ void ldsm4(uint32_t* r, uint32_t addr) {
    asm volatile("ldmatrix.sync.aligned.m8n8.x4.shared.b16 {%0,%1,%2,%3}, [%4];"
        : "=r"(r[0]), "=r"(r[1]), "=r"(r[2]), "=r"(r[3]) : "r"(addr));
}
__device__ __forceinline__ void ldsm2t(uint32_t* r, uint32_t addr) {
    asm volatile("ldmatrix.sync.aligned.m8n8.x2.trans.shared.b16 {%0,%1}, [%2];"
        : "=r"(r[0]), "=r"(r[1]) : "r"(addr));
}
__device__ __forceinline__ float fexp2(float x) {
    float r; asm("ex2.approx.ftz.f32 %0, %1;" : "=f"(r) : "f"(x)); return r;
}
__device__ __forceinline__ uint32_t packh2(float a, float b) {
    __half2 h = __floats2half2_rn(a, b);
    return *(uint32_t*)&h;
}

// ---------------- fold LN gamma/beta into GEMM weights ---------------------
__global__ void prep_kernel(const float* __restrict__ wq,  const float* __restrict__ bq,
                            const float* __restrict__ wkv, const float* __restrict__ bkv,
                            const float* __restrict__ an_g, const float* __restrict__ an_b,
                            const float* __restrict__ anc_g, const float* __restrict__ anc_b,
                            const float* __restrict__ w_in, const float* __restrict__ b_in,
                            const float* __restrict__ fn_g, const float* __restrict__ fn_b) {
    int r = blockIdx.x, t = threadIdx.x;   // 640 blocks x 128 threads
    __shared__ float red[2][4];
    float wl, gg, bb, extra;
    float *Wdst, *Sgd, *Cd;
    if (r < 128)      { wl = wq [r*128 + t];        gg = an_g[t];  bb = an_b[t];  extra = bq [r];
                        Wdst = g_WA  + r*128;        Sgd = g_SgA + r;  Cd = g_CA + r; }
    else if (r < 384) { int rr = r - 128;
                        wl = wkv[rr*128 + t];       gg = anc_g[t]; bb = anc_b[t]; extra = bkv[rr];
                        Wdst = g_WA  + r*128;        Sgd = g_SgA + r;  Cd = g_CA + r; }
    else              { int rr = r - 384;
                        wl = w_in[rr*128 + t];      gg = fn_g[t];  bb = fn_b[t];  extra = b_in[rr];
                        Wdst = g_WIN + rr*128;       Sgd = g_SgI + rr; Cd = g_CI + rr; }
    float wg = wl * gg;
    Wdst[t] = wg;
    float s1 = wg, s2 = wl * bb;
    #pragma unroll
    for (int off = 16; off; off >>= 1) {
        s1 += __shfl_down_sync(0xffffffffu, s1, off);
        s2 += __shfl_down_sync(0xffffffffu, s2, off);
    }
    if ((t & 31) == 0) { red[0][t >> 5] = s1; red[1][t >> 5] = s2; }
    __syncthreads();
    if (t == 0) {
        float a = red[0][0] + red[0][1] + red[0][2] + red[0][3];
        float b = red[1][0] + red[1][1] + red[1][2] + red[1][3];
        *Sgd = a; *Cd = b + extra;
    }
}

// ---------------- convert fp32 weights to fp16 ------------------------------
__global__ void convh_kernel(const float* __restrict__ W, __half* __restrict__ Wh, int n) {
    int i = blockIdx.x * 256 + threadIdx.x;
    if (i < n) Wh[i] = __float2half(W[i]);
}

// ---------------- tf32 tensor-core GEMM (round-11 proven config) ------------
template<int K, int MODE, int BM, int BN>
__global__ void __launch_bounds__(256)
gemm_tc(const float* __restrict__ A, const float* __restrict__ B,
        float* __restrict__ O0, float* __restrict__ O1, float* __restrict__ O2,
        const float* __restrict__ Sg, const float* __restrict__ Cst,
        const float* __restrict__ X1, const float* __restrict__ X2,
        const float* __restrict__ bias, float eps) {
    constexpr int BK = 16, ST = 3;
    constexpr int KT = K / BK;
    constexpr int ASP = 20;
    constexpr int BSP = BN + 8;
    constexpr int ASZ = BM * ASP;
    constexpr int BSZ = BK * BSP;
    constexpr int NA = BM / 64;
    constexpr int NB = BN / 64;
    constexpr int WN = (BM == 128) ? 4 : 2;
    constexpr bool STATS = (MODE == 0 || MODE == 2);
    constexpr int SH = (BN == 64) ? 4 : 2;
    constexpr int RT = 16 / SH;
    extern __shared__ float smf[];
    float* As = smf;
    float* Bs = smf + ST * ASZ;
    __shared__ float sst[STATS ? 2 : 1][STATS ? SH : 1][STATS ? BN : 1];

    int tid = threadIdx.x, lane = tid & 31, wid = tid >> 5;
    int wm = wid / WN, wn = wid % WN;
    int n0 = blockIdx.x * BN, m0 = blockIdx.y * BM, u = blockIdx.z;
    const float* Ap = A + (size_t)m0 * K;
    const float* Bp;
    if (MODE == 0) Bp = (u < 2 ? X1 : X2) + (size_t)(u & 1) * 128 * HW + n0;
    else           Bp = B + (size_t)u * K * HW + n0;

    float acc[4][4][4];
    #pragma unroll
    for (int i = 0; i < 4; i++)
        #pragma unroll
        for (int j = 0; j < 4; j++)
            #pragma unroll
            for (int e = 0; e < 4; e++) acc[i][j][e] = 0.f;

    int ar[NA], ac[NA], br[NB], bc[NB];
    #pragma unroll
    for (int i = 0; i < NA; i++) {
        int idx = tid + i * 256;
        ar[i] = idx >> 2; ac[i] = (idx & 3) << 2;
    }
    #pragma unroll
    for (int i = 0; i < NB; i++) {
        int idx = tid + i * 256;
        br[i] = idx / (BN / 4); bc[i] = (idx % (BN / 4)) << 2;
    }
    int sc = tid % BN, sg = tid / BN;
    float s_sum = 0.f, s_sq = 0.f;
    int lm = lane >> 3;
    int loff = (((lane & 7) + (lm & 1) * 8)) * ASP + (lm >> 1) * 4;
    uint32_t as_base = smem_u32(As);

    #define PREFETCH(sidx, k0)                                                     \
        {   _Pragma("unroll")                                                      \
            for (int i = 0; i < NA; i++)                                           \
                cp16(smem_u32(&As[(sidx) * ASZ + ar[i] * ASP + ac[i]]),            \
                     Ap + (size_t)ar[i] * K + (k0) + ac[i]);                       \
            _Pragma("unroll")                                                      \
            for (int i = 0; i < NB; i++)                                           \
                cp16(smem_u32(&Bs[(sidx) * BSZ + br[i] * BSP + bc[i]]),            \
                     Bp + (size_t)((k0) + br[i]) * HW + bc[i]);                    \
        }

    PREFETCH(0, 0); cp_commit();
    if (KT > 1) PREFETCH(1, BK);
    cp_commit();

    for (int kt = 0; kt < KT; kt++) {
        cp_wait1();
        __syncthreads();
        int st = kt % ST;
        const float* bs = Bs + st * BSZ;
        if (STATS) {
            #pragma unroll
            for (int rr = 0; rr < RT; rr++) {
                float v = bs[(sg * RT + rr) * BSP + sc];
                s_sum += v; s_sq += v * v;
            }
        }
        uint32_t abase = as_base + (uint32_t)(st * ASZ + wm * 64 * ASP + loff) * 4;
        #pragma unroll
        for (int s8 = 0; s8 < 2; s8++) {
            uint32_t a[4][4], b[4][2];
            #pragma unroll
            for (int mt = 0; mt < 4; mt++)
                ldsm4(a[mt], abase + (uint32_t)(mt * 16 * ASP + s8 * 8) * 4);
            #pragma unroll
            for (int nt = 0; nt < 4; nt++) {
                const float* bp = bs + (s8 * 8 + (lane & 3)) * BSP
                                     + wn * 32 + nt * 8 + (lane >> 2);
                b[nt][0] = __float_as_uint(bp[0]);
                b[nt][1] = __float_as_uint(bp[4 * BSP]);
            }
            #pragma unroll
            for (int mt = 0; mt < 4; mt++)
                #pragma unroll
                for (int nt = 0; nt < 4; nt++)
                    mma_tf32(acc[mt][nt], a[mt], b[nt]);
        }
        if (kt + 2 < KT) PREFETCH((kt + 2) % ST, (kt + 2) * BK);
        cp_commit();
    }
    #undef PREFETCH

    if (STATS) {
        sst[0][sg][sc] = s_sum;
        sst[1][sg][sc] = s_sq;
        __syncthreads();
        if (tid < BN) {
            float S = 0.f, SS = 0.f;
            #pragma unroll
            for (int g = 0; g < SH; g++) { S += sst[0][g][tid]; SS += sst[1][g][tid]; }
            float m = S * (1.f / 128.f);
            float var = SS * (1.f / 128.f) - m * m;
            sst[0][0][tid] = m;
            sst[1][0][tid] = rsqrtf(var + eps);
        }
        __syncthreads();
    }

    #pragma unroll
    for (int mt = 0; mt < 4; mt++) {
        #pragma unroll
        for (int half = 0; half < 2; half++) {
            int row = m0 + wm * 64 + mt * 16 + (lane >> 2) + half * 8;
            float sgr = 0.f, cstr = 0.f, br2 = 0.f;
            if (MODE == 0 || MODE == 2) { sgr = Sg[row]; cstr = Cst[row]; }
            else br2 = bias[row];
            #pragma unroll
            for (int nt = 0; nt < 4; nt++) {
                #pragma unroll
                for (int e = 0; e < 2; e++) {
                    int pl = wn * 32 + nt * 8 + (lane & 3) * 2 + e;
                    int p = n0 + pl;
                    float v = acc[mt][nt][half * 2 + e];
                    if (MODE == 0) {
                        float mv = sst[0][0][pl], rv = sst[1][0][pl];
                        v = rv * v + (cstr - mv * rv * sgr);
                        if (row < 128)
                            ((__half*)O0)[((size_t)u * 128 + row) * HW + p] = __float2half(v * QSCALE);
                        else if (row < 256)
                            ((__half*)O1)[((size_t)(u ^ 2) * 128 + (row - 128)) * HW + p] = __float2half(v);
                        else
                            ((__half*)O2)[((size_t)(u ^ 2) * 128 + (row - 256)) * HW + p] = __float2half(v);
                    } else if (MODE == 2) {
                        float mv = sst[0][0][pl], rv = sst[1][0][pl];
                        v = rv * v + (cstr - mv * rv * sgr);
                        v = v / (1.f + __expf(-v));
                        O0[((size_t)u * 256 + row) * HW + p] = v;
                    } else {
                        v += br2;
                        size_t idx = ((size_t)u * 128 + row) * HW + p;
                        O0[idx] += v;
                    }
                }
            }
        }
    }
}

// ---------------- fp16 GEMM for the pointwise conv (round-11 proven) --------
__global__ void __launch_bounds__(256)
gemm_pw_f16(const __half* __restrict__ A, const __half* __restrict__ B,
            float* __restrict__ Y, const float* __restrict__ bias) {
    constexpr int K = 768, BN = 64, BK = 32, ST = 3;
    constexpr int KT = K / BK;
    constexpr int ASPH = 40;
    constexpr int BSPH = BN + 8;
    constexpr int ASZ = 256 * ASPH;
    constexpr int BSZ = BK * BSPH;
    extern __shared__ __half smh[];
    __half* As = smh;
    __half* Bs = smh + ST * ASZ;

    int tid = threadIdx.x, lane = tid & 31, wid = tid >> 5;
    int wm = wid >> 1, wn = wid & 1;
    int n0 = blockIdx.x * BN, u = blockIdx.z;
    const __half* Bp = B + (size_t)u * K * HW + n0;

    float acc[4][4][4];
    #pragma unroll
    for (int i = 0; i < 4; i++)
        #pragma unroll
        for (int j = 0; j < 4; j++)
            #pragma unroll
            for (int e = 0; e < 4; e++) acc[i][j][e] = 0.f;

    int aro[4], aco[4];
    #pragma unroll
    for (int i = 0; i < 4; i++) {
        int idx = tid + i * 256;
        aro[i] = idx >> 2; aco[i] = (idx & 3) << 3;
    }
    int brw = tid >> 3, bcl = (tid & 7) << 3;

    int arow_l = lane & 15, acol_l = (lane >> 4) << 3;
    int brow_l = (lane & 7) + ((lane >> 3) & 1) * 8;
    uint32_t as_base = smem_u32(As);
    uint32_t bs_base = smem_u32(Bs);

    #define PF16(sidx, k0)                                                         \
        {   _Pragma("unroll")                                                      \
            for (int i = 0; i < 4; i++)                                            \
                cp16(smem_u32(&As[(sidx) * ASZ + aro[i] * ASPH + aco[i]]),         \
                     A + (size_t)aro[i] * K + (k0) + aco[i]);                      \
            cp16(smem_u32(&Bs[(sidx) * BSZ + brw * BSPH + bcl]),                   \
                 Bp + (size_t)((k0) + brw) * HW + bcl);                            \
        }

    PF16(0, 0); cp_commit();
    PF16(1, BK); cp_commit();

    for (int kt = 0; kt < KT; kt++) {
        cp_wait1();
        __syncthreads();
        int st = kt % ST;
        uint32_t abase = as_base + (uint32_t)(st * ASZ + (wm * 64 + arow_l) * ASPH + acol_l) * 2;
        uint32_t bbase = bs_base + (uint32_t)(st * BSZ + brow_l * BSPH + wn * 32) * 2;
        #pragma unroll
        for (int s16 = 0; s16 < 2; s16++) {
            uint32_t a[4][4], b[4][2];
            #pragma unroll
            for (int mt = 0; mt < 4; mt++)
                ldsm4(a[mt], abase + (uint32_t)(mt * 16 * ASPH + s16 * 16) * 2);
            #pragma unroll
            for (int nt = 0; nt < 4; nt++)
                ldsm2t(b[nt], bbase + (uint32_t)(s16 * 16 * BSPH + nt * 8) * 2);
            #pragma unroll
            for (int mt = 0; mt < 4; mt++)
                #pragma unroll
                for (int nt = 0; nt < 4; nt++)
                    mma_f16(acc[mt][nt], a[mt], b[nt]);
        }
        if (kt + 2 < KT) PF16((kt + 2) % ST, (kt + 2) * BK);
        cp_commit();
    }
    #undef PF16

    #pragma unroll
    for (int mt = 0; mt < 4; mt++) {
        #pragma unroll
        for (int half = 0; half < 2; half++) {
            int row = wm * 64 + mt * 16 + (lane >> 2) + half * 8;
            float br2 = bias[row];
            #pragma unroll
            for (int nt = 0; nt < 4; nt++) {
                #pragma unroll
                for (int e = 0; e < 2; e++) {
                    int p = n0 + wn * 32 + nt * 8 + (lane & 3) * 2 + e;
                    float v = acc[mt][nt][half * 2 + e] + br2;
                    v = v / (1.f + __expf(-v));
                    size_t idx = ((size_t)u * 256 + row) * HW + p;
                    Y[idx] = Y[idx] + v;
                }
            }
        }
    }
}

// ---------------- fp16 GEMM for wo projection (MODE1) -----------------------
// A: WOh [128][128] half, B: Oh [4][128][HW] half. BM=128, BN=128, BK=32,
// warps 2x4, warp tile 64x32.  Out: dout = A*B + bias + residual(feats).
__global__ void __launch_bounds__(256)
gemm_wo_f16(const __half* __restrict__ A, const __half* __restrict__ B,
            float* __restrict__ O0,
            const float* __restrict__ X1, const float* __restrict__ X2,
            const float* __restrict__ bias) {
    constexpr int K = 128, BM = 128, BN = 128, BK = 32, ST = 3;
    constexpr int KT = K / BK;           // 4
    constexpr int ASPH = 40;
    constexpr int BSPH = BN + 8;         // 136
    constexpr int ASZ = BM * ASPH;
    constexpr int BSZ = BK * BSPH;
    extern __shared__ __half smh[];
    __half* As = smh;
    __half* Bs = smh + ST * ASZ;

    int tid = threadIdx.x, lane = tid & 31, wid = tid >> 5;
    int wm = wid >> 2, wn = wid & 3;
    int n0 = blockIdx.x * BN, u = blockIdx.z;
    const __half* Bp = B + (size_t)u * K * HW + n0;

    float acc[4][4][4];
    #pragma unroll
    for (int i = 0; i < 4; i++)
        #pragma unroll
        for (int j = 0; j < 4; j++)
            #pragma unroll
            for (int e = 0; e < 4; e++) acc[i][j][e] = 0.f;

    // A: 2 cp16/thread (128 rows x 4 segs of 8 halves = 512)
    int aro[2], aco[2];
    #pragma unroll
    for (int i = 0; i < 2; i++) {
        int idx = tid + i * 256;
        aro[i] = idx >> 2; aco[i] = (idx & 3) << 3;
    }
    // B: 2 cp16/thread (32 rows x 16 segs = 512)
    int brw[2], bcl[2];
    #pragma unroll
    for (int i = 0; i < 2; i++) {
        int idx = tid + i * 256;
        brw[i] = idx >> 4; bcl[i] = (idx & 15) << 3;
    }

    int arow_l = lane & 15, acol_l = (lane >> 4) << 3;
    int brow_l = (lane & 7) + ((lane >> 3) & 1) * 8;
    uint32_t as_base = smem_u32(As);
    uint32_t bs_base = smem_u32(Bs);

    #define PFW(sidx, k0)                                                          \
        {   _Pragma("unroll")                                                      \
            for (int i = 0; i < 2; i++)                                            \
                cp16(smem_u32(&As[(sidx) * ASZ + aro[i] * ASPH + aco[i]]),         \
                     A + (size_t)aro[i] * K + (k0) + aco[i]);                      \
            _Pragma("unroll")                                                      \
            for (int i = 0; i < 2; i++)                                            \
                cp16(smem_u32(&Bs[(sidx) * BSZ + brw[i] * BSPH + bcl[i]]),         \
                     Bp + (size_t)((k0) + brw[i]) * HW + bcl[i]);                  \
        }

    PFW(0, 0); cp_commit();
    PFW(1, BK); cp_commit();

    for (int kt = 0; kt < KT; kt++) {
        cp_wait1();
        __syncthreads();
        int st = kt % ST;
        uint32_t abase = as_base + (uint32_t)(st * ASZ + (wm * 64 + arow_l) * ASPH + acol_l) * 2;
        uint32_t bbase = bs_base + (uint32_t)(st * BSZ + brow_l * BSPH + wn * 32) * 2;
        #pragma unroll
        for (int s16 = 0; s16 < 2; s16++) {
            uint32_t a[4][4], b[4][2];
            #pragma unroll
            for (int mt = 0; mt < 4; mt++)
                ldsm4(a[mt], abase + (uint32_t)(mt * 16 * ASPH + s16 * 16) * 2);
            #pragma unroll
            for (int nt = 0; nt < 4; nt++)
                ldsm2t(b[nt], bbase + (uint32_t)(s16 * 16 * BSPH + nt * 8) * 2);
            #pragma unroll
            for (int mt = 0; mt < 4; mt++)
                #pragma unroll
                for (int nt = 0; nt < 4; nt++)
                    mma_f16(acc[mt][nt], a[mt], b[nt]);
        }
        if (kt + 2 < KT) PFW((kt + 2) % ST, (kt + 2) * BK);
        cp_commit();
    }
    #undef PFW

    // wm in {0,1} covers rows 0..127 (warp tile 64 rows)
    #pragma unroll
    for (int mt = 0; mt < 4; mt++) {
        #pragma unroll
        for (int half = 0; half < 2; half++) {
            int row = wm * 64 + mt * 16 + (lane >> 2) + half * 8;
            float br2 = bias[row];
            #pragma unroll
            for (int nt = 0; nt < 4; nt++) {
                #pragma unroll
                for (int e = 0; e < 2; e++) {
                    int p = n0 + wn * 32 + nt * 8 + (lane & 3) * 2 + e;
                    float res = ((u < 2 ? X1 : X2))[((size_t)(u & 1) * 128 + row) * HW + p];
                    size_t idx = ((size_t)u * 128 + row) * HW + p;
                    O0[idx] = acc[mt][nt][half * 2 + e] + br2 + res;
                }
            }
        }
    }
}

// ---------------- fp16 flash attention (register-direct P reuse) -------------
#define AT2_QS 0
#define AT2_VS 10240
#define AT2_KT 20480
#define AT2_HALVES 28928
#define ATTN2_SMEM (AT2_HALVES * 2 + 256 * 4 + 32 * 4)

__global__ void __launch_bounds__(256, 2)
attn_f16(const __half* __restrict__ Q, const __half* __restrict__ K,
         const __half* __restrict__ V, __half* __restrict__ O) {
    int blk = blockIdx.x;                  // b*256 + n*64 + h
    int h = blk & 63, n = (blk >> 6) & 3, b = blk >> 8;
    size_t base = ((size_t)(b * 128 + n * 32) * 64 + h) * 256;
    extern __shared__ __half smh2[];
    __half* Qs = smh2 + AT2_QS;            // [i][d] pitch 40
    __half* Vs = smh2 + AT2_VS;            // [j][d] pitch 40
    __half* Kt = smh2 + AT2_KT;            // [d][j] pitch 264
    float* V2 = (float*)(smh2 + AT2_HALVES);
    float* Vsum = V2 + 256;
    int tid = threadIdx.x, lane = tid & 31, w = tid >> 5;

    #pragma unroll 4
    for (int dd = 0; dd < 32; dd++) {
        Qs[tid * 40 + dd] = Q[base + (size_t)dd * HW + tid];
        Vs[tid * 40 + dd] = V[base + (size_t)dd * HW + tid];
    }
    #pragma unroll
    for (int i = 0; i < 4; i++) {
        int idx = tid + i * 256;
        int row = idx >> 5, seg = idx & 31;
        *(uint4*)&Kt[row * 264 + seg * 8] =
            *(const uint4*)&K[base + (size_t)row * HW + seg * 8];
    }
    __syncthreads();
    {
        float s = 0.f;
        #pragma unroll 8
        for (int jj = 0; jj < 32; jj++) s += __half2float(Vs[(w * 32 + jj) * 40 + lane]);
        V2[w * 32 + lane] = s;
    }

    int i0 = w * 32;
    uint32_t qa[2][2][4];
    #pragma unroll
    for (int mt = 0; mt < 2; mt++)
        #pragma unroll
        for (int dk = 0; dk < 2; dk++)
            ldsm4(qa[mt][dk],
                  smem_u32(&Qs[(i0 + mt * 16 + (lane & 15)) * 40 + dk * 16 + ((lane >> 4) << 3)]));
    int brow = (lane & 7) + ((lane >> 3) & 1) * 8;

    float l0[2] = {0.f, 0.f}, l1[2] = {0.f, 0.f};
    float o[2][4][4];
    #pragma unroll
    for (int mt = 0; mt < 2; mt++)
        #pragma unroll
        for (int dt = 0; dt < 4; dt++)
            #pragma unroll
            for (int e = 0; e < 4; e++) o[mt][dt][e] = 0.f;

    for (int j0 = 0; j0 < 256; j0 += 16) {
        float s[2][2][4];
        #pragma unroll
        for (int mt = 0; mt < 2; mt++)
            #pragma unroll
            for (int jh = 0; jh < 2; jh++)
                #pragma unroll
                for (int e = 0; e < 4; e++) s[mt][jh][e] = 0.f;
        uint32_t bS[2][2][2];
        #pragma unroll
        for (int dk = 0; dk < 2; dk++)
            #pragma unroll
            for (int jh = 0; jh < 2; jh++)
                ldsm2t(bS[dk][jh], smem_u32(&Kt[(dk * 16 + brow) * 264 + j0 + jh * 8]));
        #pragma unroll
        for (int mt = 0; mt < 2; mt++)
            #pragma unroll
            for (int jh = 0; jh < 2; jh++)
                #pragma unroll
                for (int dk = 0; dk < 2; dk++)
                    mma_f16(s[mt][jh], qa[mt][dk], bS[dk][jh]);
        uint32_t pa[2][4];
        #pragma unroll
        for (int mt = 0; mt < 2; mt++) {
            float p00 = fexp2(s[mt][0][0]), p01 = fexp2(s[mt][0][1]);
            float p02 = fexp2(s[mt][0][2]), p03 = fexp2(s[mt][0][3]);
            float p10 = fexp2(s[mt][1][0]), p11 = fexp2(s[mt][1][1]);
            float p12 = fexp2(s[mt][1][2]), p13 = fexp2(s[mt][1][3]);
            l0[mt] += p00 + p01 + p10 + p11;
            l1[mt] += p02 + p03 + p12 + p13;
            pa[mt][0] = packh2(p00, p01);
            pa[mt][1] = packh2(p02, p03);
            pa[mt][2] = packh2(p10, p11);
            pa[mt][3] = packh2(p12, p13);
        }
        uint32_t bV[4][2];
        #pragma unroll
        for (int dt = 0; dt < 4; dt++)
            ldsm2t(bV[dt], smem_u32(&Vs[(j0 + brow) * 40 + dt * 8]));
        #pragma unroll
        for (int mt = 0; mt < 2; mt++)
            #pragma unroll
            for (int dt = 0; dt < 4; dt++)
                mma_f16(o[mt][dt], pa[mt], bV[dt]);
    }
    #pragma unroll
    for (int mt = 0; mt < 2; mt++) {
        l0[mt] += __shfl_xor_sync(0xffffffffu, l0[mt], 1);
        l0[mt] += __shfl_xor_sync(0xffffffffu, l0[mt], 2);
        l1[mt] += __shfl_xor_sync(0xffffffffu, l1[mt], 1);
        l1[mt] += __shfl_xor_sync(0xffffffffu, l1[mt], 2);
    }

    __syncthreads();
    float* Ow = (float*)smh2 + w * 32 * 36;     // reuse Qs/Vs region
    #pragma unroll
    for (int mt = 0; mt < 2; mt++)
        #pragma unroll
        for (int hf = 0; hf < 2; hf++) {
            float inv = 1.f / (hf == 0 ? l0[mt] : l1[mt]);
            int row = mt * 16 + (lane >> 2) + hf * 8;
            #pragma unroll
            for (int dt = 0; dt < 4; dt++) {
                Ow[row * 36 + dt * 8 + (lane & 3) * 2]     = o[mt][dt][hf * 2]     * inv;
                Ow[row * 36 + dt * 8 + (lane & 3) * 2 + 1] = o[mt][dt][hf * 2 + 1] * inv;
            }
        }
    if (tid < 32) {
        float s = 0.f;
        #pragma unroll
        for (int ww = 0; ww < 8; ww++) s += V2[ww * 32 + tid];
        Vsum[tid] = s;
    }
    __syncthreads();
    const float eps = 1e-6f;
    const float norm = 1.f / (1.f + 256.f * eps);
    #pragma unroll 4
    for (int d = 0; d < 32; d++) {
        float val = (Ow[lane * 36 + d] + eps * Vsum[d]) * norm;
        O[base + (size_t)d * HW + i0 + lane] = __float2half(val);
    }
}

// ---------------- depthwise 3x3 / 5x5 / 7x7 -> half F (fp32 in) -------------
__global__ void dw_kernel(const float* __restrict__ Y,
                          const float* __restrict__ w3, const float* __restrict__ b3,
                          const float* __restrict__ w5, const float* __restrict__ b5,
                          const float* __restrict__ w7, const float* __restrict__ b7,
                          __half* __restrict__ F) {
    __shared__ float S[14][70];
    __shared__ float wgt[84];
    int z = blockIdx.z; int ch = z & 255; int u = z >> 8;
    int w0 = blockIdx.x * 64, h0 = blockIdx.y * 8;
    int tid = threadIdx.x;
    if (tid < 9)       wgt[tid] = w3[ch * 9 + tid];
    else if (tid < 34) wgt[tid] = w5[ch * 25 + tid - 9];
    else if (tid < 83) wgt[tid] = w7[ch * 49 + tid - 34];
    const float* Yp = Y + ((size_t)u * 256 + ch) * HW;
    for (int i = tid; i < 980; i += 256) {
        int r = i / 70, c = i % 70;
        int gh = h0 - 3 + r, gw = w0 - 3 + c;
        float v = 0.f;
        if ((unsigned)gh < 64u && (unsigned)gw < 256u) v = Yp[gh * 256 + gw];
        S[r][c] = v;
    }
    __syncthreads();
    int tx = tid & 63, ty = tid >> 6;
    float bb3 = b3[ch], bb5 = b5[ch], bb7 = b7[ch];
    #pragma unroll
    for (int rr = 0; rr < 2; rr++) {
        int rc = ty + rr * 4 + 3, cc = tx + 3;
        float f3 = bb3, f5 = bb5, f7 = bb7;
        #pragma unroll
        for (int dy = -3; dy <= 3; dy++)
            #pragma unroll
            for (int dx = -3; dx <= 3; dx++) {
                float v = S[rc + dy][cc + dx];
                f7 += v * wgt[34 + (dy + 3) * 7 + (dx + 3)];
                if (dy >= -2 && dy <= 2 && dx >= -2 && dx <= 2)
                    f5 += v * wgt[9 + (dy + 2) * 5 + (dx + 2)];
                if (dy >= -1 && dy <= 1 && dx >= -1 && dx <= 1)
                    f3 += v * wgt[(dy + 1) * 3 + (dx + 1)];
            }
        size_t pix = (size_t)(h0 + ty + rr * 4) * 256 + (w0 + tx);
        size_t ob = (size_t)u * 768 * HW + pix;
        F[ob + (size_t) ch        * HW] = __float2half(f3);
        F[ob + (size_t)(256 + ch) * HW] = __float2half(f5);
        F[ob + (size_t)(512 + ch) * HW] = __float2half(f7);
    }
}

// ---------------- host launcher --------------------------------------------
extern "C" void kernel_launch(void* const* d_in, const int* in_sizes, int n_in,
                              void* d_out, int out_size) {
    const float* feats1 = (const float*)d_in[0];
    const float* feats2 = (const float*)d_in[1];
    const float* an_g  = (const float*)d_in[2];
    const float* an_b  = (const float*)d_in[3];
    const float* anc_g = (const float*)d_in[4];
    const float* anc_b = (const float*)d_in[5];
    const float* wq    = (const float*)d_in[6];
    const float* bq    = (const float*)d_in[7];
    const float* wkv   = (const float*)d_in[8];
    const float* bkv   = (const float*)d_in[9];
    const float* wo    = (const float*)d_in[10];
    const float* bo    = (const float*)d_in[11];
    const float* fn_g  = (const float*)d_in[12];
    const float* fn_b  = (const float*)d_in[13];
    const float* w_in  = (const float*)d_in[14];
    const float* b_in  = (const float*)d_in[15];
    const float* w_dw3 = (const float*)d_in[16];
    const float* b_dw3 = (const float*)d_in[17];
    const float* w_dw5 = (const float*)d_in[18];
    const float* b_dw5 = (const float*)d_in[19];
    const float* w_dw7 = (const float*)d_in[20];
    const float* b_dw7 = (const float*)d_in[21];
    const float* w_pw  = (const float*)d_in[22];
    const float* b_pw  = (const float*)d_in[23];
    const float* w_out = (const float*)d_in[24];
    const float* b_out = (const float*)d_in[25];
    float* dout = (float*)d_out;

    float *Y, *WA, *SgA, *CA, *WIN, *SgI, *CI;
    __half *Qh, *Kh, *Vh, *Oh, *Fh, *WPWh, *WOh;
    cudaGetSymbolAddress((void**)&Qh, g_Qh);
    cudaGetSymbolAddress((void**)&Kh, g_Kh);
    cudaGetSymbolAddress((void**)&Vh, g_Vh);
    cudaGetSymbolAddress((void**)&Oh, g_Oh);
    cudaGetSymbolAddress((void**)&Y,  g_Y);
    cudaGetSymbolAddress((void**)&Fh, g_Fh);
    cudaGetSymbolAddress((void**)&WPWh, g_WPWh);
    cudaGetSymbolAddress((void**)&WOh, g_WOh);
    cudaGetSymbolAddress((void**)&WA, g_WA);
    cudaGetSymbolAddress((void**)&SgA, g_SgA);
    cudaGetSymbolAddress((void**)&CA, g_CA);
    cudaGetSymbolAddress((void**)&WIN, g_WIN);
    cudaGetSymbolAddress((void**)&SgI, g_SgI);
    cudaGetSymbolAddress((void**)&CI, g_CI);

    const int smA  = 3 * (128 * 20 + 16 * 136) * 4;   // tf32 BM=128/BN=128
    const int smB  = 3 * (256 * 20 + 16 * 72)  * 4;   // tf32 BM=256/BN=64
    const int smH  = 3 * (256 * 40 + 32 * 72)  * 2;   // f16 pw
    const int smW  = 3 * (128 * 40 + 32 * 136) * 2;   // f16 wo: 56832
    cudaFuncSetAttribute((const void*)gemm_tc<128, 0, 128, 128>, cudaFuncAttributeMaxDynamicSharedMemorySize, smA);
    cudaFuncSetAttribute((const void*)gemm_tc<128, 2, 256, 64>,  cudaFuncAttributeMaxDynamicSharedMemorySize, smB);
    cudaFuncSetAttribute((const void*)gemm_tc<256, 4, 128, 128>, cudaFuncAttributeMaxDynamicSharedMemorySize, smA);
    cudaFuncSetAttribute((const void*)gemm_pw_f16, cudaFuncAttributeMaxDynamicSharedMemorySize, smH);
    cudaFuncSetAttribute((const void*)gemm_wo_f16, cudaFuncAttributeMaxDynamicSharedMemorySize, smW);
    cudaFuncSetAttribute((const void*)attn_f16, cudaFuncAttributeMaxDynamicSharedMemorySize, ATTN2_SMEM);

    // 1. weight prep + fp16 conversions
    prep_kernel<<<640, 128>>>(wq, bq, wkv, bkv, an_g, an_b, anc_g, anc_b,
                              w_in, b_in, fn_g, fn_b);
    convh_kernel<<<768, 256>>>(w_pw, WPWh, 256 * 768);
    convh_kernel<<<64, 256>>>(wo, WOh, 128 * 128);
    // 2. fused LN + q/kv projection -> fp16 Q (pre-scaled), K, V
    gemm_tc<128, 0, 128, 128><<<dim3(128, 3, 4), 256, smA>>>(WA, nullptr,
                                                             (float*)Qh, (float*)Kh, (float*)Vh,
                                                             SgA, CA, feats1, feats2, nullptr, 1e-6f);
    // 3. fp16 flash attention -> fp16 O
    attn_f16<<<1024, 256, ATTN2_SMEM>>>(Qh, Kh, Vh, Oh);
    // 4. fp16 wo projection + residual(feats) -> d_out
    gemm_wo_f16<<<dim3(128, 1, 4), 256, smW>>>(WOh, Oh, dout, feats1, feats2, bo);
    // 5. fused LN + w_in + SiLU -> Y (fp32)
    gemm_tc<128, 2, 256, 64><<<dim3(256, 1, 4), 256, smB>>>(WIN, dout, Y, nullptr, nullptr,
                                                            SgI, CI, nullptr, nullptr, nullptr, 1e-5f);
    // 6. depthwise 3/5/7 -> Fh (fp16)
    dw_kernel<<<dim3(4, 8, 1024), 256>>>(Y, w_dw3, b_dw3, w_dw5, b_dw5, w_dw7, b_dw7, Fh);
    // 7. fp16 pointwise GEMM + SiLU, Y += (fp32 RMW)
    gemm_pw_f16<<<dim3(256, 1, 4), 256, smH>>>(WPWh, Fh, Y, b_pw);
    // 8. w_out GEMM (tf32, K=256), d_out +=
    gemm_tc<256, 4, 128, 128><<<dim3(128, 1, 4), 256, smA>>>(w_out, Y, dout, nullptr, nullptr,
                                                             nullptr, nullptr, nullptr, nullptr, b_out, 0.f);
}

// round 14
// speedup vs baseline: 1.2117x; 1.0029x over previous
#include <cuda_runtime.h>
#include <cuda_fp16.h>
#include <math.h>
#include <stdint.h>

#define HW 16384          // 64*256 pixels per (batch, channel) plane

// ---------------- scratch (static device globals; no allocation allowed) ----
__device__ __half g_Qh[4*128*HW];
__device__ __half g_Kh[4*128*HW];
__device__ __half g_Vh[4*128*HW];
__device__ __half g_Oh[4*128*HW];
__device__ __half g_X1h[2*128*HW];
__device__ __half g_X2h[2*128*HW];
__device__ float g_Y [4*256*HW];
__device__ __half g_Fh[(size_t)4*768*HW];
__device__ __half g_WPWh[256*768];
__device__ __half g_WOh[128*128];
__device__ __half g_WAh[384*128];
__device__ float g_WA [384*128], g_SgA[384], g_CA[384];
__device__ float g_WIN[256*128], g_SgI[256], g_CI[256];

#define QSCALE (0.17677669529663687f * 1.4426950408889634f)

// ---------------- small helpers --------------------------------------------
__device__ __forceinline__ uint32_t smem_u32(const void* p) {
    return (uint32_t)__cvta_generic_to_shared(p);
}
__device__ __forceinline__ void cp16(uint32_t dst, const void* src) {
    asm volatile("cp.async.cg.shared.global [%0], [%1], 16;\n" :: "r"(dst), "l"(src));
}
__device__ __forceinline__ void cp_commit() { asm volatile("cp.async.commit_group;\n"); }
__device__ __forceinline__ void cp_wait1()  { asm volatile("cp.async.wait_group 1;\n"); }

__device__ __forceinline__ void mma_tf32(float* c, const uint32_t* a, const uint32_t* b) {
    asm volatile("mma.sync.aligned.m16n8k8.row.col.f32.tf32.tf32.f32 "
        "{%0,%1,%2,%3}, {%4,%5,%6,%7}, {%8,%9}, {%0,%1,%2,%3};"
        : "+f"(c[0]), "+f"(c[1]), "+f"(c[2]), "+f"(c[3])
        : "r"(a[0]), "r"(a[1]), "r"(a[2]), "r"(a[3]), "r"(b[0]), "r"(b[1]));
}
__device__ __forceinline__ void mma_f16(float* c, const uint32_t* a, const uint32_t* b) {
    asm volatile("mma.sync.aligned.m16n8k16.row.col.f32.f16.f16.f32 "
        "{%0,%1,%2,%3}, {%4,%5,%6,%7}, {%8,%9}, {%0,%1,%2,%3};"
        : "+f"(c[0]), "+f"(c[1]), "+f"(c[2]), "+f"(c[3])
        : "r"(a[0]), "r"(a[1]), "r"(a[2]), "r"(a[3]), "r"(b[0]), "r"(b[1]));
}
__device__ __forceinline__ void ldsm4(uint32_t* r, uint32_t addr) {
    asm volatile("ldmatrix.sync.aligned.m8n8.x4.shared.b16 {%0,%1,%2,%3}, [%4];"
        : "=r"(r[0]), "=r"(r[1]), "=r"(r[2]), "=r"(r[3]) : "r"(addr));
}
__device__ __forceinline__ void ldsm2t(uint32_t* r, uint32_t addr) {
    asm volatile("ldmatrix.sync.aligned.m8n8.x2.trans.shared.b16 {%0,%1}, [%2];"
        : "=r"(r[0]), "=r"(r[1]) : "r"(addr));
}
__device__ __forceinline__ float fexp2(float x) {
    float r; asm("ex2.approx.ftz.f32 %0, %1;" : "=f"(r) : "f"(x)); return r;
}
__device__ __forceinline__ uint32_t packh2(float a, float b) {
    __half2 h = __floats2half2_rn(a, b);
    return *(uint32_t*)&h;
}

// ---------------- fold LN gamma/beta into GEMM weights ---------------------
__global__ void prep_kernel(const float* __restrict__ wq,  const float* __restrict__ bq,
                            const float* __restrict__ wkv, const float* __restrict__ bkv,
                            const float* __restrict__ an_g, const float* __restrict__ an_b,
                            const float* __restrict__ anc_g, const float* __restrict__ anc_b,
                            const float* __restrict__ w_in, const float* __restrict__ b_in,
                            const float* __restrict__ fn_g, const float* __restrict__ fn_b) {
    int r = blockIdx.x, t = threadIdx.x;   // 640 blocks x 128 threads
    __shared__ float red[2][4];
    float wl, gg, bb, extra;
    float *Wdst, *Sgd, *Cd;
    if (r < 128)      { wl = wq [r*128 + t];        gg = an_g[t];  bb = an_b[t];  extra = bq [r];
                        Wdst = g_WA  + r*128;        Sgd = g_SgA + r;  Cd = g_CA + r; }
    else if (r < 384) { int rr = r - 128;
                        wl = wkv[rr*128 + t];       gg = anc_g[t]; bb = anc_b[t]; extra = bkv[rr];
                        Wdst = g_WA  + r*128;        Sgd = g_SgA + r;  Cd = g_CA + r; }
    else              { int rr = r - 384;
                        wl = w_in[rr*128 + t];      gg = fn_g[t];  bb = fn_b[t];  extra = b_in[rr];
                        Wdst = g_WIN + rr*128;       Sgd = g_SgI + rr; Cd = g_CI + rr; }
    float wg = wl * gg;
    Wdst[t] = wg;
    if (r < 384) g_WAh[r*128 + t] = __float2half(wg);
    float s1 = wg, s2 = wl * bb;
    #pragma unroll
    for (int off = 16; off; off >>= 1) {
        s1 += __shfl_down_sync(0xffffffffu, s1, off);
        s2 += __shfl_down_sync(0xffffffffu, s2, off);
    }
    if ((t & 31) == 0) { red[0][t >> 5] = s1; red[1][t >> 5] = s2; }
    __syncthreads();
    if (t == 0) {
        float a = red[0][0] + red[0][1] + red[0][2] + red[0][3];
        float b = red[1][0] + red[1][1] + red[1][2] + red[1][3];
        *Sgd = a; *Cd = b + extra;
    }
}

// ---------------- convert fp32 weights to fp16 ------------------------------
__global__ void convh_kernel(const float* __restrict__ W, __half* __restrict__ Wh, int n) {
    int i = blockIdx.x * 256 + threadIdx.x;
    if (i < n) Wh[i] = __float2half(W[i]);
}

// ---------------- convert feats to fp16 (vectorized) ------------------------
__global__ void convfeats_kernel(const float4* __restrict__ s1, const float4* __restrict__ s2,
                                 uint2* __restrict__ d1, uint2* __restrict__ d2, int n4) {
    int i = blockIdx.x * 256 + threadIdx.x;
    if (i < n4) {
        float4 a = s1[i];
        uint2 o;
        o.x = packh2(a.x, a.y); o.y = packh2(a.z, a.w);
        d1[i] = o;
        float4 b = s2[i];
        o.x = packh2(b.x, b.y); o.y = packh2(b.z, b.w);
        d2[i] = o;
    }
}

// ---------------- fp16 q/kv GEMM, LN-fused with in-kernel stats -------------
// A: g_WAh [384][128] half.  B: fp16 feats split.  grid (128, 3, 4).
// BM=128, BN=128, BK=32, warps 2x4, warp tile 64x32.
__global__ void __launch_bounds__(256)
gemm_qkv_f16(const __half* __restrict__ A,
             __half* __restrict__ Qo, __half* __restrict__ Ko, __half* __restrict__ Vo,
             const float* __restrict__ Sg, const float* __restrict__ Cst,
             const __half* __restrict__ X1h, const __half* __restrict__ X2h, float eps) {
    constexpr int K = 128, BM = 128, BN = 128, BK = 32, ST = 3;
    constexpr int KT = K / BK;           // 4
    constexpr int ASPH = 40;
    constexpr int BSPH = BN + 8;         // 136
    constexpr int ASZ = BM * ASPH;
    constexpr int BSZ = BK * BSPH;
    extern __shared__ __half smh[];
    __half* As = smh;
    __half* Bs = smh + ST * ASZ;
    __shared__ float sst[2][2][BN];

    int tid = threadIdx.x, lane = tid & 31, wid = tid >> 5;
    int wm = wid >> 2, wn = wid & 3;
    int n0 = blockIdx.x * BN, m0 = blockIdx.y * BM, u = blockIdx.z;
    const __half* Ap = A + (size_t)m0 * K;
    const __half* Bp = (u < 2 ? X1h : X2h) + (size_t)(u & 1) * 128 * HW + n0;

    float acc[4][4][4];
    #pragma unroll
    for (int i = 0; i < 4; i++)
        #pragma unroll
        for (int j = 0; j < 4; j++)
            #pragma unroll
            for (int e = 0; e < 4; e++) acc[i][j][e] = 0.f;

    int aro[2], aco[2];
    #pragma unroll
    for (int i = 0; i < 2; i++) {
        int idx = tid + i * 256;
        aro[i] = idx >> 2; aco[i] = (idx & 3) << 3;
    }
    int brw[2], bcl[2];
    #pragma unroll
    for (int i = 0; i < 2; i++) {
        int idx = tid + i * 256;
        brw[i] = idx >> 4; bcl[i] = (idx & 15) << 3;
    }
    // stats coords: 2 groups x 128 cols, 16 rows each per k-tile
    int sc = tid & 127, sg = tid >> 7;
    float s_sum = 0.f, s_sq = 0.f;

    int arow_l = lane & 15, acol_l = (lane >> 4) << 3;
    int brow_l = (lane & 7) + ((lane >> 3) & 1) * 8;
    uint32_t as_base = smem_u32(As);
    uint32_t bs_base = smem_u32(Bs);

    #define PFQ(sidx, k0)                                                          \
        {   _Pragma("unroll")                                                      \
            for (int i = 0; i < 2; i++)                                            \
                cp16(smem_u32(&As[(sidx) * ASZ + aro[i] * ASPH + aco[i]]),         \
                     Ap + (size_t)aro[i] * K + (k0) + aco[i]);                     \
            _Pragma("unroll")                                                      \
            for (int i = 0; i < 2; i++)                                            \
                cp16(smem_u32(&Bs[(sidx) * BSZ + brw[i] * BSPH + bcl[i]]),         \
                     Bp + (size_t)((k0) + brw[i]) * HW + bcl[i]);                  \
        }

    PFQ(0, 0); cp_commit();
    PFQ(1, BK); cp_commit();

    for (int kt = 0; kt < KT; kt++) {
        cp_wait1();
        __syncthreads();
        int st = kt % ST;
        const __half* bs = Bs + st * BSZ;
        #pragma unroll
        for (int rr = 0; rr < 16; rr++) {
            float v = __half2float(bs[(sg * 16 + rr) * BSPH + sc]);
            s_sum += v; s_sq += v * v;
        }
        uint32_t abase = as_base + (uint32_t)(st * ASZ + (wm * 64 + arow_l) * ASPH + acol_l) * 2;
        uint32_t bbase = bs_base + (uint32_t)(st * BSZ + brow_l * BSPH + wn * 32) * 2;
        #pragma unroll
        for (int s16 = 0; s16 < 2; s16++) {
            uint32_t a[4][4], b[4][2];
            #pragma unroll
            for (int mt = 0; mt < 4; mt++)
                ldsm4(a[mt], abase + (uint32_t)(mt * 16 * ASPH + s16 * 16) * 2);
            #pragma unroll
            for (int nt = 0; nt < 4; nt++)
                ldsm2t(b[nt], bbase + (uint32_t)(s16 * 16 * BSPH + nt * 8) * 2);
            #pragma unroll
            for (int mt = 0; mt < 4; mt++)
                #pragma unroll
                for (int nt = 0; nt < 4; nt++)
                    mma_f16(acc[mt][nt], a[mt], b[nt]);
        }
        if (kt + 2 < KT) PFQ((kt + 2) % ST, (kt + 2) * BK);
        cp_commit();
    }
    #undef PFQ

    sst[0][sg][sc] = s_sum;
    sst[1][sg][sc] = s_sq;
    __syncthreads();
    if (tid < BN) {
        float S = sst[0][0][tid] + sst[0][1][tid];
        float SS = sst[1][0][tid] + sst[1][1][tid];
        float m = S * (1.f / 128.f);
        float var = SS * (1.f / 128.f) - m * m;
        sst[0][0][tid] = m;
        sst[1][0][tid] = rsqrtf(var + eps);
    }
    __syncthreads();

    #pragma unroll
    for (int mt = 0; mt < 4; mt++) {
        #pragma unroll
        for (int half = 0; half < 2; half++) {
            int row = m0 + wm * 64 + mt * 16 + (lane >> 2) + half * 8;
            float sgr = Sg[row], cstr = Cst[row];
            #pragma unroll
            for (int nt = 0; nt < 4; nt++) {
                #pragma unroll
                for (int e = 0; e < 2; e++) {
                    int pl = wn * 32 + nt * 8 + (lane & 3) * 2 + e;
                    int p = n0 + pl;
                    float v = acc[mt][nt][half * 2 + e];
                    float mv = sst[0][0][pl], rv = sst[1][0][pl];
                    v = rv * v + (cstr - mv * rv * sgr);
                    if (row < 128)
                        Qo[((size_t)u * 128 + row) * HW + p] = __float2half(v * QSCALE);
                    else if (row < 256)
                        Ko[((size_t)(u ^ 2) * 128 + (row - 128)) * HW + p] = __float2half(v);
                    else
                        Vo[((size_t)(u ^ 2) * 128 + (row - 256)) * HW + p] = __float2half(v);
                }
            }
        }
    }
}

// ---------------- tf32 tensor-core GEMM (MODE 2: w_in; MODE 4: w_out) -------
template<int K, int MODE, int BM, int BN>
__global__ void __launch_bounds__(256)
gemm_tc(const float* __restrict__ A, const float* __restrict__ B,
        float* __restrict__ O0,
        const float* __restrict__ Sg, const float* __restrict__ Cst,
        const float* __restrict__ bias, float eps) {
    constexpr int BK = 16, ST = 3;
    constexpr int KT = K / BK;
    constexpr int ASP = 20;
    constexpr int BSP = BN + 8;
    constexpr int ASZ = BM * ASP;
    constexpr int BSZ = BK * BSP;
    constexpr int NA = BM / 64;
    constexpr int NB = BN / 64;
    constexpr int WN = (BM == 128) ? 4 : 2;
    constexpr bool STATS = (MODE == 2);
    constexpr int SH = (BN == 64) ? 4 : 2;
    constexpr int RT = 16 / SH;
    extern __shared__ float smf[];
    float* As = smf;
    float* Bs = smf + ST * ASZ;
    __shared__ float sst[STATS ? 2 : 1][STATS ? SH : 1][STATS ? BN : 1];

    int tid = threadIdx.x, lane = tid & 31, wid = tid >> 5;
    int wm = wid / WN, wn = wid % WN;
    int n0 = blockIdx.x * BN, m0 = blockIdx.y * BM, u = blockIdx.z;
    const float* Ap = A + (size_t)m0 * K;
    const float* Bp = B + (size_t)u * K * HW + n0;

    float acc[4][4][4];
    #pragma unroll
    for (int i = 0; i < 4; i++)
        #pragma unroll
        for (int j = 0; j < 4; j++)
            #pragma unroll
            for (int e = 0; e < 4; e++) acc[i][j][e] = 0.f;

    int ar[NA], ac[NA], br[NB], bc[NB];
    #pragma unroll
    for (int i = 0; i < NA; i++) {
        int idx = tid + i * 256;
        ar[i] = idx >> 2; ac[i] = (idx & 3) << 2;
    }
    #pragma unroll
    for (int i = 0; i < NB; i++) {
        int idx = tid + i * 256;
        br[i] = idx / (BN / 4); bc[i] = (idx % (BN / 4)) << 2;
    }
    int sc = tid % BN, sg = tid / BN;
    float s_sum = 0.f, s_sq = 0.f;
    int lm = lane >> 3;
    int loff = (((lane & 7) + (lm & 1) * 8)) * ASP + (lm >> 1) * 4;
    uint32_t as_base = smem_u32(As);

    #define PREFETCH(sidx, k0)                                                     \
        {   _Pragma("unroll")                                                      \
            for (int i = 0; i < NA; i++)                                           \
                cp16(smem_u32(&As[(sidx) * ASZ + ar[i] * ASP + ac[i]]),            \
                     Ap + (size_t)ar[i] * K + (k0) + ac[i]);                       \
            _Pragma("unroll")                                                      \
            for (int i = 0; i < NB; i++)                                           \
                cp16(smem_u32(&Bs[(sidx) * BSZ + br[i] * BSP + bc[i]]),            \
                     Bp + (size_t)((k0) + br[i]) * HW + bc[i]);                    \
        }

    PREFETCH(0, 0); cp_commit();
    if (KT > 1) PREFETCH(1, BK);
    cp_commit();

    for (int kt = 0; kt < KT; kt++) {
        cp_wait1();
        __syncthreads();
        int st = kt % ST;
        const float* bs = Bs + st * BSZ;
        if (STATS) {
            #pragma unroll
            for (int rr = 0; rr < RT; rr++) {
                float v = bs[(sg * RT + rr) * BSP + sc];
                s_sum += v; s_sq += v * v;
            }
        }
        uint32_t abase = as_base + (uint32_t)(st * ASZ + wm * 64 * ASP + loff) * 4;
        #pragma unroll
        for (int s8 = 0; s8 < 2; s8++) {
            uint32_t a[4][4], b[4][2];
            #pragma unroll
            for (int mt = 0; mt < 4; mt++)
                ldsm4(a[mt], abase + (uint32_t)(mt * 16 * ASP + s8 * 8) * 4);
            #pragma unroll
            for (int nt = 0; nt < 4; nt++) {
                const float* bp = bs + (s8 * 8 + (lane & 3)) * BSP
                                     + wn * 32 + nt * 8 + (lane >> 2);
                b[nt][0] = __float_as_uint(bp[0]);
                b[nt][1] = __float_as_uint(bp[4 * BSP]);
            }
            #pragma unroll
            for (int mt = 0; mt < 4; mt++)
                #pragma unroll
                for (int nt = 0; nt < 4; nt++)
                    mma_tf32(acc[mt][nt], a[mt], b[nt]);
        }
        if (kt + 2 < KT) PREFETCH((kt + 2) % ST, (kt + 2) * BK);
        cp_commit();
    }
    #undef PREFETCH

    if (STATS) {
        sst[0][sg][sc] = s_sum;
        sst[1][sg][sc] = s_sq;
        __syncthreads();
        if (tid < BN) {
            float S = 0.f, SS = 0.f;
            #pragma unroll
            for (int g = 0; g < SH; g++) { S += sst[0][g][tid]; SS += sst[1][g][tid]; }
            float m = S * (1.f / 128.f);
            float var = SS * (1.f / 128.f) - m * m;
            sst[0][0][tid] = m;
            sst[1][0][tid] = rsqrtf(var + eps);
        }
        __syncthreads();
    }

    #pragma unroll
    for (int mt = 0; mt < 4; mt++) {
        #pragma unroll
        for (int half = 0; half < 2; half++) {
            int row = m0 + wm * 64 + mt * 16 + (lane >> 2) + half * 8;
            float sgr = 0.f, cstr = 0.f, br2 = 0.f;
            if (MODE == 2) { sgr = Sg[row]; cstr = Cst[row]; }
            else br2 = bias[row];
            #pragma unroll
            for (int nt = 0; nt < 4; nt++) {
                #pragma unroll
                for (int e = 0; e < 2; e++) {
                    int pl = wn * 32 + nt * 8 + (lane & 3) * 2 + e;
                    int p = n0 + pl;
                    float v = acc[mt][nt][half * 2 + e];
                    if (MODE == 2) {
                        float mv = sst[0][0][pl], rv = sst[1][0][pl];
                        v = rv * v + (cstr - mv * rv * sgr);
                        v = v / (1.f + __expf(-v));
                        O0[((size_t)u * 256 + row) * HW + p] = v;
                    } else {
                        v += br2;
                        size_t idx = ((size_t)u * 128 + row) * HW + p;
                        O0[idx] += v;
                    }
                }
            }
        }
    }
}

// ---------------- fp16 GEMM for the pointwise conv --------------------------
__global__ void __launch_bounds__(256)
gemm_pw_f16(const __half* __restrict__ A, const __half* __restrict__ B,
            float* __restrict__ Y, const float* __restrict__ bias) {
    constexpr int K = 768, BN = 64, BK = 32, ST = 3;
    constexpr int KT = K / BK;
    constexpr int ASPH = 40;
    constexpr int BSPH = BN + 8;
    constexpr int ASZ = 256 * ASPH;
    constexpr int BSZ = BK * BSPH;
    extern __shared__ __half smh[];
    __half* As = smh;
    __half* Bs = smh + ST * ASZ;

    int tid = threadIdx.x, lane = tid & 31, wid = tid >> 5;
    int wm = wid >> 1, wn = wid & 1;
    int n0 = blockIdx.x * BN, u = blockIdx.z;
    const __half* Bp = B + (size_t)u * K * HW + n0;

    float acc[4][4][4];
    #pragma unroll
    for (int i = 0; i < 4; i++)
        #pragma unroll
        for (int j = 0; j < 4; j++)
            #pragma unroll
            for (int e = 0; e < 4; e++) acc[i][j][e] = 0.f;

    int aro[4], aco[4];
    #pragma unroll
    for (int i = 0; i < 4; i++) {
        int idx = tid + i * 256;
        aro[i] = idx >> 2; aco[i] = (idx & 3) << 3;
    }
    int brw = tid >> 3, bcl = (tid & 7) << 3;

    int arow_l = lane & 15, acol_l = (lane >> 4) << 3;
    int brow_l = (lane & 7) + ((lane >> 3) & 1) * 8;
    uint32_t as_base = smem_u32(As);
    uint32_t bs_base = smem_u32(Bs);

    #define PF16(sidx, k0)                                                         \
        {   _Pragma("unroll")                                                      \
            for (int i = 0; i < 4; i++)                                            \
                cp16(smem_u32(&As[(sidx) * ASZ + aro[i] * ASPH + aco[i]]),         \
                     A + (size_t)aro[i] * K + (k0) + aco[i]);                      \
            cp16(smem_u32(&Bs[(sidx) * BSZ + brw * BSPH + bcl]),                   \
                 Bp + (size_t)((k0) + brw) * HW + bcl);                            \
        }

    PF16(0, 0); cp_commit();
    PF16(1, BK); cp_commit();

    for (int kt = 0; kt < KT; kt++) {
        cp_wait1();
        __syncthreads();
        int st = kt % ST;
        uint32_t abase = as_base + (uint32_t)(st * ASZ + (wm * 64 + arow_l) * ASPH + acol_l) * 2;
        uint32_t bbase = bs_base + (uint32_t)(st * BSZ + brow_l * BSPH + wn * 32) * 2;
        #pragma unroll
        for (int s16 = 0; s16 < 2; s16++) {
            uint32_t a[4][4], b[4][2];
            #pragma unroll
            for (int mt = 0; mt < 4; mt++)
                ldsm4(a[mt], abase + (uint32_t)(mt * 16 * ASPH + s16 * 16) * 2);
            #pragma unroll
            for (int nt = 0; nt < 4; nt++)
                ldsm2t(b[nt], bbase + (uint32_t)(s16 * 16 * BSPH + nt * 8) * 2);
            #pragma unroll
            for (int mt = 0; mt < 4; mt++)
                #pragma unroll
                for (int nt = 0; nt < 4; nt++)
                    mma_f16(acc[mt][nt], a[mt], b[nt]);
        }
        if (kt + 2 < KT) PF16((kt + 2) % ST, (kt + 2) * BK);
        cp_commit();
    }
    #undef PF16

    #pragma unroll
    for (int mt = 0; mt < 4; mt++) {
        #pragma unroll
        for (int half = 0; half < 2; half++) {
            int row = wm * 64 + mt * 16 + (lane >> 2) + half * 8;
            float br2 = bias[row];
            #pragma unroll
            for (int nt = 0; nt < 4; nt++) {
                #pragma unroll
                for (int e = 0; e < 2; e++) {
                    int p = n0 + wn * 32 + nt * 8 + (lane & 3) * 2 + e;
                    float v = acc[mt][nt][half * 2 + e] + br2;
                    v = v / (1.f + __expf(-v));
                    size_t idx = ((size_t)u * 256 + row) * HW + p;
                    Y[idx] = Y[idx] + v;
                }
            }
        }
    }
}

// ---------------- fp16 GEMM for wo projection -------------------------------
__global__ void __launch_bounds__(256)
gemm_wo_f16(const __half* __restrict__ A, const __half* __restrict__ B,
            float* __restrict__ O0,
            const float* __restrict__ X1, const float* __restrict__ X2,
            const float* __restrict__ bias) {
    constexpr int K = 128, BM = 128, BN = 128, BK = 32, ST = 3;
    constexpr int KT = K / BK;
    constexpr int ASPH = 40;
    constexpr int BSPH = BN + 8;
    constexpr int ASZ = BM * ASPH;
    constexpr int BSZ = BK * BSPH;
    extern __shared__ __half smh[];
    __half* As = smh;
    __half* Bs = smh + ST * ASZ;

    int tid = threadIdx.x, lane = tid & 31, wid = tid >> 5;
    int wm = wid >> 2, wn = wid & 3;
    int n0 = blockIdx.x * BN, u = blockIdx.z;
    const __half* Bp = B + (size_t)u * K * HW + n0;

    float acc[4][4][4];
    #pragma unroll
    for (int i = 0; i < 4; i++)
        #pragma unroll
        for (int j = 0; j < 4; j++)
            #pragma unroll
            for (int e = 0; e < 4; e++) acc[i][j][e] = 0.f;

    int aro[2], aco[2];
    #pragma unroll
    for (int i = 0; i < 2; i++) {
        int idx = tid + i * 256;
        aro[i] = idx >> 2; aco[i] = (idx & 3) << 3;
    }
    int brw[2], bcl[2];
    #pragma unroll
    for (int i = 0; i < 2; i++) {
        int idx = tid + i * 256;
        brw[i] = idx >> 4; bcl[i] = (idx & 15) << 3;
    }

    int arow_l = lane & 15, acol_l = (lane >> 4) << 3;
    int brow_l = (lane & 7) + ((lane >> 3) & 1) * 8;
    uint32_t as_base = smem_u32(As);
    uint32_t bs_base = smem_u32(Bs);

    #define PFW(sidx, k0)                                                          \
        {   _Pragma("unroll")                                                      \
            for (int i = 0; i < 2; i++)                                            \
                cp16(smem_u32(&As[(sidx) * ASZ + aro[i] * ASPH + aco[i]]),         \
                     A + (size_t)aro[i] * K + (k0) + aco[i]);                      \
            _Pragma("unroll")                                                      \
            for (int i = 0; i < 2; i++)                                            \
                cp16(smem_u32(&Bs[(sidx) * BSZ + brw[i] * BSPH + bcl[i]]),         \
                     Bp + (size_t)((k0) + brw[i]) * HW + bcl[i]);                  \
        }

    PFW(0, 0); cp_commit();
    PFW(1, BK); cp_commit();

    for (int kt = 0; kt < KT; kt++) {
        cp_wait1();
        __syncthreads();
        int st = kt % ST;
        uint32_t abase = as_base + (uint32_t)(st * ASZ + (wm * 64 + arow_l) * ASPH + acol_l) * 2;
        uint32_t bbase = bs_base + (uint32_t)(st * BSZ + brow_l * BSPH + wn * 32) * 2;
        #pragma unroll
        for (int s16 = 0; s16 < 2; s16++) {
            uint32_t a[4][4], b[4][2];
            #pragma unroll
            for (int mt = 0; mt < 4; mt++)
                ldsm4(a[mt], abase + (uint32_t)(mt * 16 * ASPH + s16 * 16) * 2);
            #pragma unroll
            for (int nt = 0; nt < 4; nt++)
                ldsm2t(b[nt], bbase + (uint32_t)(s16 * 16 * BSPH + nt * 8) * 2);
            #pragma unroll
            for (int mt = 0; mt < 4; mt++)
                #pragma unroll
                for (int nt = 0; nt < 4; nt++)
                    mma_f16(acc[mt][nt], a[mt], b[nt]);
        }
        if (kt + 2 < KT) PFW((kt + 2) % ST, (kt + 2) * BK);
        cp_commit();
    }
    #undef PFW

    #pragma unroll
    for (int mt = 0; mt < 4; mt++) {
        #pragma unroll
        for (int half = 0; half < 2; half++) {
            int row = wm * 64 + mt * 16 + (lane >> 2) + half * 8;
            float br2 = bias[row];
            #pragma unroll
            for (int nt = 0; nt < 4; nt++) {
                #pragma unroll
                for (int e = 0; e < 2; e++) {
                    int p = n0 + wn * 32 + nt * 8 + (lane & 3) * 2 + e;
                    float res = ((u < 2 ? X1 : X2))[((size_t)(u & 1) * 128 + row) * HW + p];
                    size_t idx = ((size_t)u * 128 + row) * HW + p;
                    O0[idx] = acc[mt][nt][half * 2 + e] + br2 + res;
                }
            }
        }
    }
}

// ---------------- fp16 flash attention (register-direct P reuse) -------------
#define AT2_QS 0
#define AT2_VS 10240
#define AT2_KT 20480
#define AT2_HALVES 28928
#define ATTN2_SMEM (AT2_HALVES * 2 + 256 * 4 + 32 * 4)

__global__ void __launch_bounds__(256, 2)
attn_f16(const __half* __restrict__ Q, const __half* __restrict__ K,
         const __half* __restrict__ V, __half* __restrict__ O) {
    int blk = blockIdx.x;                  // b*256 + n*64 + h
    int h = blk & 63, n = (blk >> 6) & 3, b = blk >> 8;
    size_t base = ((size_t)(b * 128 + n * 32) * 64 + h) * 256;
    extern __shared__ __half smh2[];
    __half* Qs = smh2 + AT2_QS;            // [i][d] pitch 40
    __half* Vs = smh2 + AT2_VS;            // [j][d] pitch 40
    __half* Kt = smh2 + AT2_KT;            // [d][j] pitch 264
    float* V2 = (float*)(smh2 + AT2_HALVES);
    float* Vsum = V2 + 256;
    int tid = threadIdx.x, lane = tid & 31, w = tid >> 5;

    #pragma unroll 4
    for (int dd = 0; dd < 32; dd++) {
        Qs[tid * 40 + dd] = Q[base + (size_t)dd * HW + tid];
        Vs[tid * 40 + dd] = V[base + (size_t)dd * HW + tid];
    }
    #pragma unroll
    for (int i = 0; i < 4; i++) {
        int idx = tid + i * 256;
        int row = idx >> 5, seg = idx & 31;
        *(uint4*)&Kt[row * 264 + seg * 8] =
            *(const uint4*)&K[base + (size_t)row * HW + seg * 8];
    }
    __syncthreads();
    {
        float s = 0.f;
        #pragma unroll 8
        for (int jj = 0; jj < 32; jj++) s += __half2float(Vs[(w * 32 + jj) * 40 + lane]);
        V2[w * 32 + lane] = s;
    }

    int i0 = w * 32;
    uint32_t qa[2][2][4];
    #pragma unroll
    for (int mt = 0; mt < 2; mt++)
        #pragma unroll
        for (int dk = 0; dk < 2; dk++)
            ldsm4(qa[mt][dk],
                  smem_u32(&Qs[(i0 + mt * 16 + (lane & 15)) * 40 + dk * 16 + ((lane >> 4) << 3)]));
    int brow = (lane & 7) + ((lane >> 3) & 1) * 8;

    float l0[2] = {0.f, 0.f}, l1[2] = {0.f, 0.f};
    float o[2][4][4];
    #pragma unroll
    for (int mt = 0; mt < 2; mt++)
        #pragma unroll
        for (int dt = 0; dt < 4; dt++)
            #pragma unroll
            for (int e = 0; e < 4; e++) o[mt][dt][e] = 0.f;

    for (int j0 = 0; j0 < 256; j0 += 16) {
        float s[2][2][4];
        #pragma unroll
        for (int mt = 0; mt < 2; mt++)
            #pragma unroll
            for (int jh = 0; jh < 2; jh++)
                #pragma unroll
                for (int e = 0; e < 4; e++) s[mt][jh][e] = 0.f;
        uint32_t bS[2][2][2];
        #pragma unroll
        for (int dk = 0; dk < 2; dk++)
            #pragma unroll
            for (int jh = 0; jh < 2; jh++)
                ldsm2t(bS[dk][jh], smem_u32(&Kt[(dk * 16 + brow) * 264 + j0 + jh * 8]));
        #pragma unroll
        for (int mt = 0; mt < 2; mt++)
            #pragma unroll
            for (int jh = 0; jh < 2; jh++)
                #pragma unroll
                for (int dk = 0; dk < 2; dk++)
                    mma_f16(s[mt][jh], qa[mt][dk], bS[dk][jh]);
        uint32_t pa[2][4];
        #pragma unroll
        for (int mt = 0; mt < 2; mt++) {
            float p00 = fexp2(s[mt][0][0]), p01 = fexp2(s[mt][0][1]);
            float p02 = fexp2(s[mt][0][2]), p03 = fexp2(s[mt][0][3]);
            float p10 = fexp2(s[mt][1][0]), p11 = fexp2(s[mt][1][1]);
            float p12 = fexp2(s[mt][1][2]), p13 = fexp2(s[mt][1][3]);
            l0[mt] += p00 + p01 + p10 + p11;
            l1[mt] += p02 + p03 + p12 + p13;
            pa[mt][0] = packh2(p00, p01);
            pa[mt][1] = packh2(p02, p03);
            pa[mt][2] = packh2(p10, p11);
            pa[mt][3] = packh2(p12, p13);
        }
        uint32_t bV[4][2];
        #pragma unroll
        for (int dt = 0; dt < 4; dt++)
            ldsm2t(bV[dt], smem_u32(&Vs[(j0 + brow) * 40 + dt * 8]));
        #pragma unroll
        for (int mt = 0; mt < 2; mt++)
            #pragma unroll
            for (int dt = 0; dt < 4; dt++)
                mma_f16(o[mt][dt], pa[mt], bV[dt]);
    }
    #pragma unroll
    for (int mt = 0; mt < 2; mt++) {
        l0[mt] += __shfl_xor_sync(0xffffffffu, l0[mt], 1);
        l0[mt] += __shfl_xor_sync(0xffffffffu, l0[mt], 2);
        l1[mt] += __shfl_xor_sync(0xffffffffu, l1[mt], 1);
        l1[mt] += __shfl_xor_sync(0xffffffffu, l1[mt], 2);
    }

    __syncthreads();
    float* Ow = (float*)smh2 + w * 32 * 36;
    #pragma unroll
    for (int mt = 0; mt < 2; mt++)
        #pragma unroll
        for (int hf = 0; hf < 2; hf++) {
            float inv = 1.f / (hf == 0 ? l0[mt] : l1[mt]);
            int row = mt * 16 + (lane >> 2) + hf * 8;
            #pragma unroll
            for (int dt = 0; dt < 4; dt++) {
                Ow[row * 36 + dt * 8 + (lane & 3) * 2]     = o[mt][dt][hf * 2]     * inv;
                Ow[row * 36 + dt * 8 + (lane & 3) * 2 + 1] = o[mt][dt][hf * 2 + 1] * inv;
            }
        }
    if (tid < 32) {
        float s = 0.f;
        #pragma unroll
        for (int ww = 0; ww < 8; ww++) s += V2[ww * 32 + tid];
        Vsum[tid] = s;
    }
    __syncthreads();
    const float eps = 1e-6f;
    const float norm = 1.f / (1.f + 256.f * eps);
    #pragma unroll 4
    for (int d = 0; d < 32; d++) {
        float val = (Ow[lane * 36 + d] + eps * Vsum[d]) * norm;
        O[base + (size_t)d * HW + i0 + lane] = __float2half(val);
    }
}

// ---------------- depthwise 3x3 / 5x5 / 7x7 -> half F (fp32 in) -------------
__global__ void dw_kernel(const float* __restrict__ Y,
                          const float* __restrict__ w3, const float* __restrict__ b3,
                          const float* __restrict__ w5, const float* __restrict__ b5,
                          const float* __restrict__ w7, const float* __restrict__ b7,
                          __half* __restrict__ F) {
    __shared__ float S[14][70];
    __shared__ float wgt[84];
    int z = blockIdx.z; int ch = z & 255; int u = z >> 8;
    int w0 = blockIdx.x * 64, h0 = blockIdx.y * 8;
    int tid = threadIdx.x;
    if (tid < 9)       wgt[tid] = w3[ch * 9 + tid];
    else if (tid < 34) wgt[tid] = w5[ch * 25 + tid - 9];
    else if (tid < 83) wgt[tid] = w7[ch * 49 + tid - 34];
    const float* Yp = Y + ((size_t)u * 256 + ch) * HW;
    for (int i = tid; i < 980; i += 256) {
        int r = i / 70, c = i % 70;
        int gh = h0 - 3 + r, gw = w0 - 3 + c;
        float v = 0.f;
        if ((unsigned)gh < 64u && (unsigned)gw < 256u) v = Yp[gh * 256 + gw];
        S[r][c] = v;
    }
    __syncthreads();
    int tx = tid & 63, ty = tid >> 6;
    float bb3 = b3[ch], bb5 = b5[ch], bb7 = b7[ch];
    #pragma unroll
    for (int rr = 0; rr < 2; rr++) {
        int rc = ty + rr * 4 + 3, cc = tx + 3;
        float f3 = bb3, f5 = bb5, f7 = bb7;
        #pragma unroll
        for (int dy = -3; dy <= 3; dy++)
            #pragma unroll
            for (int dx = -3; dx <= 3; dx++) {
                float v = S[rc + dy][cc + dx];
                f7 += v * wgt[34 + (dy + 3) * 7 + (dx + 3)];
                if (dy >= -2 && dy <= 2 && dx >= -2 && dx <= 2)
                    f5 += v * wgt[9 + (dy + 2) * 5 + (dx + 2)];
                if (dy >= -1 && dy <= 1 && dx >= -1 && dx <= 1)
                    f3 += v * wgt[(dy + 1) * 3 + (dx + 1)];
            }
        size_t pix = (size_t)(h0 + ty + rr * 4) * 256 + (w0 + tx);
        size_t ob = (size_t)u * 768 * HW + pix;
        F[ob + (size_t) ch        * HW] = __float2half(f3);
        F[ob + (size_t)(256 + ch) * HW] = __float2half(f5);
        F[ob + (size_t)(512 + ch) * HW] = __float2half(f7);
    }
}

// ---------------- host launcher --------------------------------------------
extern "C" void kernel_launch(void* const* d_in, const int* in_sizes, int n_in,
                              void* d_out, int out_size) {
    const float* feats1 = (const float*)d_in[0];
    const float* feats2 = (const float*)d_in[1];
    const float* an_g  = (const float*)d_in[2];
    const float* an_b  = (const float*)d_in[3];
    const float* anc_g = (const float*)d_in[4];
    const float* anc_b = (const float*)d_in[5];
    const float* wq    = (const float*)d_in[6];
    const float* bq    = (const float*)d_in[7];
    const float* wkv   = (const float*)d_in[8];
    const float* bkv   = (const float*)d_in[9];
    const float* wo    = (const float*)d_in[10];
    const float* bo    = (const float*)d_in[11];
    const float* fn_g  = (const float*)d_in[12];
    const float* fn_b  = (const float*)d_in[13];
    const float* w_in  = (const float*)d_in[14];
    const float* b_in  = (const float*)d_in[15];
    const float* w_dw3 = (const float*)d_in[16];
    const float* b_dw3 = (const float*)d_in[17];
    const float* w_dw5 = (const float*)d_in[18];
    const float* b_dw5 = (const float*)d_in[19];
    const float* w_dw7 = (const float*)d_in[20];
    const float* b_dw7 = (const float*)d_in[21];
    const float* w_pw  = (const float*)d_in[22];
    const float* b_pw  = (const float*)d_in[23];
    const float* w_out = (const float*)d_in[24];
    const float* b_out = (const float*)d_in[25];
    float* dout = (float*)d_out;

    float *Y, *WA, *SgA, *CA, *WIN, *SgI, *CI;
    __half *Qh, *Kh, *Vh, *Oh, *Fh, *WPWh, *WOh, *WAh, *X1h, *X2h;
    cudaGetSymbolAddress((void**)&Qh, g_Qh);
    cudaGetSymbolAddress((void**)&Kh, g_Kh);
    cudaGetSymbolAddress((void**)&Vh, g_Vh);
    cudaGetSymbolAddress((void**)&Oh, g_Oh);
    cudaGetSymbolAddress((void**)&Y,  g_Y);
    cudaGetSymbolAddress((void**)&Fh, g_Fh);
    cudaGetSymbolAddress((void**)&WPWh, g_WPWh);
    cudaGetSymbolAddress((void**)&WOh, g_WOh);
    cudaGetSymbolAddress((void**)&WAh, g_WAh);
    cudaGetSymbolAddress((void**)&X1h, g_X1h);
    cudaGetSymbolAddress((void**)&X2h, g_X2h);
    cudaGetSymbolAddress((void**)&WA, g_WA);
    cudaGetSymbolAddress((void**)&SgA, g_SgA);
    cudaGetSymbolAddress((void**)&CA, g_CA);
    cudaGetSymbolAddress((void**)&WIN, g_WIN);
    cudaGetSymbolAddress((void**)&SgI, g_SgI);
    cudaGetSymbolAddress((void**)&CI, g_CI);

    const int smB  = 3 * (256 * 20 + 16 * 72)  * 4;   // tf32 BM=256/BN=64
    const int smA  = 3 * (128 * 20 + 16 * 136) * 4;   // tf32 BM=128/BN=128
    const int smH  = 3 * (256 * 40 + 32 * 72)  * 2;   // f16 pw
    const int smW  = 3 * (128 * 40 + 32 * 136) * 2;   // f16 BM=128/BN=128: 56832
    cudaFuncSetAttribute((const void*)gemm_qkv_f16, cudaFuncAttributeMaxDynamicSharedMemorySize, smW);
    cudaFuncSetAttribute((const void*)gemm_tc<128, 2, 256, 64>,  cudaFuncAttributeMaxDynamicSharedMemorySize, smB);
    cudaFuncSetAttribute((const void*)gemm_tc<256, 4, 128, 128>, cudaFuncAttributeMaxDynamicSharedMemorySize, smA);
    cudaFuncSetAttribute((const void*)gemm_pw_f16, cudaFuncAttributeMaxDynamicSharedMemorySize, smH);
    cudaFuncSetAttribute((const void*)gemm_wo_f16, cudaFuncAttributeMaxDynamicSharedMemorySize, smW);
    cudaFuncSetAttribute((const void*)attn_f16, cudaFuncAttributeMaxDynamicSharedMemorySize, ATTN2_SMEM);

    // 1. weight prep + fp16 conversions (weights + feats)
    prep_kernel<<<640, 128>>>(wq, bq, wkv, bkv, an_g, an_b, anc_g, anc_b,
                              w_in, b_in, fn_g, fn_b);
    convh_kernel<<<768, 256>>>(w_pw, WPWh, 256 * 768);
    convh_kernel<<<64, 256>>>(wo, WOh, 128 * 128);
    convfeats_kernel<<<4096, 256>>>((const float4*)feats1, (const float4*)feats2,
                                    (uint2*)X1h, (uint2*)X2h, 2 * 128 * HW / 4);
    // 2. fp16 fused LN + q/kv projection -> fp16 Q (pre-scaled), K, V
    gemm_qkv_f16<<<dim3(128, 3, 4), 256, smW>>>(WAh, Qh, Kh, Vh, SgA, CA, X1h, X2h, 1e-6f);
    // 3. fp16 flash attention -> fp16 O
    attn_f16<<<1024, 256, ATTN2_SMEM>>>(Qh, Kh, Vh, Oh);
    // 4. fp16 wo projection + residual(feats fp32) -> d_out
    gemm_wo_f16<<<dim3(128, 1, 4), 256, smW>>>(WOh, Oh, dout, feats1, feats2, bo);
    // 5. fused LN + w_in + SiLU -> Y (tf32, fp32 B)
    gemm_tc<128, 2, 256, 64><<<dim3(256, 1, 4), 256, smB>>>(WIN, dout, Y, SgI, CI, nullptr, 1e-5f);
    // 6. depthwise 3/5/7 -> Fh (fp16)
    dw_kernel<<<dim3(4, 8, 1024), 256>>>(Y, w_dw3, b_dw3, w_dw5, b_dw5, w_dw7, b_dw7, Fh);
    // 7. fp16 pointwise GEMM + SiLU, Y += (fp32 RMW)
    gemm_pw_f16<<<dim3(256, 1, 4), 256, smH>>>(WPWh, Fh, Y, b_pw);
    // 8. w_out GEMM (tf32, K=256), d_out +=
    gemm_tc<256, 4, 128, 128><<<dim3(128, 1, 4), 256, smA>>>(w_out, Y, dout, nullptr, nullptr, b_out, 0.f);
}

// round 15
// speedup vs baseline: 1.2613x; 1.0410x over previous
#include <cuda_runtime.h>
#include <cuda_fp16.h>
#include <math.h>
#include <stdint.h>

#define HW 16384          // 64*256 pixels per (batch, channel) plane

// ---------------- scratch (static device globals; no allocation allowed) ----
__device__ __half g_Qh[4*128*HW];
__device__ __half g_Kh[4*128*HW];
__device__ __half g_Vh[4*128*HW];
__device__ __half g_Oh[4*128*HW];
__device__ __half g_X1h[2*128*HW];
__device__ __half g_X2h[2*128*HW];
__device__ float g_Y [4*256*HW];
__device__ __half g_Y2h[4*256*HW];
__device__ __half g_Fh[(size_t)4*768*HW];
__device__ __half g_WPWh[256*768];
__device__ __half g_WOh[128*128];
__device__ __half g_WOUTh[128*256];
__device__ __half g_WAh[384*128];
__device__ float g_WA [384*128], g_SgA[384], g_CA[384];
__device__ float g_WIN[256*128], g_SgI[256], g_CI[256];

#define QSCALE (0.17677669529663687f * 1.4426950408889634f)

// ---------------- small helpers --------------------------------------------
__device__ __forceinline__ uint32_t smem_u32(const void* p) {
    return (uint32_t)__cvta_generic_to_shared(p);
}
__device__ __forceinline__ void cp16(uint32_t dst, const void* src) {
    asm volatile("cp.async.cg.shared.global [%0], [%1], 16;\n" :: "r"(dst), "l"(src));
}
__device__ __forceinline__ void cp_commit() { asm volatile("cp.async.commit_group;\n"); }
__device__ __forceinline__ void cp_wait1()  { asm volatile("cp.async.wait_group 1;\n"); }

__device__ __forceinline__ void mma_tf32(float* c, const uint32_t* a, const uint32_t* b) {
    asm volatile("mma.sync.aligned.m16n8k8.row.col.f32.tf32.tf32.f32 "
        "{%0,%1,%2,%3}, {%4,%5,%6,%7}, {%8,%9}, {%0,%1,%2,%3};"
        : "+f"(c[0]), "+f"(c[1]), "+f"(c[2]), "+f"(c[3])
        : "r"(a[0]), "r"(a[1]), "r"(a[2]), "r"(a[3]), "r"(b[0]), "r"(b[1]));
}
__device__ __forceinline__ void mma_f16(float* c, const uint32_t* a, const uint32_t* b) {
    asm volatile("mma.sync.aligned.m16n8k16.row.col.f32.f16.f16.f32 "
        "{%0,%1,%2,%3}, {%4,%5,%6,%7}, {%8,%9}, {%0,%1,%2,%3};"
        : "+f"(c[0]), "+f"(c[1]), "+f"(c[2]), "+f"(c[3])
        : "r"(a[0]), "r"(a[1]), "r"(a[2]), "r"(a[3]), "r"(b[0]), "r"(b[1]));
}
__device__ __forceinline__ void ldsm4(uint32_t* r, uint32_t addr) {
    asm volatile("ldmatrix.sync.aligned.m8n8.x4.shared.b16 {%0,%1,%2,%3}, [%4];"
        : "=r"(r[0]), "=r"(r[1]), "=r"(r[2]), "=r"(r[3]) : "r"(addr));
}
__device__ __forceinline__ void ldsm2t(uint32_t* r, uint32_t addr) {
    asm volatile("ldmatrix.sync.aligned.m8n8.x2.trans.shared.b16 {%0,%1}, [%2];"
        : "=r"(r[0]), "=r"(r[1]) : "r"(addr));
}
__device__ __forceinline__ float fexp2(float x) {
    float r; asm("ex2.approx.ftz.f32 %0, %1;" : "=f"(r) : "f"(x)); return r;
}
__device__ __forceinline__ uint32_t packh2(float a, float b) {
    __half2 h = __floats2half2_rn(a, b);
    return *(uint32_t*)&h;
}

// ---------------- fold LN gamma/beta into GEMM weights ---------------------
__global__ void prep_kernel(const float* __restrict__ wq,  const float* __restrict__ bq,
                            const float* __restrict__ wkv, const float* __restrict__ bkv,
                            const float* __restrict__ an_g, const float* __restrict__ an_b,
                            const float* __restrict__ anc_g, const float* __restrict__ anc_b,
                            const float* __restrict__ w_in, const float* __restrict__ b_in,
                            const float* __restrict__ fn_g, const float* __restrict__ fn_b) {
    int r = blockIdx.x, t = threadIdx.x;   // 640 blocks x 128 threads
    __shared__ float red[2][4];
    float wl, gg, bb, extra;
    float *Wdst, *Sgd, *Cd;
    if (r < 128)      { wl = wq [r*128 + t];        gg = an_g[t];  bb = an_b[t];  extra = bq [r];
                        Wdst = g_WA  + r*128;        Sgd = g_SgA + r;  Cd = g_CA + r; }
    else if (r < 384) { int rr = r - 128;
                        wl = wkv[rr*128 + t];       gg = anc_g[t]; bb = anc_b[t]; extra = bkv[rr];
                        Wdst = g_WA  + r*128;        Sgd = g_SgA + r;  Cd = g_CA + r; }
    else              { int rr = r - 384;
                        wl = w_in[rr*128 + t];      gg = fn_g[t];  bb = fn_b[t];  extra = b_in[rr];
                        Wdst = g_WIN + rr*128;       Sgd = g_SgI + rr; Cd = g_CI + rr; }
    float wg = wl * gg;
    Wdst[t] = wg;
    if (r < 384) g_WAh[r*128 + t] = __float2half(wg);
    float s1 = wg, s2 = wl * bb;
    #pragma unroll
    for (int off = 16; off; off >>= 1) {
        s1 += __shfl_down_sync(0xffffffffu, s1, off);
        s2 += __shfl_down_sync(0xffffffffu, s2, off);
    }
    if ((t & 31) == 0) { red[0][t >> 5] = s1; red[1][t >> 5] = s2; }
    __syncthreads();
    if (t == 0) {
        float a = red[0][0] + red[0][1] + red[0][2] + red[0][3];
        float b = red[1][0] + red[1][1] + red[1][2] + red[1][3];
        *Sgd = a; *Cd = b + extra;
    }
}

// ---------------- convert fp32 weights to fp16 ------------------------------
__global__ void convh_kernel(const float* __restrict__ W, __half* __restrict__ Wh, int n) {
    int i = blockIdx.x * 256 + threadIdx.x;
    if (i < n) Wh[i] = __float2half(W[i]);
}

// ---------------- convert feats to fp16 (vectorized) ------------------------
__global__ void convfeats_kernel(const float4* __restrict__ s1, const float4* __restrict__ s2,
                                 uint2* __restrict__ d1, uint2* __restrict__ d2, int n4) {
    int i = blockIdx.x * 256 + threadIdx.x;
    if (i < n4) {
        float4 a = s1[i];
        uint2 o;
        o.x = packh2(a.x, a.y); o.y = packh2(a.z, a.w);
        d1[i] = o;
        float4 b = s2[i];
        o.x = packh2(b.x, b.y); o.y = packh2(b.z, b.w);
        d2[i] = o;
    }
}

// ---------------- fp16 q/kv GEMM, LN-fused with in-kernel stats -------------
__global__ void __launch_bounds__(256)
gemm_qkv_f16(const __half* __restrict__ A,
             __half* __restrict__ Qo, __half* __restrict__ Ko, __half* __restrict__ Vo,
             const float* __restrict__ Sg, const float* __restrict__ Cst,
             const __half* __restrict__ X1h, const __half* __restrict__ X2h, float eps) {
    constexpr int K = 128, BM = 128, BN = 128, BK = 32, ST = 3;
    constexpr int KT = K / BK;
    constexpr int ASPH = 40;
    constexpr int BSPH = BN + 8;
    constexpr int ASZ = BM * ASPH;
    constexpr int BSZ = BK * BSPH;
    extern __shared__ __half smh[];
    __half* As = smh;
    __half* Bs = smh + ST * ASZ;
    __shared__ float sst[2][2][BN];

    int tid = threadIdx.x, lane = tid & 31, wid = tid >> 5;
    int wm = wid >> 2, wn = wid & 3;
    int n0 = blockIdx.x * BN, m0 = blockIdx.y * BM, u = blockIdx.z;
    const __half* Ap = A + (size_t)m0 * K;
    const __half* Bp = (u < 2 ? X1h : X2h) + (size_t)(u & 1) * 128 * HW + n0;

    float acc[4][4][4];
    #pragma unroll
    for (int i = 0; i < 4; i++)
        #pragma unroll
        for (int j = 0; j < 4; j++)
            #pragma unroll
            for (int e = 0; e < 4; e++) acc[i][j][e] = 0.f;

    int aro[2], aco[2];
    #pragma unroll
    for (int i = 0; i < 2; i++) {
        int idx = tid + i * 256;
        aro[i] = idx >> 2; aco[i] = (idx & 3) << 3;
    }
    int brw[2], bcl[2];
    #pragma unroll
    for (int i = 0; i < 2; i++) {
        int idx = tid + i * 256;
        brw[i] = idx >> 4; bcl[i] = (idx & 15) << 3;
    }
    int sc = tid & 127, sg = tid >> 7;
    float s_sum = 0.f, s_sq = 0.f;

    int arow_l = lane & 15, acol_l = (lane >> 4) << 3;
    int brow_l = (lane & 7) + ((lane >> 3) & 1) * 8;
    uint32_t as_base = smem_u32(As);
    uint32_t bs_base = smem_u32(Bs);

    #define PFQ(sidx, k0)                                                          \
        {   _Pragma("unroll")                                                      \
            for (int i = 0; i < 2; i++)                                            \
                cp16(smem_u32(&As[(sidx) * ASZ + aro[i] * ASPH + aco[i]]),         \
                     Ap + (size_t)aro[i] * K + (k0) + aco[i]);                     \
            _Pragma("unroll")                                                      \
            for (int i = 0; i < 2; i++)                                            \
                cp16(smem_u32(&Bs[(sidx) * BSZ + brw[i] * BSPH + bcl[i]]),         \
                     Bp + (size_t)((k0) + brw[i]) * HW + bcl[i]);                  \
        }

    PFQ(0, 0); cp_commit();
    PFQ(1, BK); cp_commit();

    for (int kt = 0; kt < KT; kt++) {
        cp_wait1();
        __syncthreads();
        int st = kt % ST;
        const __half* bs = Bs + st * BSZ;
        #pragma unroll
        for (int rr = 0; rr < 16; rr++) {
            float v = __half2float(bs[(sg * 16 + rr) * BSPH + sc]);
            s_sum += v; s_sq += v * v;
        }
        uint32_t abase = as_base + (uint32_t)(st * ASZ + (wm * 64 + arow_l) * ASPH + acol_l) * 2;
        uint32_t bbase = bs_base + (uint32_t)(st * BSZ + brow_l * BSPH + wn * 32) * 2;
        #pragma unroll
        for (int s16 = 0; s16 < 2; s16++) {
            uint32_t a[4][4], b[4][2];
            #pragma unroll
            for (int mt = 0; mt < 4; mt++)
                ldsm4(a[mt], abase + (uint32_t)(mt * 16 * ASPH + s16 * 16) * 2);
            #pragma unroll
            for (int nt = 0; nt < 4; nt++)
                ldsm2t(b[nt], bbase + (uint32_t)(s16 * 16 * BSPH + nt * 8) * 2);
            #pragma unroll
            for (int mt = 0; mt < 4; mt++)
                #pragma unroll
                for (int nt = 0; nt < 4; nt++)
                    mma_f16(acc[mt][nt], a[mt], b[nt]);
        }
        if (kt + 2 < KT) PFQ((kt + 2) % ST, (kt + 2) * BK);
        cp_commit();
    }
    #undef PFQ

    sst[0][sg][sc] = s_sum;
    sst[1][sg][sc] = s_sq;
    __syncthreads();
    if (tid < BN) {
        float S = sst[0][0][tid] + sst[0][1][tid];
        float SS = sst[1][0][tid] + sst[1][1][tid];
        float m = S * (1.f / 128.f);
        float var = SS * (1.f / 128.f) - m * m;
        sst[0][0][tid] = m;
        sst[1][0][tid] = rsqrtf(var + eps);
    }
    __syncthreads();

    #pragma unroll
    for (int mt = 0; mt < 4; mt++) {
        #pragma unroll
        for (int half = 0; half < 2; half++) {
            int row = m0 + wm * 64 + mt * 16 + (lane >> 2) + half * 8;
            float sgr = Sg[row], cstr = Cst[row];
            #pragma unroll
            for (int nt = 0; nt < 4; nt++) {
                #pragma unroll
                for (int e = 0; e < 2; e++) {
                    int pl = wn * 32 + nt * 8 + (lane & 3) * 2 + e;
                    int p = n0 + pl;
                    float v = acc[mt][nt][half * 2 + e];
                    float mv = sst[0][0][pl], rv = sst[1][0][pl];
                    v = rv * v + (cstr - mv * rv * sgr);
                    if (row < 128)
                        Qo[((size_t)u * 128 + row) * HW + p] = __float2half(v * QSCALE);
                    else if (row < 256)
                        Ko[((size_t)(u ^ 2) * 128 + (row - 128)) * HW + p] = __float2half(v);
                    else
                        Vo[((size_t)(u ^ 2) * 128 + (row - 256)) * HW + p] = __float2half(v);
                }
            }
        }
    }
}

// ---------------- tf32 GEMM (MODE 2: w_in, LN-fused) ------------------------
template<int K, int MODE, int BM, int BN>
__global__ void __launch_bounds__(256)
gemm_tc(const float* __restrict__ A, const float* __restrict__ B,
        float* __restrict__ O0,
        const float* __restrict__ Sg, const float* __restrict__ Cst,
        const float* __restrict__ bias, float eps) {
    constexpr int BK = 16, ST = 3;
    constexpr int KT = K / BK;
    constexpr int ASP = 20;
    constexpr int BSP = BN + 8;
    constexpr int ASZ = BM * ASP;
    constexpr int BSZ = BK * BSP;
    constexpr int NA = BM / 64;
    constexpr int NB = BN / 64;
    constexpr int WN = (BM == 128) ? 4 : 2;
    constexpr bool STATS = (MODE == 2);
    constexpr int SH = (BN == 64) ? 4 : 2;
    constexpr int RT = 16 / SH;
    extern __shared__ float smf[];
    float* As = smf;
    float* Bs = smf + ST * ASZ;
    __shared__ float sst[STATS ? 2 : 1][STATS ? SH : 1][STATS ? BN : 1];

    int tid = threadIdx.x, lane = tid & 31, wid = tid >> 5;
    int wm = wid / WN, wn = wid % WN;
    int n0 = blockIdx.x * BN, m0 = blockIdx.y * BM, u = blockIdx.z;
    const float* Ap = A + (size_t)m0 * K;
    const float* Bp = B + (size_t)u * K * HW + n0;

    float acc[4][4][4];
    #pragma unroll
    for (int i = 0; i < 4; i++)
        #pragma unroll
        for (int j = 0; j < 4; j++)
            #pragma unroll
            for (int e = 0; e < 4; e++) acc[i][j][e] = 0.f;

    int ar[NA], ac[NA], br[NB], bc[NB];
    #pragma unroll
    for (int i = 0; i < NA; i++) {
        int idx = tid + i * 256;
        ar[i] = idx >> 2; ac[i] = (idx & 3) << 2;
    }
    #pragma unroll
    for (int i = 0; i < NB; i++) {
        int idx = tid + i * 256;
        br[i] = idx / (BN / 4); bc[i] = (idx % (BN / 4)) << 2;
    }
    int sc = tid % BN, sg = tid / BN;
    float s_sum = 0.f, s_sq = 0.f;
    int lm = lane >> 3;
    int loff = (((lane & 7) + (lm & 1) * 8)) * ASP + (lm >> 1) * 4;
    uint32_t as_base = smem_u32(As);

    #define PREFETCH(sidx, k0)                                                     \
        {   _Pragma("unroll")                                                      \
            for (int i = 0; i < NA; i++)                                           \
                cp16(smem_u32(&As[(sidx) * ASZ + ar[i] * ASP + ac[i]]),            \
                     Ap + (size_t)ar[i] * K + (k0) + ac[i]);                       \
            _Pragma("unroll")                                                      \
            for (int i = 0; i < NB; i++)                                           \
                cp16(smem_u32(&Bs[(sidx) * BSZ + br[i] * BSP + bc[i]]),            \
                     Bp + (size_t)((k0) + br[i]) * HW + bc[i]);                    \
        }

    PREFETCH(0, 0); cp_commit();
    if (KT > 1) PREFETCH(1, BK);
    cp_commit();

    for (int kt = 0; kt < KT; kt++) {
        cp_wait1();
        __syncthreads();
        int st = kt % ST;
        const float* bs = Bs + st * BSZ;
        if (STATS) {
            #pragma unroll
            for (int rr = 0; rr < RT; rr++) {
                float v = bs[(sg * RT + rr) * BSP + sc];
                s_sum += v; s_sq += v * v;
            }
        }
        uint32_t abase = as_base + (uint32_t)(st * ASZ + wm * 64 * ASP + loff) * 4;
        #pragma unroll
        for (int s8 = 0; s8 < 2; s8++) {
            uint32_t a[4][4], b[4][2];
            #pragma unroll
            for (int mt = 0; mt < 4; mt++)
                ldsm4(a[mt], abase + (uint32_t)(mt * 16 * ASP + s8 * 8) * 4);
            #pragma unroll
            for (int nt = 0; nt < 4; nt++) {
                const float* bp = bs + (s8 * 8 + (lane & 3)) * BSP
                                     + wn * 32 + nt * 8 + (lane >> 2);
                b[nt][0] = __float_as_uint(bp[0]);
                b[nt][1] = __float_as_uint(bp[4 * BSP]);
            }
            #pragma unroll
            for (int mt = 0; mt < 4; mt++)
                #pragma unroll
                for (int nt = 0; nt < 4; nt++)
                    mma_tf32(acc[mt][nt], a[mt], b[nt]);
        }
        if (kt + 2 < KT) PREFETCH((kt + 2) % ST, (kt + 2) * BK);
        cp_commit();
    }
    #undef PREFETCH

    if (STATS) {
        sst[0][sg][sc] = s_sum;
        sst[1][sg][sc] = s_sq;
        __syncthreads();
        if (tid < BN) {
            float S = 0.f, SS = 0.f;
            #pragma unroll
            for (int g = 0; g < SH; g++) { S += sst[0][g][tid]; SS += sst[1][g][tid]; }
            float m = S * (1.f / 128.f);
            float var = SS * (1.f / 128.f) - m * m;
            sst[0][0][tid] = m;
            sst[1][0][tid] = rsqrtf(var + eps);
        }
        __syncthreads();
    }

    #pragma unroll
    for (int mt = 0; mt < 4; mt++) {
        #pragma unroll
        for (int half = 0; half < 2; half++) {
            int row = m0 + wm * 64 + mt * 16 + (lane >> 2) + half * 8;
            float sgr = 0.f, cstr = 0.f, br2 = 0.f;
            if (MODE == 2) { sgr = Sg[row]; cstr = Cst[row]; }
            else br2 = bias[row];
            #pragma unroll
            for (int nt = 0; nt < 4; nt++) {
                #pragma unroll
                for (int e = 0; e < 2; e++) {
                    int pl = wn * 32 + nt * 8 + (lane & 3) * 2 + e;
                    int p = n0 + pl;
                    float v = acc[mt][nt][half * 2 + e];
                    if (MODE == 2) {
                        float mv = sst[0][0][pl], rv = sst[1][0][pl];
                        v = rv * v + (cstr - mv * rv * sgr);
                        v = v / (1.f + __expf(-v));
                        O0[((size_t)u * 256 + row) * HW + p] = v;
                    } else {
                        v += br2;
                        size_t idx = ((size_t)u * 128 + row) * HW + p;
                        O0[idx] += v;
                    }
                }
            }
        }
    }
}

// ---------------- fp16 GEMM for the pointwise conv (writes fp16 Y2h) --------
__global__ void __launch_bounds__(256)
gemm_pw_f16(const __half* __restrict__ A, const __half* __restrict__ B,
            const float* __restrict__ Y, __half* __restrict__ Y2h,
            const float* __restrict__ bias) {
    constexpr int K = 768, BN = 64, BK = 32, ST = 3;
    constexpr int KT = K / BK;
    constexpr int ASPH = 40;
    constexpr int BSPH = BN + 8;
    constexpr int ASZ = 256 * ASPH;
    constexpr int BSZ = BK * BSPH;
    extern __shared__ __half smh[];
    __half* As = smh;
    __half* Bs = smh + ST * ASZ;

    int tid = threadIdx.x, lane = tid & 31, wid = tid >> 5;
    int wm = wid >> 1, wn = wid & 1;
    int n0 = blockIdx.x * BN, u = blockIdx.z;
    const __half* Bp = B + (size_t)u * K * HW + n0;

    float acc[4][4][4];
    #pragma unroll
    for (int i = 0; i < 4; i++)
        #pragma unroll
        for (int j = 0; j < 4; j++)
            #pragma unroll
            for (int e = 0; e < 4; e++) acc[i][j][e] = 0.f;

    int aro[4], aco[4];
    #pragma unroll
    for (int i = 0; i < 4; i++) {
        int idx = tid + i * 256;
        aro[i] = idx >> 2; aco[i] = (idx & 3) << 3;
    }
    int brw = tid >> 3, bcl = (tid & 7) << 3;

    int arow_l = lane & 15, acol_l = (lane >> 4) << 3;
    int brow_l = (lane & 7) + ((lane >> 3) & 1) * 8;
    uint32_t as_base = smem_u32(As);
    uint32_t bs_base = smem_u32(Bs);

    #define PF16(sidx, k0)                                                         \
        {   _Pragma("unroll")                                                      \
            for (int i = 0; i < 4; i++)                                            \
                cp16(smem_u32(&As[(sidx) * ASZ + aro[i] * ASPH + aco[i]]),         \
                     A + (size_t)aro[i] * K + (k0) + aco[i]);                      \
            cp16(smem_u32(&Bs[(sidx) * BSZ + brw * BSPH + bcl]),                   \
                 Bp + (size_t)((k0) + brw) * HW + bcl);                            \
        }

    PF16(0, 0); cp_commit();
    PF16(1, BK); cp_commit();

    for (int kt = 0; kt < KT; kt++) {
        cp_wait1();
        __syncthreads();
        int st = kt % ST;
        uint32_t abase = as_base + (uint32_t)(st * ASZ + (wm * 64 + arow_l) * ASPH + acol_l) * 2;
        uint32_t bbase = bs_base + (uint32_t)(st * BSZ + brow_l * BSPH + wn * 32) * 2;
        #pragma unroll
        for (int s16 = 0; s16 < 2; s16++) {
            uint32_t a[4][4], b[4][2];
            #pragma unroll
            for (int mt = 0; mt < 4; mt++)
                ldsm4(a[mt], abase + (uint32_t)(mt * 16 * ASPH + s16 * 16) * 2);
            #pragma unroll
            for (int nt = 0; nt < 4; nt++)
                ldsm2t(b[nt], bbase + (uint32_t)(s16 * 16 * BSPH + nt * 8) * 2);
            #pragma unroll
            for (int mt = 0; mt < 4; mt++)
                #pragma unroll
                for (int nt = 0; nt < 4; nt++)
                    mma_f16(acc[mt][nt], a[mt], b[nt]);
        }
        if (kt + 2 < KT) PF16((kt + 2) % ST, (kt + 2) * BK);
        cp_commit();
    }
    #undef PF16

    #pragma unroll
    for (int mt = 0; mt < 4; mt++) {
        #pragma unroll
        for (int half = 0; half < 2; half++) {
            int row = wm * 64 + mt * 16 + (lane >> 2) + half * 8;
            float br2 = bias[row];
            #pragma unroll
            for (int nt = 0; nt < 4; nt++) {
                int p0 = n0 + wn * 32 + nt * 8 + (lane & 3) * 2;
                size_t idx = ((size_t)u * 256 + row) * HW + p0;
                float v0 = acc[mt][nt][half * 2]     + br2;
                float v1 = acc[mt][nt][half * 2 + 1] + br2;
                v0 = v0 / (1.f + __expf(-v0));
                v1 = v1 / (1.f + __expf(-v1));
                v0 += Y[idx];
                v1 += Y[idx + 1];
                *(uint32_t*)&Y2h[idx] = packh2(v0, v1);
            }
        }
    }
}

// ---------------- fp16 GEMM: generic WxB, fp32 accumulate-out ---------------
// MODE 1: wo (K=128), dout = v + bias + residual(feats)
// MODE 4: w_out (K=256, B = Y2h), dout += v + bias
template<int K, int MODE>
__global__ void __launch_bounds__(256)
gemm_f16o(const __half* __restrict__ A, const __half* __restrict__ B,
          float* __restrict__ O0,
          const float* __restrict__ X1, const float* __restrict__ X2,
          const float* __restrict__ bias) {
    constexpr int BM = 128, BN = 128, BK = 32, ST = 3;
    constexpr int KT = K / BK;
    constexpr int ASPH = 40;
    constexpr int BSPH = BN + 8;
    constexpr int ASZ = BM * ASPH;
    constexpr int BSZ = BK * BSPH;
    extern __shared__ __half smh[];
    __half* As = smh;
    __half* Bs = smh + ST * ASZ;

    int tid = threadIdx.x, lane = tid & 31, wid = tid >> 5;
    int wm = wid >> 2, wn = wid & 3;
    int n0 = blockIdx.x * BN, u = blockIdx.z;
    const __half* Bp = B + (size_t)u * K * HW + n0;

    float acc[4][4][4];
    #pragma unroll
    for (int i = 0; i < 4; i++)
        #pragma unroll
        for (int j = 0; j < 4; j++)
            #pragma unroll
            for (int e = 0; e < 4; e++) acc[i][j][e] = 0.f;

    int aro[2], aco[2];
    #pragma unroll
    for (int i = 0; i < 2; i++) {
        int idx = tid + i * 256;
        aro[i] = idx >> 2; aco[i] = (idx & 3) << 3;
    }
    int brw[2], bcl[2];
    #pragma unroll
    for (int i = 0; i < 2; i++) {
        int idx = tid + i * 256;
        brw[i] = idx >> 4; bcl[i] = (idx & 15) << 3;
    }

    int arow_l = lane & 15, acol_l = (lane >> 4) << 3;
    int brow_l = (lane & 7) + ((lane >> 3) & 1) * 8;
    uint32_t as_base = smem_u32(As);
    uint32_t bs_base = smem_u32(Bs);

    #define PFW(sidx, k0)                                                          \
        {   _Pragma("unroll")                                                      \
            for (int i = 0; i < 2; i++)                                            \
                cp16(smem_u32(&As[(sidx) * ASZ + aro[i] * ASPH + aco[i]]),         \
                     A + (size_t)aro[i] * K + (k0) + aco[i]);                      \
            _Pragma("unroll")                                                      \
            for (int i = 0; i < 2; i++)                                            \
                cp16(smem_u32(&Bs[(sidx) * BSZ + brw[i] * BSPH + bcl[i]]),         \
                     Bp + (size_t)((k0) + brw[i]) * HW + bcl[i]);                  \
        }

    PFW(0, 0); cp_commit();
    if (KT > 1) PFW(1, BK);
    cp_commit();

    for (int kt = 0; kt < KT; kt++) {
        cp_wait1();
        __syncthreads();
        int st = kt % ST;
        uint32_t abase = as_base + (uint32_t)(st * ASZ + (wm * 64 + arow_l) * ASPH + acol_l) * 2;
        uint32_t bbase = bs_base + (uint32_t)(st * BSZ + brow_l * BSPH + wn * 32) * 2;
        #pragma unroll
        for (int s16 = 0; s16 < 2; s16++) {
            uint32_t a[4][4], b[4][2];
            #pragma unroll
            for (int mt = 0; mt < 4; mt++)
                ldsm4(a[mt], abase + (uint32_t)(mt * 16 * ASPH + s16 * 16) * 2);
            #pragma unroll
            for (int nt = 0; nt < 4; nt++)
                ldsm2t(b[nt], bbase + (uint32_t)(s16 * 16 * BSPH + nt * 8) * 2);
            #pragma unroll
            for (int mt = 0; mt < 4; mt++)
                #pragma unroll
                for (int nt = 0; nt < 4; nt++)
                    mma_f16(acc[mt][nt], a[mt], b[nt]);
        }
        if (kt + 2 < KT) PFW((kt + 2) % ST, (kt + 2) * BK);
        cp_commit();
    }
    #undef PFW

    #pragma unroll
    for (int mt = 0; mt < 4; mt++) {
        #pragma unroll
        for (int half = 0; half < 2; half++) {
            int row = wm * 64 + mt * 16 + (lane >> 2) + half * 8;
            float br2 = bias[row];
            #pragma unroll
            for (int nt = 0; nt < 4; nt++) {
                #pragma unroll
                for (int e = 0; e < 2; e++) {
                    int p = n0 + wn * 32 + nt * 8 + (lane & 3) * 2 + e;
                    float v = acc[mt][nt][half * 2 + e] + br2;
                    size_t idx = ((size_t)u * 128 + row) * HW + p;
                    if (MODE == 1) {
                        float res = ((u < 2 ? X1 : X2))[((size_t)(u & 1) * 128 + row) * HW + p];
                        O0[idx] = v + res;
                    } else {
                        O0[idx] += v;
                    }
                }
            }
        }
    }
}

// ---------------- fp16 flash attention (register-direct P reuse) -------------
#define AT2_QS 0
#define AT2_VS 10240
#define AT2_KT 20480
#define AT2_HALVES 28928
#define ATTN2_SMEM (AT2_HALVES * 2 + 256 * 4 + 32 * 4)

__global__ void __launch_bounds__(256, 2)
attn_f16(const __half* __restrict__ Q, const __half* __restrict__ K,
         const __half* __restrict__ V, __half* __restrict__ O) {
    int blk = blockIdx.x;                  // b*256 + n*64 + h
    int h = blk & 63, n = (blk >> 6) & 3, b = blk >> 8;
    size_t base = ((size_t)(b * 128 + n * 32) * 64 + h) * 256;
    extern __shared__ __half smh2[];
    __half* Qs = smh2 + AT2_QS;
    __half* Vs = smh2 + AT2_VS;
    __half* Kt = smh2 + AT2_KT;
    float* V2 = (float*)(smh2 + AT2_HALVES);
    float* Vsum = V2 + 256;
    int tid = threadIdx.x, lane = tid & 31, w = tid >> 5;

    #pragma unroll 4
    for (int dd = 0; dd < 32; dd++) {
        Qs[tid * 40 + dd] = Q[base + (size_t)dd * HW + tid];
        Vs[tid * 40 + dd] = V[base + (size_t)dd * HW + tid];
    }
    #pragma unroll
    for (int i = 0; i < 4; i++) {
        int idx = tid + i * 256;
        int row = idx >> 5, seg = idx & 31;
        *(uint4*)&Kt[row * 264 + seg * 8] =
            *(const uint4*)&K[base + (size_t)row * HW + seg * 8];
    }
    __syncthreads();
    {
        float s = 0.f;
        #pragma unroll 8
        for (int jj = 0; jj < 32; jj++) s += __half2float(Vs[(w * 32 + jj) * 40 + lane]);
        V2[w * 32 + lane] = s;
    }

    int i0 = w * 32;
    uint32_t qa[2][2][4];
    #pragma unroll
    for (int mt = 0; mt < 2; mt++)
        #pragma unroll
        for (int dk = 0; dk < 2; dk++)
            ldsm4(qa[mt][dk],
                  smem_u32(&Qs[(i0 + mt * 16 + (lane & 15)) * 40 + dk * 16 + ((lane >> 4) << 3)]));
    int brow = (lane & 7) + ((lane >> 3) & 1) * 8;

    float l0[2] = {0.f, 0.f}, l1[2] = {0.f, 0.f};
    float o[2][4][4];
    #pragma unroll
    for (int mt = 0; mt < 2; mt++)
        #pragma unroll
        for (int dt = 0; dt < 4; dt++)
            #pragma unroll
            for (int e = 0; e < 4; e++) o[mt][dt][e] = 0.f;

    for (int j0 = 0; j0 < 256; j0 += 16) {
        float s[2][2][4];
        #pragma unroll
        for (int mt = 0; mt < 2; mt++)
            #pragma unroll
            for (int jh = 0; jh < 2; jh++)
                #pragma unroll
                for (int e = 0; e < 4; e++) s[mt][jh][e] = 0.f;
        uint32_t bS[2][2][2];
        #pragma unroll
        for (int dk = 0; dk < 2; dk++)
            #pragma unroll
            for (int jh = 0; jh < 2; jh++)
                ldsm2t(bS[dk][jh], smem_u32(&Kt[(dk * 16 + brow) * 264 + j0 + jh * 8]));
        #pragma unroll
        for (int mt = 0; mt < 2; mt++)
            #pragma unroll
            for (int jh = 0; jh < 2; jh++)
                #pragma unroll
                for (int dk = 0; dk < 2; dk++)
                    mma_f16(s[mt][jh], qa[mt][dk], bS[dk][jh]);
        uint32_t pa[2][4];
        #pragma unroll
        for (int mt = 0; mt < 2; mt++) {
            float p00 = fexp2(s[mt][0][0]), p01 = fexp2(s[mt][0][1]);
            float p02 = fexp2(s[mt][0][2]), p03 = fexp2(s[mt][0][3]);
            float p10 = fexp2(s[mt][1][0]), p11 = fexp2(s[mt][1][1]);
            float p12 = fexp2(s[mt][1][2]), p13 = fexp2(s[mt][1][3]);
            l0[mt] += p00 + p01 + p10 + p11;
            l1[mt] += p02 + p03 + p12 + p13;
            pa[mt][0] = packh2(p00, p01);
            pa[mt][1] = packh2(p02, p03);
            pa[mt][2] = packh2(p10, p11);
            pa[mt][3] = packh2(p12, p13);
        }
        uint32_t bV[4][2];
        #pragma unroll
        for (int dt = 0; dt < 4; dt++)
            ldsm2t(bV[dt], smem_u32(&Vs[(j0 + brow) * 40 + dt * 8]));
        #pragma unroll
        for (int mt = 0; mt < 2; mt++)
            #pragma unroll
            for (int dt = 0; dt < 4; dt++)
                mma_f16(o[mt][dt], pa[mt], bV[dt]);
    }
    #pragma unroll
    for (int mt = 0; mt < 2; mt++) {
        l0[mt] += __shfl_xor_sync(0xffffffffu, l0[mt], 1);
        l0[mt] += __shfl_xor_sync(0xffffffffu, l0[mt], 2);
        l1[mt] += __shfl_xor_sync(0xffffffffu, l1[mt], 1);
        l1[mt] += __shfl_xor_sync(0xffffffffu, l1[mt], 2);
    }

    __syncthreads();
    float* Ow = (float*)smh2 + w * 32 * 36;
    #pragma unroll
    for (int mt = 0; mt < 2; mt++)
        #pragma unroll
        for (int hf = 0; hf < 2; hf++) {
            float inv = 1.f / (hf == 0 ? l0[mt] : l1[mt]);
            int row = mt * 16 + (lane >> 2) + hf * 8;
            #pragma unroll
            for (int dt = 0; dt < 4; dt++) {
                Ow[row * 36 + dt * 8 + (lane & 3) * 2]     = o[mt][dt][hf * 2]     * inv;
                Ow[row * 36 + dt * 8 + (lane & 3) * 2 + 1] = o[mt][dt][hf * 2 + 1] * inv;
            }
        }
    if (tid < 32) {
        float s = 0.f;
        #pragma unroll
        for (int ww = 0; ww < 8; ww++) s += V2[ww * 32 + tid];
        Vsum[tid] = s;
    }
    __syncthreads();
    const float eps = 1e-6f;
    const float norm = 1.f / (1.f + 256.f * eps);
    #pragma unroll 4
    for (int d = 0; d < 32; d++) {
        float val = (Ow[lane * 36 + d] + eps * Vsum[d]) * norm;
        O[base + (size_t)d * HW + i0 + lane] = __float2half(val);
    }
}

// ---------------- depthwise 3x3 / 5x5 / 7x7 -> half F (fp32 in) -------------
__global__ void dw_kernel(const float* __restrict__ Y,
                          const float* __restrict__ w3, const float* __restrict__ b3,
                          const float* __restrict__ w5, const float* __restrict__ b5,
                          const float* __restrict__ w7, const float* __restrict__ b7,
                          __half* __restrict__ F) {
    __shared__ float S[14][70];
    __shared__ float wgt[84];
    int z = blockIdx.z; int ch = z & 255; int u = z >> 8;
    int w0 = blockIdx.x * 64, h0 = blockIdx.y * 8;
    int tid = threadIdx.x;
    if (tid < 9)       wgt[tid] = w3[ch * 9 + tid];
    else if (tid < 34) wgt[tid] = w5[ch * 25 + tid - 9];
    else if (tid < 83) wgt[tid] = w7[ch * 49 + tid - 34];
    const float* Yp = Y + ((size_t)u * 256 + ch) * HW;
    for (int i = tid; i < 980; i += 256) {
        int r = i / 70, c = i % 70;
        int gh = h0 - 3 + r, gw = w0 - 3 + c;
        float v = 0.f;
        if ((unsigned)gh < 64u && (unsigned)gw < 256u) v = Yp[gh * 256 + gw];
        S[r][c] = v;
    }
    __syncthreads();
    int tx = tid & 63, ty = tid >> 6;
    float bb3 = b3[ch], bb5 = b5[ch], bb7 = b7[ch];
    #pragma unroll
    for (int rr = 0; rr < 2; rr++) {
        int rc = ty + rr * 4 + 3, cc = tx + 3;
        float f3 = bb3, f5 = bb5, f7 = bb7;
        #pragma unroll
        for (int dy = -3; dy <= 3; dy++)
            #pragma unroll
            for (int dx = -3; dx <= 3; dx++) {
                float v = S[rc + dy][cc + dx];
                f7 += v * wgt[34 + (dy + 3) * 7 + (dx + 3)];
                if (dy >= -2 && dy <= 2 && dx >= -2 && dx <= 2)
                    f5 += v * wgt[9 + (dy + 2) * 5 + (dx + 2)];
                if (dy >= -1 && dy <= 1 && dx >= -1 && dx <= 1)
                    f3 += v * wgt[(dy + 1) * 3 + (dx + 1)];
            }
        size_t pix = (size_t)(h0 + ty + rr * 4) * 256 + (w0 + tx);
        size_t ob = (size_t)u * 768 * HW + pix;
        F[ob + (size_t) ch        * HW] = __float2half(f3);
        F[ob + (size_t)(256 + ch) * HW] = __float2half(f5);
        F[ob + (size_t)(512 + ch) * HW] = __float2half(f7);
    }
}

// ---------------- host launcher --------------------------------------------
extern "C" void kernel_launch(void* const* d_in, const int* in_sizes, int n_in,
                              void* d_out, int out_size) {
    const float* feats1 = (const float*)d_in[0];
    const float* feats2 = (const float*)d_in[1];
    const float* an_g  = (const float*)d_in[2];
    const float* an_b  = (const float*)d_in[3];
    const float* anc_g = (const float*)d_in[4];
    const float* anc_b = (const float*)d_in[5];
    const float* wq    = (const float*)d_in[6];
    const float* bq    = (const float*)d_in[7];
    const float* wkv   = (const float*)d_in[8];
    const float* bkv   = (const float*)d_in[9];
    const float* wo    = (const float*)d_in[10];
    const float* bo    = (const float*)d_in[11];
    const float* fn_g  = (const float*)d_in[12];
    const float* fn_b  = (const float*)d_in[13];
    const float* w_in  = (const float*)d_in[14];
    const float* b_in  = (const float*)d_in[15];
    const float* w_dw3 = (const float*)d_in[16];
    const float* b_dw3 = (const float*)d_in[17];
    const float* w_dw5 = (const float*)d_in[18];
    const float* b_dw5 = (const float*)d_in[19];
    const float* w_dw7 = (const float*)d_in[20];
    const float* b_dw7 = (const float*)d_in[21];
    const float* w_pw  = (const float*)d_in[22];
    const float* b_pw  = (const float*)d_in[23];
    const float* w_out = (const float*)d_in[24];
    const float* b_out = (const float*)d_in[25];
    float* dout = (float*)d_out;

    float *Y, *WA, *SgA, *CA, *WIN, *SgI, *CI;
    __half *Qh, *Kh, *Vh, *Oh, *Y2h, *Fh, *WPWh, *WOh, *WOUTh, *WAh, *X1h, *X2h;
    cudaGetSymbolAddress((void**)&Qh, g_Qh);
    cudaGetSymbolAddress((void**)&Kh, g_Kh);
    cudaGetSymbolAddress((void**)&Vh, g_Vh);
    cudaGetSymbolAddress((void**)&Oh, g_Oh);
    cudaGetSymbolAddress((void**)&Y,  g_Y);
    cudaGetSymbolAddress((void**)&Y2h, g_Y2h);
    cudaGetSymbolAddress((void**)&Fh, g_Fh);
    cudaGetSymbolAddress((void**)&WPWh, g_WPWh);
    cudaGetSymbolAddress((void**)&WOh, g_WOh);
    cudaGetSymbolAddress((void**)&WOUTh, g_WOUTh);
    cudaGetSymbolAddress((void**)&WAh, g_WAh);
    cudaGetSymbolAddress((void**)&X1h, g_X1h);
    cudaGetSymbolAddress((void**)&X2h, g_X2h);
    cudaGetSymbolAddress((void**)&WA, g_WA);
    cudaGetSymbolAddress((void**)&SgA, g_SgA);
    cudaGetSymbolAddress((void**)&CA, g_CA);
    cudaGetSymbolAddress((void**)&WIN, g_WIN);
    cudaGetSymbolAddress((void**)&SgI, g_SgI);
    cudaGetSymbolAddress((void**)&CI, g_CI);

    const int smB  = 3 * (256 * 20 + 16 * 72)  * 4;   // tf32 BM=256/BN=64
    const int smH  = 3 * (256 * 40 + 32 * 72)  * 2;   // f16 pw
    const int smW  = 3 * (128 * 40 + 32 * 136) * 2;   // f16 BM=128/BN=128
    cudaFuncSetAttribute((const void*)gemm_qkv_f16, cudaFuncAttributeMaxDynamicSharedMemorySize, smW);
    cudaFuncSetAttribute((const void*)gemm_tc<128, 2, 256, 64>, cudaFuncAttributeMaxDynamicSharedMemorySize, smB);
    cudaFuncSetAttribute((const void*)gemm_pw_f16, cudaFuncAttributeMaxDynamicSharedMemorySize, smH);
    cudaFuncSetAttribute((const void*)gemm_f16o<128, 1>, cudaFuncAttributeMaxDynamicSharedMemorySize, smW);
    cudaFuncSetAttribute((const void*)gemm_f16o<256, 4>, cudaFuncAttributeMaxDynamicSharedMemorySize, smW);
    cudaFuncSetAttribute((const void*)attn_f16, cudaFuncAttributeMaxDynamicSharedMemorySize, ATTN2_SMEM);

    // 1. weight prep + fp16 conversions (weights + feats)
    prep_kernel<<<640, 128>>>(wq, bq, wkv, bkv, an_g, an_b, anc_g, anc_b,
                              w_in, b_in, fn_g, fn_b);
    convh_kernel<<<768, 256>>>(w_pw, WPWh, 256 * 768);
    convh_kernel<<<64, 256>>>(wo, WOh, 128 * 128);
    convh_kernel<<<128, 256>>>(w_out, WOUTh, 128 * 256);
    convfeats_kernel<<<4096, 256>>>((const float4*)feats1, (const float4*)feats2,
                                    (uint2*)X1h, (uint2*)X2h, 2 * 128 * HW / 4);
    // 2. fp16 fused LN + q/kv projection -> fp16 Q (pre-scaled), K, V
    gemm_qkv_f16<<<dim3(128, 3, 4), 256, smW>>>(WAh, Qh, Kh, Vh, SgA, CA, X1h, X2h, 1e-6f);
    // 3. fp16 flash attention -> fp16 O
    attn_f16<<<1024, 256, ATTN2_SMEM>>>(Qh, Kh, Vh, Oh);
    // 4. fp16 wo projection + residual(feats fp32) -> d_out
    gemm_f16o<128, 1><<<dim3(128, 1, 4), 256, smW>>>(WOh, Oh, dout, feats1, feats2, bo);
    // 5. fused LN + w_in + SiLU -> Y (tf32)
    gemm_tc<128, 2, 256, 64><<<dim3(256, 1, 4), 256, smB>>>(WIN, dout, Y, SgI, CI, nullptr, 1e-5f);
    // 6. depthwise 3/5/7 -> Fh (fp16)
    dw_kernel<<<dim3(4, 8, 1024), 256>>>(Y, w_dw3, b_dw3, w_dw5, b_dw5, w_dw7, b_dw7, Fh);
    // 7. fp16 pointwise GEMM + SiLU + residual -> Y2h (fp16, no RMW)
    gemm_pw_f16<<<dim3(256, 1, 4), 256, smH>>>(WPWh, Fh, Y, Y2h, b_pw);
    // 8. fp16 w_out GEMM (K=256, reads Y2h), d_out +=
    gemm_f16o<256, 4><<<dim3(128, 1, 4), 256, smW>>>(WOUTh, Y2h, dout, nullptr, nullptr, b_out);
}

// round 16
// speedup vs baseline: 1.3385x; 1.0612x over previous
#include <cuda_runtime.h>
#include <cuda_fp16.h>
#include <math.h>
#include <stdint.h>

#define HW 16384          // 64*256 pixels per (batch, channel) plane

// ---------------- scratch (static device globals; no allocation allowed) ----
__device__ __half g_Qh[4*128*HW];
__device__ __half g_Kh[4*128*HW];
__device__ __half g_Vh[4*128*HW];
__device__ __half g_Oh[4*128*HW];
__device__ __half g_X1h[2*128*HW];
__device__ __half g_X2h[2*128*HW];
__device__ __half g_Yh[4*256*HW];
__device__ __half g_Y2h[4*256*HW];
__device__ __half g_Fh[(size_t)4*768*HW];
__device__ __half g_WPWh[256*768];
__device__ __half g_WOh[128*128];
__device__ __half g_WOUTh[128*256];
__device__ __half g_WAh[384*128];
__device__ float g_WA [384*128], g_SgA[384], g_CA[384];
__device__ float g_WIN[256*128], g_SgI[256], g_CI[256];

#define QSCALE (0.17677669529663687f * 1.4426950408889634f)

// ---------------- small helpers --------------------------------------------
__device__ __forceinline__ uint32_t smem_u32(const void* p) {
    return (uint32_t)__cvta_generic_to_shared(p);
}
__device__ __forceinline__ void cp16(uint32_t dst, const void* src) {
    asm volatile("cp.async.cg.shared.global [%0], [%1], 16;\n" :: "r"(dst), "l"(src));
}
__device__ __forceinline__ void cp_commit() { asm volatile("cp.async.commit_group;\n"); }
__device__ __forceinline__ void cp_wait1()  { asm volatile("cp.async.wait_group 1;\n"); }

__device__ __forceinline__ void mma_tf32(float* c, const uint32_t* a, const uint32_t* b) {
    asm volatile("mma.sync.aligned.m16n8k8.row.col.f32.tf32.tf32.f32 "
        "{%0,%1,%2,%3}, {%4,%5,%6,%7}, {%8,%9}, {%0,%1,%2,%3};"
        : "+f"(c[0]), "+f"(c[1]), "+f"(c[2]), "+f"(c[3])
        : "r"(a[0]), "r"(a[1]), "r"(a[2]), "r"(a[3]), "r"(b[0]), "r"(b[1]));
}
__device__ __forceinline__ void mma_f16(float* c, const uint32_t* a, const uint32_t* b) {
    asm volatile("mma.sync.aligned.m16n8k16.row.col.f32.f16.f16.f32 "
        "{%0,%1,%2,%3}, {%4,%5,%6,%7}, {%8,%9}, {%0,%1,%2,%3};"
        : "+f"(c[0]), "+f"(c[1]), "+f"(c[2]), "+f"(c[3])
        : "r"(a[0]), "r"(a[1]), "r"(a[2]), "r"(a[3]), "r"(b[0]), "r"(b[1]));
}
__device__ __forceinline__ void ldsm4(uint32_t* r, uint32_t addr) {
    asm volatile("ldmatrix.sync.aligned.m8n8.x4.shared.b16 {%0,%1,%2,%3}, [%4];"
        : "=r"(r[0]), "=r"(r[1]), "=r"(r[2]), "=r"(r[3]) : "r"(addr));
}
__device__ __forceinline__ void ldsm2t(uint32_t* r, uint32_t addr) {
    asm volatile("ldmatrix.sync.aligned.m8n8.x2.trans.shared.b16 {%0,%1}, [%2];"
        : "=r"(r[0]), "=r"(r[1]) : "r"(addr));
}
__device__ __forceinline__ float fexp2(float x) {
    float r; asm("ex2.approx.ftz.f32 %0, %1;" : "=f"(r) : "f"(x)); return r;
}
__device__ __forceinline__ uint32_t packh2(float a, float b) {
    __half2 h = __floats2half2_rn(a, b);
    return *(uint32_t*)&h;
}

// ---------------- fold LN gamma/beta into GEMM weights ---------------------
__global__ void prep_kernel(const float* __restrict__ wq,  const float* __restrict__ bq,
                            const float* __restrict__ wkv, const float* __restrict__ bkv,
                            const float* __restrict__ an_g, const float* __restrict__ an_b,
                            const float* __restrict__ anc_g, const float* __restrict__ anc_b,
                            const float* __restrict__ w_in, const float* __restrict__ b_in,
                            const float* __restrict__ fn_g, const float* __restrict__ fn_b) {
    int r = blockIdx.x, t = threadIdx.x;   // 640 blocks x 128 threads
    __shared__ float red[2][4];
    float wl, gg, bb, extra;
    float *Wdst, *Sgd, *Cd;
    if (r < 128)      { wl = wq [r*128 + t];        gg = an_g[t];  bb = an_b[t];  extra = bq [r];
                        Wdst = g_WA  + r*128;        Sgd = g_SgA + r;  Cd = g_CA + r; }
    else if (r < 384) { int rr = r - 128;
                        wl = wkv[rr*128 + t];       gg = anc_g[t]; bb = anc_b[t]; extra = bkv[rr];
                        Wdst = g_WA  + r*128;        Sgd = g_SgA + r;  Cd = g_CA + r; }
    else              { int rr = r - 384;
                        wl = w_in[rr*128 + t];      gg = fn_g[t];  bb = fn_b[t];  extra = b_in[rr];
                        Wdst = g_WIN + rr*128;       Sgd = g_SgI + rr; Cd = g_CI + rr; }
    float wg = wl * gg;
    Wdst[t] = wg;
    if (r < 384) g_WAh[r*128 + t] = __float2half(wg);
    float s1 = wg, s2 = wl * bb;
    #pragma unroll
    for (int off = 16; off; off >>= 1) {
        s1 += __shfl_down_sync(0xffffffffu, s1, off);
        s2 += __shfl_down_sync(0xffffffffu, s2, off);
    }
    if ((t & 31) == 0) { red[0][t >> 5] = s1; red[1][t >> 5] = s2; }
    __syncthreads();
    if (t == 0) {
        float a = red[0][0] + red[0][1] + red[0][2] + red[0][3];
        float b = red[1][0] + red[1][1] + red[1][2] + red[1][3];
        *Sgd = a; *Cd = b + extra;
    }
}

// ---------------- convert fp32 weights to fp16 ------------------------------
__global__ void convh_kernel(const float* __restrict__ W, __half* __restrict__ Wh, int n) {
    int i = blockIdx.x * 256 + threadIdx.x;
    if (i < n) Wh[i] = __float2half(W[i]);
}

// ---------------- convert feats to fp16 (vectorized) ------------------------
__global__ void convfeats_kernel(const float4* __restrict__ s1, const float4* __restrict__ s2,
                                 uint2* __restrict__ d1, uint2* __restrict__ d2, int n4) {
    int i = blockIdx.x * 256 + threadIdx.x;
    if (i < n4) {
        float4 a = s1[i];
        uint2 o;
        o.x = packh2(a.x, a.y); o.y = packh2(a.z, a.w);
        d1[i] = o;
        float4 b = s2[i];
        o.x = packh2(b.x, b.y); o.y = packh2(b.z, b.w);
        d2[i] = o;
    }
}

// ---------------- fp16 q/kv GEMM, LN-fused with in-kernel stats -------------
__global__ void __launch_bounds__(256)
gemm_qkv_f16(const __half* __restrict__ A,
             __half* __restrict__ Qo, __half* __restrict__ Ko, __half* __restrict__ Vo,
             const float* __restrict__ Sg, const float* __restrict__ Cst,
             const __half* __restrict__ X1h, const __half* __restrict__ X2h, float eps) {
    constexpr int K = 128, BM = 128, BN = 128, BK = 32, ST = 3;
    constexpr int KT = K / BK;
    constexpr int ASPH = 40;
    constexpr int BSPH = BN + 8;
    constexpr int ASZ = BM * ASPH;
    constexpr int BSZ = BK * BSPH;
    extern __shared__ __half smh[];
    __half* As = smh;
    __half* Bs = smh + ST * ASZ;
    __shared__ float sst[2][2][BN];

    int tid = threadIdx.x, lane = tid & 31, wid = tid >> 5;
    int wm = wid >> 2, wn = wid & 3;
    int n0 = blockIdx.x * BN, m0 = blockIdx.y * BM, u = blockIdx.z;
    const __half* Ap = A + (size_t)m0 * K;
    const __half* Bp = (u < 2 ? X1h : X2h) + (size_t)(u & 1) * 128 * HW + n0;

    float acc[4][4][4];
    #pragma unroll
    for (int i = 0; i < 4; i++)
        #pragma unroll
        for (int j = 0; j < 4; j++)
            #pragma unroll
            for (int e = 0; e < 4; e++) acc[i][j][e] = 0.f;

    int aro[2], aco[2];
    #pragma unroll
    for (int i = 0; i < 2; i++) {
        int idx = tid + i * 256;
        aro[i] = idx >> 2; aco[i] = (idx & 3) << 3;
    }
    int brw[2], bcl[2];
    #pragma unroll
    for (int i = 0; i < 2; i++) {
        int idx = tid + i * 256;
        brw[i] = idx >> 4; bcl[i] = (idx & 15) << 3;
    }
    int sc = tid & 127, sg = tid >> 7;
    float s_sum = 0.f, s_sq = 0.f;

    int arow_l = lane & 15, acol_l = (lane >> 4) << 3;
    int brow_l = (lane & 7) + ((lane >> 3) & 1) * 8;
    uint32_t as_base = smem_u32(As);
    uint32_t bs_base = smem_u32(Bs);

    #define PFQ(sidx, k0)                                                          \
        {   _Pragma("unroll")                                                      \
            for (int i = 0; i < 2; i++)                                            \
                cp16(smem_u32(&As[(sidx) * ASZ + aro[i] * ASPH + aco[i]]),         \
                     Ap + (size_t)aro[i] * K + (k0) + aco[i]);                     \
            _Pragma("unroll")                                                      \
            for (int i = 0; i < 2; i++)                                            \
                cp16(smem_u32(&Bs[(sidx) * BSZ + brw[i] * BSPH + bcl[i]]),         \
                     Bp + (size_t)((k0) + brw[i]) * HW + bcl[i]);                  \
        }

    PFQ(0, 0); cp_commit();
    PFQ(1, BK); cp_commit();

    for (int kt = 0; kt < KT; kt++) {
        cp_wait1();
        __syncthreads();
        int st = kt % ST;
        const __half* bs = Bs + st * BSZ;
        #pragma unroll
        for (int rr = 0; rr < 16; rr++) {
            float v = __half2float(bs[(sg * 16 + rr) * BSPH + sc]);
            s_sum += v; s_sq += v * v;
        }
        uint32_t abase = as_base + (uint32_t)(st * ASZ + (wm * 64 + arow_l) * ASPH + acol_l) * 2;
        uint32_t bbase = bs_base + (uint32_t)(st * BSZ + brow_l * BSPH + wn * 32) * 2;
        #pragma unroll
        for (int s16 = 0; s16 < 2; s16++) {
            uint32_t a[4][4], b[4][2];
            #pragma unroll
            for (int mt = 0; mt < 4; mt++)
                ldsm4(a[mt], abase + (uint32_t)(mt * 16 * ASPH + s16 * 16) * 2);
            #pragma unroll
            for (int nt = 0; nt < 4; nt++)
                ldsm2t(b[nt], bbase + (uint32_t)(s16 * 16 * BSPH + nt * 8) * 2);
            #pragma unroll
            for (int mt = 0; mt < 4; mt++)
                #pragma unroll
                for (int nt = 0; nt < 4; nt++)
                    mma_f16(acc[mt][nt], a[mt], b[nt]);
        }
        if (kt + 2 < KT) PFQ((kt + 2) % ST, (kt + 2) * BK);
        cp_commit();
    }
    #undef PFQ

    sst[0][sg][sc] = s_sum;
    sst[1][sg][sc] = s_sq;
    __syncthreads();
    if (tid < BN) {
        float S = sst[0][0][tid] + sst[0][1][tid];
        float SS = sst[1][0][tid] + sst[1][1][tid];
        float m = S * (1.f / 128.f);
        float var = SS * (1.f / 128.f) - m * m;
        sst[0][0][tid] = m;
        sst[1][0][tid] = rsqrtf(var + eps);
    }
    __syncthreads();

    #pragma unroll
    for (int mt = 0; mt < 4; mt++) {
        #pragma unroll
        for (int half = 0; half < 2; half++) {
            int row = m0 + wm * 64 + mt * 16 + (lane >> 2) + half * 8;
            float sgr = Sg[row], cstr = Cst[row];
            #pragma unroll
            for (int nt = 0; nt < 4; nt++) {
                #pragma unroll
                for (int e = 0; e < 2; e++) {
                    int pl = wn * 32 + nt * 8 + (lane & 3) * 2 + e;
                    int p = n0 + pl;
                    float v = acc[mt][nt][half * 2 + e];
                    float mv = sst[0][0][pl], rv = sst[1][0][pl];
                    v = rv * v + (cstr - mv * rv * sgr);
                    if (row < 128)
                        Qo[((size_t)u * 128 + row) * HW + p] = __float2half(v * QSCALE);
                    else if (row < 256)
                        Ko[((size_t)(u ^ 2) * 128 + (row - 128)) * HW + p] = __float2half(v);
                    else
                        Vo[((size_t)(u ^ 2) * 128 + (row - 256)) * HW + p] = __float2half(v);
                }
            }
        }
    }
}

// ---------------- tf32 GEMM (MODE 2: w_in, LN-fused, fp16 packed out) -------
template<int K, int BM, int BN>
__global__ void __launch_bounds__(256)
gemm_win_tc(const float* __restrict__ A, const float* __restrict__ B,
            __half* __restrict__ Yh,
            const float* __restrict__ Sg, const float* __restrict__ Cst, float eps) {
    constexpr int BK = 16, ST = 3;
    constexpr int KT = K / BK;
    constexpr int ASP = 20;
    constexpr int BSP = BN + 8;
    constexpr int ASZ = BM * ASP;
    constexpr int BSZ = BK * BSP;
    constexpr int NA = BM / 64;
    constexpr int NB = BN / 64;
    constexpr int WN = (BM == 128) ? 4 : 2;
    constexpr int SH = (BN == 64) ? 4 : 2;
    constexpr int RT = 16 / SH;
    extern __shared__ float smf[];
    float* As = smf;
    float* Bs = smf + ST * ASZ;
    __shared__ float sst[2][SH][BN];

    int tid = threadIdx.x, lane = tid & 31, wid = tid >> 5;
    int wm = wid / WN, wn = wid % WN;
    int n0 = blockIdx.x * BN, m0 = blockIdx.y * BM, u = blockIdx.z;
    const float* Ap = A + (size_t)m0 * K;
    const float* Bp = B + (size_t)u * K * HW + n0;

    float acc[4][4][4];
    #pragma unroll
    for (int i = 0; i < 4; i++)
        #pragma unroll
        for (int j = 0; j < 4; j++)
            #pragma unroll
            for (int e = 0; e < 4; e++) acc[i][j][e] = 0.f;

    int ar[NA], ac[NA], br[NB], bc[NB];
    #pragma unroll
    for (int i = 0; i < NA; i++) {
        int idx = tid + i * 256;
        ar[i] = idx >> 2; ac[i] = (idx & 3) << 2;
    }
    #pragma unroll
    for (int i = 0; i < NB; i++) {
        int idx = tid + i * 256;
        br[i] = idx / (BN / 4); bc[i] = (idx % (BN / 4)) << 2;
    }
    int sc = tid % BN, sg = tid / BN;
    float s_sum = 0.f, s_sq = 0.f;
    int lm = lane >> 3;
    int loff = (((lane & 7) + (lm & 1) * 8)) * ASP + (lm >> 1) * 4;
    uint32_t as_base = smem_u32(As);

    #define PREFETCH(sidx, k0)                                                     \
        {   _Pragma("unroll")                                                      \
            for (int i = 0; i < NA; i++)                                           \
                cp16(smem_u32(&As[(sidx) * ASZ + ar[i] * ASP + ac[i]]),            \
                     Ap + (size_t)ar[i] * K + (k0) + ac[i]);                       \
            _Pragma("unroll")                                                      \
            for (int i = 0; i < NB; i++)                                           \
                cp16(smem_u32(&Bs[(sidx) * BSZ + br[i] * BSP + bc[i]]),            \
                     Bp + (size_t)((k0) + br[i]) * HW + bc[i]);                    \
        }

    PREFETCH(0, 0); cp_commit();
    if (KT > 1) PREFETCH(1, BK);
    cp_commit();

    for (int kt = 0; kt < KT; kt++) {
        cp_wait1();
        __syncthreads();
        int st = kt % ST;
        const float* bs = Bs + st * BSZ;
        #pragma unroll
        for (int rr = 0; rr < RT; rr++) {
            float v = bs[(sg * RT + rr) * BSP + sc];
            s_sum += v; s_sq += v * v;
        }
        uint32_t abase = as_base + (uint32_t)(st * ASZ + wm * 64 * ASP + loff) * 4;
        #pragma unroll
        for (int s8 = 0; s8 < 2; s8++) {
            uint32_t a[4][4], b[4][2];
            #pragma unroll
            for (int mt = 0; mt < 4; mt++)
                ldsm4(a[mt], abase + (uint32_t)(mt * 16 * ASP + s8 * 8) * 4);
            #pragma unroll
            for (int nt = 0; nt < 4; nt++) {
                const float* bp = bs + (s8 * 8 + (lane & 3)) * BSP
                                     + wn * 32 + nt * 8 + (lane >> 2);
                b[nt][0] = __float_as_uint(bp[0]);
                b[nt][1] = __float_as_uint(bp[4 * BSP]);
            }
            #pragma unroll
            for (int mt = 0; mt < 4; mt++)
                #pragma unroll
                for (int nt = 0; nt < 4; nt++)
                    mma_tf32(acc[mt][nt], a[mt], b[nt]);
        }
        if (kt + 2 < KT) PREFETCH((kt + 2) % ST, (kt + 2) * BK);
        cp_commit();
    }
    #undef PREFETCH

    sst[0][sg][sc] = s_sum;
    sst[1][sg][sc] = s_sq;
    __syncthreads();
    if (tid < BN) {
        float S = 0.f, SS = 0.f;
        #pragma unroll
        for (int g = 0; g < SH; g++) { S += sst[0][g][tid]; SS += sst[1][g][tid]; }
        float m = S * (1.f / 128.f);
        float var = SS * (1.f / 128.f) - m * m;
        sst[0][0][tid] = m;
        sst[1][0][tid] = rsqrtf(var + eps);
    }
    __syncthreads();

    #pragma unroll
    for (int mt = 0; mt < 4; mt++) {
        #pragma unroll
        for (int half = 0; half < 2; half++) {
            int row = m0 + wm * 64 + mt * 16 + (lane >> 2) + half * 8;
            float sgr = Sg[row], cstr = Cst[row];
            #pragma unroll
            for (int nt = 0; nt < 4; nt++) {
                int pl0 = wn * 32 + nt * 8 + (lane & 3) * 2;
                float v0 = acc[mt][nt][half * 2];
                float v1 = acc[mt][nt][half * 2 + 1];
                float mv0 = sst[0][0][pl0],     rv0 = sst[1][0][pl0];
                float mv1 = sst[0][0][pl0 + 1], rv1 = sst[1][0][pl0 + 1];
                v0 = rv0 * v0 + (cstr - mv0 * rv0 * sgr);
                v1 = rv1 * v1 + (cstr - mv1 * rv1 * sgr);
                v0 = v0 / (1.f + __expf(-v0));
                v1 = v1 / (1.f + __expf(-v1));
                size_t idx = ((size_t)u * 256 + row) * HW + n0 + pl0;
                *(uint32_t*)&Yh[idx] = packh2(v0, v1);
            }
        }
    }
}

// ---------------- fp16 GEMM for the pointwise conv (fp16 in/out) ------------
__global__ void __launch_bounds__(256)
gemm_pw_f16(const __half* __restrict__ A, const __half* __restrict__ B,
            const __half* __restrict__ Yh, __half* __restrict__ Y2h,
            const float* __restrict__ bias) {
    constexpr int K = 768, BN = 64, BK = 32, ST = 3;
    constexpr int KT = K / BK;
    constexpr int ASPH = 40;
    constexpr int BSPH = BN + 8;
    constexpr int ASZ = 256 * ASPH;
    constexpr int BSZ = BK * BSPH;
    extern __shared__ __half smh[];
    __half* As = smh;
    __half* Bs = smh + ST * ASZ;

    int tid = threadIdx.x, lane = tid & 31, wid = tid >> 5;
    int wm = wid >> 1, wn = wid & 1;
    int n0 = blockIdx.x * BN, u = blockIdx.z;
    const __half* Bp = B + (size_t)u * K * HW + n0;

    float acc[4][4][4];
    #pragma unroll
    for (int i = 0; i < 4; i++)
        #pragma unroll
        for (int j = 0; j < 4; j++)
            #pragma unroll
            for (int e = 0; e < 4; e++) acc[i][j][e] = 0.f;

    int aro[4], aco[4];
    #pragma unroll
    for (int i = 0; i < 4; i++) {
        int idx = tid + i * 256;
        aro[i] = idx >> 2; aco[i] = (idx & 3) << 3;
    }
    int brw = tid >> 3, bcl = (tid & 7) << 3;

    int arow_l = lane & 15, acol_l = (lane >> 4) << 3;
    int brow_l = (lane & 7) + ((lane >> 3) & 1) * 8;
    uint32_t as_base = smem_u32(As);
    uint32_t bs_base = smem_u32(Bs);

    #define PF16(sidx, k0)                                                         \
        {   _Pragma("unroll")                                                      \
            for (int i = 0; i < 4; i++)                                            \
                cp16(smem_u32(&As[(sidx) * ASZ + aro[i] * ASPH + aco[i]]),         \
                     A + (size_t)aro[i] * K + (k0) + aco[i]);                      \
            cp16(smem_u32(&Bs[(sidx) * BSZ + brw * BSPH + bcl]),                   \
                 Bp + (size_t)((k0) + brw) * HW + bcl);                            \
        }

    PF16(0, 0); cp_commit();
    PF16(1, BK); cp_commit();

    for (int kt = 0; kt < KT; kt++) {
        cp_wait1();
        __syncthreads();
        int st = kt % ST;
        uint32_t abase = as_base + (uint32_t)(st * ASZ + (wm * 64 + arow_l) * ASPH + acol_l) * 2;
        uint32_t bbase = bs_base + (uint32_t)(st * BSZ + brow_l * BSPH + wn * 32) * 2;
        #pragma unroll
        for (int s16 = 0; s16 < 2; s16++) {
            uint32_t a[4][4], b[4][2];
            #pragma unroll
            for (int mt = 0; mt < 4; mt++)
                ldsm4(a[mt], abase + (uint32_t)(mt * 16 * ASPH + s16 * 16) * 2);
            #pragma unroll
            for (int nt = 0; nt < 4; nt++)
                ldsm2t(b[nt], bbase + (uint32_t)(s16 * 16 * BSPH + nt * 8) * 2);
            #pragma unroll
            for (int mt = 0; mt < 4; mt++)
                #pragma unroll
                for (int nt = 0; nt < 4; nt++)
                    mma_f16(acc[mt][nt], a[mt], b[nt]);
        }
        if (kt + 2 < KT) PF16((kt + 2) % ST, (kt + 2) * BK);
        cp_commit();
    }
    #undef PF16

    #pragma unroll
    for (int mt = 0; mt < 4; mt++) {
        #pragma unroll
        for (int half = 0; half < 2; half++) {
            int row = wm * 64 + mt * 16 + (lane >> 2) + half * 8;
            float br2 = bias[row];
            #pragma unroll
            for (int nt = 0; nt < 4; nt++) {
                int p0 = n0 + wn * 32 + nt * 8 + (lane & 3) * 2;
                size_t idx = ((size_t)u * 256 + row) * HW + p0;
                float v0 = acc[mt][nt][half * 2]     + br2;
                float v1 = acc[mt][nt][half * 2 + 1] + br2;
                v0 = v0 / (1.f + __expf(-v0));
                v1 = v1 / (1.f + __expf(-v1));
                __half2 yp = *(const __half2*)&Yh[idx];
                v0 += __low2float(yp);
                v1 += __high2float(yp);
                *(uint32_t*)&Y2h[idx] = packh2(v0, v1);
            }
        }
    }
}

// ---------------- fp16 GEMM: generic WxB, fp32 accumulate-out ---------------
// MODE 1: wo (K=128), dout = v + bias + residual(feats)
// MODE 4: w_out (K=256, B = Y2h), dout += v + bias
template<int K, int MODE>
__global__ void __launch_bounds__(256)
gemm_f16o(const __half* __restrict__ A, const __half* __restrict__ B,
          float* __restrict__ O0,
          const float* __restrict__ X1, const float* __restrict__ X2,
          const float* __restrict__ bias) {
    constexpr int BM = 128, BN = 128, BK = 32, ST = 3;
    constexpr int KT = K / BK;
    constexpr int ASPH = 40;
    constexpr int BSPH = BN + 8;
    constexpr int ASZ = BM * ASPH;
    constexpr int BSZ = BK * BSPH;
    extern __shared__ __half smh[];
    __half* As = smh;
    __half* Bs = smh + ST * ASZ;

    int tid = threadIdx.x, lane = tid & 31, wid = tid >> 5;
    int wm = wid >> 2, wn = wid & 3;
    int n0 = blockIdx.x * BN, u = blockIdx.z;
    const __half* Bp = B + (size_t)u * K * HW + n0;

    float acc[4][4][4];
    #pragma unroll
    for (int i = 0; i < 4; i++)
        #pragma unroll
        for (int j = 0; j < 4; j++)
            #pragma unroll
            for (int e = 0; e < 4; e++) acc[i][j][e] = 0.f;

    int aro[2], aco[2];
    #pragma unroll
    for (int i = 0; i < 2; i++) {
        int idx = tid + i * 256;
        aro[i] = idx >> 2; aco[i] = (idx & 3) << 3;
    }
    int brw[2], bcl[2];
    #pragma unroll
    for (int i = 0; i < 2; i++) {
        int idx = tid + i * 256;
        brw[i] = idx >> 4; bcl[i] = (idx & 15) << 3;
    }

    int arow_l = lane & 15, acol_l = (lane >> 4) << 3;
    int brow_l = (lane & 7) + ((lane >> 3) & 1) * 8;
    uint32_t as_base = smem_u32(As);
    uint32_t bs_base = smem_u32(Bs);

    #define PFW(sidx, k0)                                                          \
        {   _Pragma("unroll")                                                      \
            for (int i = 0; i < 2; i++)                                            \
                cp16(smem_u32(&As[(sidx) * ASZ + aro[i] * ASPH + aco[i]]),         \
                     A + (size_t)aro[i] * K + (k0) + aco[i]);                      \
            _Pragma("unroll")                                                      \
            for (int i = 0; i < 2; i++)                                            \
                cp16(smem_u32(&Bs[(sidx) * BSZ + brw[i] * BSPH + bcl[i]]),         \
                     Bp + (size_t)((k0) + brw[i]) * HW + bcl[i]);                  \
        }

    PFW(0, 0); cp_commit();
    if (KT > 1) PFW(1, BK);
    cp_commit();

    for (int kt = 0; kt < KT; kt++) {
        cp_wait1();
        __syncthreads();
        int st = kt % ST;
        uint32_t abase = as_base + (uint32_t)(st * ASZ + (wm * 64 + arow_l) * ASPH + acol_l) * 2;
        uint32_t bbase = bs_base + (uint32_t)(st * BSZ + brow_l * BSPH + wn * 32) * 2;
        #pragma unroll
        for (int s16 = 0; s16 < 2; s16++) {
            uint32_t a[4][4], b[4][2];
            #pragma unroll
            for (int mt = 0; mt < 4; mt++)
                ldsm4(a[mt], abase + (uint32_t)(mt * 16 * ASPH + s16 * 16) * 2);
            #pragma unroll
            for (int nt = 0; nt < 4; nt++)
                ldsm2t(b[nt], bbase + (uint32_t)(s16 * 16 * BSPH + nt * 8) * 2);
            #pragma unroll
            for (int mt = 0; mt < 4; mt++)
                #pragma unroll
                for (int nt = 0; nt < 4; nt++)
                    mma_f16(acc[mt][nt], a[mt], b[nt]);
        }
        if (kt + 2 < KT) PFW((kt + 2) % ST, (kt + 2) * BK);
        cp_commit();
    }
    #undef PFW

    #pragma unroll
    for (int mt = 0; mt < 4; mt++) {
        #pragma unroll
        for (int half = 0; half < 2; half++) {
            int row = wm * 64 + mt * 16 + (lane >> 2) + half * 8;
            float br2 = bias[row];
            #pragma unroll
            for (int nt = 0; nt < 4; nt++) {
                #pragma unroll
                for (int e = 0; e < 2; e++) {
                    int p = n0 + wn * 32 + nt * 8 + (lane & 3) * 2 + e;
                    float v = acc[mt][nt][half * 2 + e] + br2;
                    size_t idx = ((size_t)u * 128 + row) * HW + p;
                    if (MODE == 1) {
                        float res = ((u < 2 ? X1 : X2))[((size_t)(u & 1) * 128 + row) * HW + p];
                        O0[idx] = v + res;
                    } else {
                        O0[idx] += v;
                    }
                }
            }
        }
    }
}

// ---------------- fp16 flash attention (register-direct P reuse) -------------
#define AT2_QS 0
#define AT2_VS 10240
#define AT2_KT 20480
#define AT2_HALVES 28928
#define ATTN2_SMEM (AT2_HALVES * 2 + 256 * 4 + 32 * 4)

__global__ void __launch_bounds__(256, 2)
attn_f16(const __half* __restrict__ Q, const __half* __restrict__ K,
         const __half* __restrict__ V, __half* __restrict__ O) {
    int blk = blockIdx.x;                  // b*256 + n*64 + h
    int h = blk & 63, n = (blk >> 6) & 3, b = blk >> 8;
    size_t base = ((size_t)(b * 128 + n * 32) * 64 + h) * 256;
    extern __shared__ __half smh2[];
    __half* Qs = smh2 + AT2_QS;
    __half* Vs = smh2 + AT2_VS;
    __half* Kt = smh2 + AT2_KT;
    float* V2 = (float*)(smh2 + AT2_HALVES);
    float* Vsum = V2 + 256;
    int tid = threadIdx.x, lane = tid & 31, w = tid >> 5;

    #pragma unroll 4
    for (int dd = 0; dd < 32; dd++) {
        Qs[tid * 40 + dd] = Q[base + (size_t)dd * HW + tid];
        Vs[tid * 40 + dd] = V[base + (size_t)dd * HW + tid];
    }
    #pragma unroll
    for (int i = 0; i < 4; i++) {
        int idx = tid + i * 256;
        int row = idx >> 5, seg = idx & 31;
        *(uint4*)&Kt[row * 264 + seg * 8] =
            *(const uint4*)&K[base + (size_t)row * HW + seg * 8];
    }
    __syncthreads();
    {
        float s = 0.f;
        #pragma unroll 8
        for (int jj = 0; jj < 32; jj++) s += __half2float(Vs[(w * 32 + jj) * 40 + lane]);
        V2[w * 32 + lane] = s;
    }

    int i0 = w * 32;
    uint32_t qa[2][2][4];
    #pragma unroll
    for (int mt = 0; mt < 2; mt++)
        #pragma unroll
        for (int dk = 0; dk < 2; dk++)
            ldsm4(qa[mt][dk],
                  smem_u32(&Qs[(i0 + mt * 16 + (lane & 15)) * 40 + dk * 16 + ((lane >> 4) << 3)]));
    int brow = (lane & 7) + ((lane >> 3) & 1) * 8;

    float l0[2] = {0.f, 0.f}, l1[2] = {0.f, 0.f};
    float o[2][4][4];
    #pragma unroll
    for (int mt = 0; mt < 2; mt++)
        #pragma unroll
        for (int dt = 0; dt < 4; dt++)
            #pragma unroll
            for (int e = 0; e < 4; e++) o[mt][dt][e] = 0.f;

    for (int j0 = 0; j0 < 256; j0 += 16) {
        float s[2][2][4];
        #pragma unroll
        for (int mt = 0; mt < 2; mt++)
            #pragma unroll
            for (int jh = 0; jh < 2; jh++)
                #pragma unroll
                for (int e = 0; e < 4; e++) s[mt][jh][e] = 0.f;
        uint32_t bS[2][2][2];
        #pragma unroll
        for (int dk = 0; dk < 2; dk++)
            #pragma unroll
            for (int jh = 0; jh < 2; jh++)
                ldsm2t(bS[dk][jh], smem_u32(&Kt[(dk * 16 + brow) * 264 + j0 + jh * 8]));
        #pragma unroll
        for (int mt = 0; mt < 2; mt++)
            #pragma unroll
            for (int jh = 0; jh < 2; jh++)
                #pragma unroll
                for (int dk = 0; dk < 2; dk++)
                    mma_f16(s[mt][jh], qa[mt][dk], bS[dk][jh]);
        uint32_t pa[2][4];
        #pragma unroll
        for (int mt = 0; mt < 2; mt++) {
            float p00 = fexp2(s[mt][0][0]), p01 = fexp2(s[mt][0][1]);
            float p02 = fexp2(s[mt][0][2]), p03 = fexp2(s[mt][0][3]);
            float p10 = fexp2(s[mt][1][0]), p11 = fexp2(s[mt][1][1]);
            float p12 = fexp2(s[mt][1][2]), p13 = fexp2(s[mt][1][3]);
            l0[mt] += p00 + p01 + p10 + p11;
            l1[mt] += p02 + p03 + p12 + p13;
            pa[mt][0] = packh2(p00, p01);
            pa[mt][1] = packh2(p02, p03);
            pa[mt][2] = packh2(p10, p11);
            pa[mt][3] = packh2(p12, p13);
        }
        uint32_t bV[4][2];
        #pragma unroll
        for (int dt = 0; dt < 4; dt++)
            ldsm2t(bV[dt], smem_u32(&Vs[(j0 + brow) * 40 + dt * 8]));
        #pragma unroll
        for (int mt = 0; mt < 2; mt++)
            #pragma unroll
            for (int dt = 0; dt < 4; dt++)
                mma_f16(o[mt][dt], pa[mt], bV[dt]);
    }
    #pragma unroll
    for (int mt = 0; mt < 2; mt++) {
        l0[mt] += __shfl_xor_sync(0xffffffffu, l0[mt], 1);
        l0[mt] += __shfl_xor_sync(0xffffffffu, l0[mt], 2);
        l1[mt] += __shfl_xor_sync(0xffffffffu, l1[mt], 1);
        l1[mt] += __shfl_xor_sync(0xffffffffu, l1[mt], 2);
    }

    __syncthreads();
    float* Ow = (float*)smh2 + w * 32 * 36;
    #pragma unroll
    for (int mt = 0; mt < 2; mt++)
        #pragma unroll
        for (int hf = 0; hf < 2; hf++) {
            float inv = 1.f / (hf == 0 ? l0[mt] : l1[mt]);
            int row = mt * 16 + (lane >> 2) + hf * 8;
            #pragma unroll
            for (int dt = 0; dt < 4; dt++) {
                Ow[row * 36 + dt * 8 + (lane & 3) * 2]     = o[mt][dt][hf * 2]     * inv;
                Ow[row * 36 + dt * 8 + (lane & 3) * 2 + 1] = o[mt][dt][hf * 2 + 1] * inv;
            }
        }
    if (tid < 32) {
        float s = 0.f;
        #pragma unroll
        for (int ww = 0; ww < 8; ww++) s += V2[ww * 32 + tid];
        Vsum[tid] = s;
    }
    __syncthreads();
    const float eps = 1e-6f;
    const float norm = 1.f / (1.f + 256.f * eps);
    #pragma unroll 4
    for (int d = 0; d < 32; d++) {
        float val = (Ow[lane * 36 + d] + eps * Vsum[d]) * norm;
        O[base + (size_t)d * HW + i0 + lane] = __float2half(val);
    }
}

// ---------------- depthwise 3x3 / 5x5 / 7x7 (fp16 in) -> half F -------------
__global__ void dw_kernel(const __half* __restrict__ Y,
                          const float* __restrict__ w3, const float* __restrict__ b3,
                          const float* __restrict__ w5, const float* __restrict__ b5,
                          const float* __restrict__ w7, const float* __restrict__ b7,
                          __half* __restrict__ F) {
    __shared__ float S[14][70];
    __shared__ float wgt[84];
    int z = blockIdx.z; int ch = z & 255; int u = z >> 8;
    int w0 = blockIdx.x * 64, h0 = blockIdx.y * 8;
    int tid = threadIdx.x;
    if (tid < 9)       wgt[tid] = w3[ch * 9 + tid];
    else if (tid < 34) wgt[tid] = w5[ch * 25 + tid - 9];
    else if (tid < 83) wgt[tid] = w7[ch * 49 + tid - 34];
    const __half* Yp = Y + ((size_t)u * 256 + ch) * HW;
    for (int i = tid; i < 980; i += 256) {
        int r = i / 70, c = i % 70;
        int gh = h0 - 3 + r, gw = w0 - 3 + c;
        float v = 0.f;
        if ((unsigned)gh < 64u && (unsigned)gw < 256u) v = __half2float(Yp[gh * 256 + gw]);
        S[r][c] = v;
    }
    __syncthreads();
    int tx = tid & 63, ty = tid >> 6;
    float bb3 = b3[ch], bb5 = b5[ch], bb7 = b7[ch];
    #pragma unroll
    for (int rr = 0; rr < 2; rr++) {
        int rc = ty + rr * 4 + 3, cc = tx + 3;
        float f3 = bb3, f5 = bb5, f7 = bb7;
        #pragma unroll
        for (int dy = -3; dy <= 3; dy++)
            #pragma unroll
            for (int dx = -3; dx <= 3; dx++) {
                float v = S[rc + dy][cc + dx];
                f7 += v * wgt[34 + (dy + 3) * 7 + (dx + 3)];
                if (dy >= -2 && dy <= 2 && dx >= -2 && dx <= 2)
                    f5 += v * wgt[9 + (dy + 2) * 5 + (dx + 2)];
                if (dy >= -1 && dy <= 1 && dx >= -1 && dx <= 1)
                    f3 += v * wgt[(dy + 1) * 3 + (dx + 1)];
            }
        size_t pix = (size_t)(h0 + ty + rr * 4) * 256 + (w0 + tx);
        size_t ob = (size_t)u * 768 * HW + pix;
        F[ob + (size_t) ch        * HW] = __float2half(f3);
        F[ob + (size_t)(256 + ch) * HW] = __float2half(f5);
        F[ob + (size_t)(512 + ch) * HW] = __float2half(f7);
    }
}

// ---------------- host launcher --------------------------------------------
extern "C" void kernel_launch(void* const* d_in, const int* in_sizes, int n_in,
                              void* d_out, int out_size) {
    const float* feats1 = (const float*)d_in[0];
    const float* feats2 = (const float*)d_in[1];
    const float* an_g  = (const float*)d_in[2];
    const float* an_b  = (const float*)d_in[3];
    const float* anc_g = (const float*)d_in[4];
    const float* anc_b = (const float*)d_in[5];
    const float* wq    = (const float*)d_in[6];
    const float* bq    = (const float*)d_in[7];
    const float* wkv   = (const float*)d_in[8];
    const float* bkv   = (const float*)d_in[9];
    const float* wo    = (const float*)d_in[10];
    const float* bo    = (const float*)d_in[11];
    const float* fn_g  = (const float*)d_in[12];
    const float* fn_b  = (const float*)d_in[13];
    const float* w_in  = (const float*)d_in[14];
    const float* b_in  = (const float*)d_in[15];
    const float* w_dw3 = (const float*)d_in[16];
    const float* b_dw3 = (const float*)d_in[17];
    const float* w_dw5 = (const float*)d_in[18];
    const float* b_dw5 = (const float*)d_in[19];
    const float* w_dw7 = (const float*)d_in[20];
    const float* b_dw7 = (const float*)d_in[21];
    const float* w_pw  = (const float*)d_in[22];
    const float* b_pw  = (const float*)d_in[23];
    const float* w_out = (const float*)d_in[24];
    const float* b_out = (const float*)d_in[25];
    float* dout = (float*)d_out;

    float *WA, *SgA, *CA, *WIN, *SgI, *CI;
    __half *Qh, *Kh, *Vh, *Oh, *Yh, *Y2h, *Fh, *WPWh, *WOh, *WOUTh, *WAh, *X1h, *X2h;
    cudaGetSymbolAddress((void**)&Qh, g_Qh);
    cudaGetSymbolAddress((void**)&Kh, g_Kh);
    cudaGetSymbolAddress((void**)&Vh, g_Vh);
    cudaGetSymbolAddress((void**)&Oh, g_Oh);
    cudaGetSymbolAddress((void**)&Yh, g_Yh);
    cudaGetSymbolAddress((void**)&Y2h, g_Y2h);
    cudaGetSymbolAddress((void**)&Fh, g_Fh);
    cudaGetSymbolAddress((void**)&WPWh, g_WPWh);
    cudaGetSymbolAddress((void**)&WOh, g_WOh);
    cudaGetSymbolAddress((void**)&WOUTh, g_WOUTh);
    cudaGetSymbolAddress((void**)&WAh, g_WAh);
    cudaGetSymbolAddress((void**)&X1h, g_X1h);
    cudaGetSymbolAddress((void**)&X2h, g_X2h);
    cudaGetSymbolAddress((void**)&WA, g_WA);
    cudaGetSymbolAddress((void**)&SgA, g_SgA);
    cudaGetSymbolAddress((void**)&CA, g_CA);
    cudaGetSymbolAddress((void**)&WIN, g_WIN);
    cudaGetSymbolAddress((void**)&SgI, g_SgI);
    cudaGetSymbolAddress((void**)&CI, g_CI);

    const int smB  = 3 * (256 * 20 + 16 * 72)  * 4;   // tf32 BM=256/BN=64
    const int smH  = 3 * (256 * 40 + 32 * 72)  * 2;   // f16 pw
    const int smW  = 3 * (128 * 40 + 32 * 136) * 2;   // f16 BM=128/BN=128
    cudaFuncSetAttribute((const void*)gemm_qkv_f16, cudaFuncAttributeMaxDynamicSharedMemorySize, smW);
    cudaFuncSetAttribute((const void*)gemm_win_tc<128, 256, 64>, cudaFuncAttributeMaxDynamicSharedMemorySize, smB);
    cudaFuncSetAttribute((const void*)gemm_pw_f16, cudaFuncAttributeMaxDynamicSharedMemorySize, smH);
    cudaFuncSetAttribute((const void*)gemm_f16o<128, 1>, cudaFuncAttributeMaxDynamicSharedMemorySize, smW);
    cudaFuncSetAttribute((const void*)gemm_f16o<256, 4>, cudaFuncAttributeMaxDynamicSharedMemorySize, smW);
    cudaFuncSetAttribute((const void*)attn_f16, cudaFuncAttributeMaxDynamicSharedMemorySize, ATTN2_SMEM);

    // 1. weight prep + fp16 conversions (weights + feats)
    prep_kernel<<<640, 128>>>(wq, bq, wkv, bkv, an_g, an_b, anc_g, anc_b,
                              w_in, b_in, fn_g, fn_b);
    convh_kernel<<<768, 256>>>(w_pw, WPWh, 256 * 768);
    convh_kernel<<<64, 256>>>(wo, WOh, 128 * 128);
    convh_kernel<<<128, 256>>>(w_out, WOUTh, 128 * 256);
    convfeats_kernel<<<4096, 256>>>((const float4*)feats1, (const float4*)feats2,
                                    (uint2*)X1h, (uint2*)X2h, 2 * 128 * HW / 4);
    // 2. fp16 fused LN + q/kv projection -> fp16 Q (pre-scaled), K, V
    gemm_qkv_f16<<<dim3(128, 3, 4), 256, smW>>>(WAh, Qh, Kh, Vh, SgA, CA, X1h, X2h, 1e-6f);
    // 3. fp16 flash attention -> fp16 O
    attn_f16<<<1024, 256, ATTN2_SMEM>>>(Qh, Kh, Vh, Oh);
    // 4. fp16 wo projection + residual(feats fp32) -> d_out
    gemm_f16o<128, 1><<<dim3(128, 1, 4), 256, smW>>>(WOh, Oh, dout, feats1, feats2, bo);
    // 5. fused LN + w_in + SiLU -> Yh (fp16, packed stores)
    gemm_win_tc<128, 256, 64><<<dim3(256, 1, 4), 256, smB>>>(WIN, dout, Yh, SgI, CI, 1e-5f);
    // 6. depthwise 3/5/7 (fp16 in) -> Fh (fp16)
    dw_kernel<<<dim3(4, 8, 1024), 256>>>(Yh, w_dw3, b_dw3, w_dw5, b_dw5, w_dw7, b_dw7, Fh);
    // 7. fp16 pointwise GEMM + SiLU + residual(Yh) -> Y2h (fp16, no RMW)
    gemm_pw_f16<<<dim3(256, 1, 4), 256, smH>>>(WPWh, Fh, Yh, Y2h, b_pw);
    // 8. fp16 w_out GEMM (K=256, reads Y2h), d_out +=
    gemm_f16o<256, 4><<<dim3(128, 1, 4), 256, smW>>>(WOUTh, Y2h, dout, nullptr, nullptr, b_out);
}

// round 17
// speedup vs baseline: 1.7537x; 1.3102x over previous
#include <cuda_runtime.h>
#include <cuda_fp16.h>
#include <math.h>
#include <stdint.h>

#define HW 16384          // 64*256 pixels per (batch, channel) plane

// ---------------- scratch (static device globals; no allocation allowed) ----
__device__ __half g_Qh[4*128*HW];
__device__ __half g_Kh[4*128*HW];
__device__ __half g_Vh[4*128*HW];
__device__ __half g_Oh[4*128*HW];
__device__ __half g_X1h[2*128*HW];
__device__ __half g_X2h[2*128*HW];
__device__ __half g_Yh[4*256*HW];
__device__ __half g_Y2h[4*256*HW];
__device__ __half g_Fh[(size_t)4*768*HW];
__device__ __half g_WPWh[256*768];
__device__ __half g_WOh[128*128];
__device__ __half g_WOUTh[128*256];
__device__ __half g_WAh[384*128];
__device__ float g_WA [384*128], g_SgA[384], g_CA[384];
__device__ float g_WIN[256*128], g_SgI[256], g_CI[256];

#define QSCALE (0.17677669529663687f * 1.4426950408889634f)

// ---------------- small helpers --------------------------------------------
__device__ __forceinline__ uint32_t smem_u32(const void* p) {
    return (uint32_t)__cvta_generic_to_shared(p);
}
__device__ __forceinline__ void cp16(uint32_t dst, const void* src) {
    asm volatile("cp.async.cg.shared.global [%0], [%1], 16;\n" :: "r"(dst), "l"(src));
}
__device__ __forceinline__ void cp_commit() { asm volatile("cp.async.commit_group;\n"); }
__device__ __forceinline__ void cp_wait1()  { asm volatile("cp.async.wait_group 1;\n"); }

__device__ __forceinline__ void mma_tf32(float* c, const uint32_t* a, const uint32_t* b) {
    asm volatile("mma.sync.aligned.m16n8k8.row.col.f32.tf32.tf32.f32 "
        "{%0,%1,%2,%3}, {%4,%5,%6,%7}, {%8,%9}, {%0,%1,%2,%3};"
        : "+f"(c[0]), "+f"(c[1]), "+f"(c[2]), "+f"(c[3])
        : "r"(a[0]), "r"(a[1]), "r"(a[2]), "r"(a[3]), "r"(b[0]), "r"(b[1]));
}
__device__ __forceinline__ void mma_f16(float* c, const uint32_t* a, const uint32_t* b) {
    asm volatile("mma.sync.aligned.m16n8k16.row.col.f32.f16.f16.f32 "
        "{%0,%1,%2,%3}, {%4,%5,%6,%7}, {%8,%9}, {%0,%1,%2,%3};"
        : "+f"(c[0]), "+f"(c[1]), "+f"(c[2]), "+f"(c[3])
        : "r"(a[0]), "r"(a[1]), "r"(a[2]), "r"(a[3]), "r"(b[0]), "r"(b[1]));
}
__device__ __forceinline__ void ldsm4(uint32_t* r, uint32_t addr) {
    asm volatile("ldmatrix.sync.aligned.m8n8.x4.shared.b16 {%0,%1,%2,%3}, [%4];"
        : "=r"(r[0]), "=r"(r[1]), "=r"(r[2]), "=r"(r[3]) : "r"(addr));
}
__device__ __forceinline__ void ldsm2t(uint32_t* r, uint32_t addr) {
    asm volatile("ldmatrix.sync.aligned.m8n8.x2.trans.shared.b16 {%0,%1}, [%2];"
        : "=r"(r[0]), "=r"(r[1]) : "r"(addr));
}
__device__ __forceinline__ float fexp2(float x) {
    float r; asm("ex2.approx.ftz.f32 %0, %1;" : "=f"(r) : "f"(x)); return r;
}
__device__ __forceinline__ uint32_t packh2(float a, float b) {
    __half2 h = __floats2half2_rn(a, b);
    return *(uint32_t*)&h;
}

// ---------------- fold LN gamma/beta into GEMM weights ---------------------
__global__ void prep_kernel(const float* __restrict__ wq,  const float* __restrict__ bq,
                            const float* __restrict__ wkv, const float* __restrict__ bkv,
                            const float* __restrict__ an_g, const float* __restrict__ an_b,
                            const float* __restrict__ anc_g, const float* __restrict__ anc_b,
                            const float* __restrict__ w_in, const float* __restrict__ b_in,
                            const float* __restrict__ fn_g, const float* __restrict__ fn_b) {
    int r = blockIdx.x, t = threadIdx.x;   // 640 blocks x 128 threads
    __shared__ float red[2][4];
    float wl, gg, bb, extra;
    float *Wdst, *Sgd, *Cd;
    if (r < 128)      { wl = wq [r*128 + t];        gg = an_g[t];  bb = an_b[t];  extra = bq [r];
                        Wdst = g_WA  + r*128;        Sgd = g_SgA + r;  Cd = g_CA + r; }
    else if (r < 384) { int rr = r - 128;
                        wl = wkv[rr*128 + t];       gg = anc_g[t]; bb = anc_b[t]; extra = bkv[rr];
                        Wdst = g_WA  + r*128;        Sgd = g_SgA + r;  Cd = g_CA + r; }
    else              { int rr = r - 384;
                        wl = w_in[rr*128 + t];      gg = fn_g[t];  bb = fn_b[t];  extra = b_in[rr];
                        Wdst = g_WIN + rr*128;       Sgd = g_SgI + rr; Cd = g_CI + rr; }
    float wg = wl * gg;
    Wdst[t] = wg;
    if (r < 384) g_WAh[r*128 + t] = __float2half(wg);
    float s1 = wg, s2 = wl * bb;
    #pragma unroll
    for (int off = 16; off; off >>= 1) {
        s1 += __shfl_down_sync(0xffffffffu, s1, off);
        s2 += __shfl_down_sync(0xffffffffu, s2, off);
    }
    if ((t & 31) == 0) { red[0][t >> 5] = s1; red[1][t >> 5] = s2; }
    __syncthreads();
    if (t == 0) {
        float a = red[0][0] + red[0][1] + red[0][2] + red[0][3];
        float b = red[1][0] + red[1][1] + red[1][2] + red[1][3];
        *Sgd = a; *Cd = b + extra;
    }
}

// ---------------- convert fp32 weights to fp16 ------------------------------
__global__ void convh_kernel(const float* __restrict__ W, __half* __restrict__ Wh, int n) {
    int i = blockIdx.x * 256 + threadIdx.x;
    if (i < n) Wh[i] = __float2half(W[i]);
}

// ---------------- convert feats to fp16 (vectorized) ------------------------
__global__ void convfeats_kernel(const float4* __restrict__ s1, const float4* __restrict__ s2,
                                 uint2* __restrict__ d1, uint2* __restrict__ d2, int n4) {
    int i = blockIdx.x * 256 + threadIdx.x;
    if (i < n4) {
        float4 a = s1[i];
        uint2 o;
        o.x = packh2(a.x, a.y); o.y = packh2(a.z, a.w);
        d1[i] = o;
        float4 b = s2[i];
        o.x = packh2(b.x, b.y); o.y = packh2(b.z, b.w);
        d2[i] = o;
    }
}

// ---------------- fp16 q/kv GEMM, LN-fused with in-kernel stats -------------
__global__ void __launch_bounds__(256)
gemm_qkv_f16(const __half* __restrict__ A,
             __half* __restrict__ Qo, __half* __restrict__ Ko, __half* __restrict__ Vo,
             const float* __restrict__ Sg, const float* __restrict__ Cst,
             const __half* __restrict__ X1h, const __half* __restrict__ X2h, float eps) {
    constexpr int K = 128, BM = 128, BN = 128, BK = 32, ST = 3;
    constexpr int KT = K / BK;
    constexpr int ASPH = 40;
    constexpr int BSPH = BN + 8;
    constexpr int ASZ = BM * ASPH;
    constexpr int BSZ = BK * BSPH;
    extern __shared__ __half smh[];
    __half* As = smh;
    __half* Bs = smh + ST * ASZ;
    __shared__ float sst[2][2][BN];

    int tid = threadIdx.x, lane = tid & 31, wid = tid >> 5;
    int wm = wid >> 2, wn = wid & 3;
    int n0 = blockIdx.x * BN, m0 = blockIdx.y * BM, u = blockIdx.z;
    const __half* Ap = A + (size_t)m0 * K;
    const __half* Bp = (u < 2 ? X1h : X2h) + (size_t)(u & 1) * 128 * HW + n0;

    float acc[4][4][4];
    #pragma unroll
    for (int i = 0; i < 4; i++)
        #pragma unroll
        for (int j = 0; j < 4; j++)
            #pragma unroll
            for (int e = 0; e < 4; e++) acc[i][j][e] = 0.f;

    int aro[2], aco[2];
    #pragma unroll
    for (int i = 0; i < 2; i++) {
        int idx = tid + i * 256;
        aro[i] = idx >> 2; aco[i] = (idx & 3) << 3;
    }
    int brw[2], bcl[2];
    #pragma unroll
    for (int i = 0; i < 2; i++) {
        int idx = tid + i * 256;
        brw[i] = idx >> 4; bcl[i] = (idx & 15) << 3;
    }
    int sc = tid & 127, sg = tid >> 7;
    float s_sum = 0.f, s_sq = 0.f;

    int arow_l = lane & 15, acol_l = (lane >> 4) << 3;
    int brow_l = (lane & 7) + ((lane >> 3) & 1) * 8;
    uint32_t as_base = smem_u32(As);
    uint32_t bs_base = smem_u32(Bs);

    #define PFQ(sidx, k0)                                                          \
        {   _Pragma("unroll")                                                      \
            for (int i = 0; i < 2; i++)                                            \
                cp16(smem_u32(&As[(sidx) * ASZ + aro[i] * ASPH + aco[i]]),         \
                     Ap + (size_t)aro[i] * K + (k0) + aco[i]);                     \
            _Pragma("unroll")                                                      \
            for (int i = 0; i < 2; i++)                                            \
                cp16(smem_u32(&Bs[(sidx) * BSZ + brw[i] * BSPH + bcl[i]]),         \
                     Bp + (size_t)((k0) + brw[i]) * HW + bcl[i]);                  \
        }

    PFQ(0, 0); cp_commit();
    PFQ(1, BK); cp_commit();

    for (int kt = 0; kt < KT; kt++) {
        cp_wait1();
        __syncthreads();
        int st = kt % ST;
        const __half* bs = Bs + st * BSZ;
        #pragma unroll
        for (int rr = 0; rr < 16; rr++) {
            float v = __half2float(bs[(sg * 16 + rr) * BSPH + sc]);
            s_sum += v; s_sq += v * v;
        }
        uint32_t abase = as_base + (uint32_t)(st * ASZ + (wm * 64 + arow_l) * ASPH + acol_l) * 2;
        uint32_t bbase = bs_base + (uint32_t)(st * BSZ + brow_l * BSPH + wn * 32) * 2;
        #pragma unroll
        for (int s16 = 0; s16 < 2; s16++) {
            uint32_t a[4][4], b[4][2];
            #pragma unroll
            for (int mt = 0; mt < 4; mt++)
                ldsm4(a[mt], abase + (uint32_t)(mt * 16 * ASPH + s16 * 16) * 2);
            #pragma unroll
            for (int nt = 0; nt < 4; nt++)
                ldsm2t(b[nt], bbase + (uint32_t)(s16 * 16 * BSPH + nt * 8) * 2);
            #pragma unroll
            for (int mt = 0; mt < 4; mt++)
                #pragma unroll
                for (int nt = 0; nt < 4; nt++)
                    mma_f16(acc[mt][nt], a[mt], b[nt]);
        }
        if (kt + 2 < KT) PFQ((kt + 2) % ST, (kt + 2) * BK);
        cp_commit();
    }
    #undef PFQ

    sst[0][sg][sc] = s_sum;
    sst[1][sg][sc] = s_sq;
    __syncthreads();
    if (tid < BN) {
        float S = sst[0][0][tid] + sst[0][1][tid];
        float SS = sst[1][0][tid] + sst[1][1][tid];
        float m = S * (1.f / 128.f);
        float var = SS * (1.f / 128.f) - m * m;
        sst[0][0][tid] = m;
        sst[1][0][tid] = rsqrtf(var + eps);
    }
    __syncthreads();

    #pragma unroll
    for (int mt = 0; mt < 4; mt++) {
        #pragma unroll
        for (int half = 0; half < 2; half++) {
            int row = m0 + wm * 64 + mt * 16 + (lane >> 2) + half * 8;
            float sgr = Sg[row], cstr = Cst[row];
            #pragma unroll
            for (int nt = 0; nt < 4; nt++) {
                #pragma unroll
                for (int e = 0; e < 2; e++) {
                    int pl = wn * 32 + nt * 8 + (lane & 3) * 2 + e;
                    int p = n0 + pl;
                    float v = acc[mt][nt][half * 2 + e];
                    float mv = sst[0][0][pl], rv = sst[1][0][pl];
                    v = rv * v + (cstr - mv * rv * sgr);
                    if (row < 128)
                        Qo[((size_t)u * 128 + row) * HW + p] = __float2half(v * QSCALE);
                    else if (row < 256)
                        Ko[((size_t)(u ^ 2) * 128 + (row - 128)) * HW + p] = __float2half(v);
                    else
                        Vo[((size_t)(u ^ 2) * 128 + (row - 256)) * HW + p] = __float2half(v);
                }
            }
        }
    }
}

// ---------------- tf32 GEMM (w_in, LN-fused, fp16 packed out) ---------------
template<int K, int BM, int BN>
__global__ void __launch_bounds__(256)
gemm_win_tc(const float* __restrict__ A, const float* __restrict__ B,
            __half* __restrict__ Yh,
            const float* __restrict__ Sg, const float* __restrict__ Cst, float eps) {
    constexpr int BK = 16, ST = 3;
    constexpr int KT = K / BK;
    constexpr int ASP = 20;
    constexpr int BSP = BN + 8;
    constexpr int ASZ = BM * ASP;
    constexpr int BSZ = BK * BSP;
    constexpr int NA = BM / 64;
    constexpr int NB = BN / 64;
    constexpr int WN = (BM == 128) ? 4 : 2;
    constexpr int SH = (BN == 64) ? 4 : 2;
    constexpr int RT = 16 / SH;
    extern __shared__ float smf[];
    float* As = smf;
    float* Bs = smf + ST * ASZ;
    __shared__ float sst[2][SH][BN];

    int tid = threadIdx.x, lane = tid & 31, wid = tid >> 5;
    int wm = wid / WN, wn = wid % WN;
    int n0 = blockIdx.x * BN, m0 = blockIdx.y * BM, u = blockIdx.z;
    const float* Ap = A + (size_t)m0 * K;
    const float* Bp = B + (size_t)u * K * HW + n0;

    float acc[4][4][4];
    #pragma unroll
    for (int i = 0; i < 4; i++)
        #pragma unroll
        for (int j = 0; j < 4; j++)
            #pragma unroll
            for (int e = 0; e < 4; e++) acc[i][j][e] = 0.f;

    int ar[NA], ac[NA], br[NB], bc[NB];
    #pragma unroll
    for (int i = 0; i < NA; i++) {
        int idx = tid + i * 256;
        ar[i] = idx >> 2; ac[i] = (idx & 3) << 2;
    }
    #pragma unroll
    for (int i = 0; i < NB; i++) {
        int idx = tid + i * 256;
        br[i] = idx / (BN / 4); bc[i] = (idx % (BN / 4)) << 2;
    }
    int sc = tid % BN, sg = tid / BN;
    float s_sum = 0.f, s_sq = 0.f;
    int lm = lane >> 3;
    int loff = (((lane & 7) + (lm & 1) * 8)) * ASP + (lm >> 1) * 4;
    uint32_t as_base = smem_u32(As);

    #define PREFETCH(sidx, k0)                                                     \
        {   _Pragma("unroll")                                                      \
            for (int i = 0; i < NA; i++)                                           \
                cp16(smem_u32(&As[(sidx) * ASZ + ar[i] * ASP + ac[i]]),            \
                     Ap + (size_t)ar[i] * K + (k0) + ac[i]);                       \
            _Pragma("unroll")                                                      \
            for (int i = 0; i < NB; i++)                                           \
                cp16(smem_u32(&Bs[(sidx) * BSZ + br[i] * BSP + bc[i]]),            \
                     Bp + (size_t)((k0) + br[i]) * HW + bc[i]);                    \
        }

    PREFETCH(0, 0); cp_commit();
    if (KT > 1) PREFETCH(1, BK);
    cp_commit();

    for (int kt = 0; kt < KT; kt++) {
        cp_wait1();
        __syncthreads();
        int st = kt % ST;
        const float* bs = Bs + st * BSZ;
        #pragma unroll
        for (int rr = 0; rr < RT; rr++) {
            float v = bs[(sg * RT + rr) * BSP + sc];
            s_sum += v; s_sq += v * v;
        }
        uint32_t abase = as_base + (uint32_t)(st * ASZ + wm * 64 * ASP + loff) * 4;
        #pragma unroll
        for (int s8 = 0; s8 < 2; s8++) {
            uint32_t a[4][4], b[4][2];
            #pragma unroll
            for (int mt = 0; mt < 4; mt++)
                ldsm4(a[mt], abase + (uint32_t)(mt * 16 * ASP + s8 * 8) * 4);
            #pragma unroll
            for (int nt = 0; nt < 4; nt++) {
                const float* bp = bs + (s8 * 8 + (lane & 3)) * BSP
                                     + wn * 32 + nt * 8 + (lane >> 2);
                b[nt][0] = __float_as_uint(bp[0]);
                b[nt][1] = __float_as_uint(bp[4 * BSP]);
            }
            #pragma unroll
            for (int mt = 0; mt < 4; mt++)
                #pragma unroll
                for (int nt = 0; nt < 4; nt++)
                    mma_tf32(acc[mt][nt], a[mt], b[nt]);
        }
        if (kt + 2 < KT) PREFETCH((kt + 2) % ST, (kt + 2) * BK);
        cp_commit();
    }
    #undef PREFETCH

    sst[0][sg][sc] = s_sum;
    sst[1][sg][sc] = s_sq;
    __syncthreads();
    if (tid < BN) {
        float S = 0.f, SS = 0.f;
        #pragma unroll
        for (int g = 0; g < SH; g++) { S += sst[0][g][tid]; SS += sst[1][g][tid]; }
        float m = S * (1.f / 128.f);
        float var = SS * (1.f / 128.f) - m * m;
        sst[0][0][tid] = m;
        sst[1][0][tid] = rsqrtf(var + eps);
    }
    __syncthreads();

    #pragma unroll
    for (int mt = 0; mt < 4; mt++) {
        #pragma unroll
        for (int half = 0; half < 2; half++) {
            int row = m0 + wm * 64 + mt * 16 + (lane >> 2) + half * 8;
            float sgr = Sg[row], cstr = Cst[row];
            #pragma unroll
            for (int nt = 0; nt < 4; nt++) {
                int pl0 = wn * 32 + nt * 8 + (lane & 3) * 2;
                float v0 = acc[mt][nt][half * 2];
                float v1 = acc[mt][nt][half * 2 + 1];
                float mv0 = sst[0][0][pl0],     rv0 = sst[1][0][pl0];
                float mv1 = sst[0][0][pl0 + 1], rv1 = sst[1][0][pl0 + 1];
                v0 = rv0 * v0 + (cstr - mv0 * rv0 * sgr);
                v1 = rv1 * v1 + (cstr - mv1 * rv1 * sgr);
                v0 = v0 / (1.f + __expf(-v0));
                v1 = v1 / (1.f + __expf(-v1));
                size_t idx = ((size_t)u * 256 + row) * HW + n0 + pl0;
                *(uint32_t*)&Yh[idx] = packh2(v0, v1);
            }
        }
    }
}

// ---------------- fp16 GEMM for the pointwise conv (fp16 in/out) ------------
__global__ void __launch_bounds__(256)
gemm_pw_f16(const __half* __restrict__ A, const __half* __restrict__ B,
            const __half* __restrict__ Yh, __half* __restrict__ Y2h,
            const float* __restrict__ bias) {
    constexpr int K = 768, BN = 64, BK = 32, ST = 3;
    constexpr int KT = K / BK;
    constexpr int ASPH = 40;
    constexpr int BSPH = BN + 8;
    constexpr int ASZ = 256 * ASPH;
    constexpr int BSZ = BK * BSPH;
    extern __shared__ __half smh[];
    __half* As = smh;
    __half* Bs = smh + ST * ASZ;

    int tid = threadIdx.x, lane = tid & 31, wid = tid >> 5;
    int wm = wid >> 1, wn = wid & 1;
    int n0 = blockIdx.x * BN, u = blockIdx.z;
    const __half* Bp = B + (size_t)u * K * HW + n0;

    float acc[4][4][4];
    #pragma unroll
    for (int i = 0; i < 4; i++)
        #pragma unroll
        for (int j = 0; j < 4; j++)
            #pragma unroll
            for (int e = 0; e < 4; e++) acc[i][j][e] = 0.f;

    int aro[4], aco[4];
    #pragma unroll
    for (int i = 0; i < 4; i++) {
        int idx = tid + i * 256;
        aro[i] = idx >> 2; aco[i] = (idx & 3) << 3;
    }
    int brw = tid >> 3, bcl = (tid & 7) << 3;

    int arow_l = lane & 15, acol_l = (lane >> 4) << 3;
    int brow_l = (lane & 7) + ((lane >> 3) & 1) * 8;
    uint32_t as_base = smem_u32(As);
    uint32_t bs_base = smem_u32(Bs);

    #define PF16(sidx, k0)                                                         \
        {   _Pragma("unroll")                                                      \
            for (int i = 0; i < 4; i++)                                            \
                cp16(smem_u32(&As[(sidx) * ASZ + aro[i] * ASPH + aco[i]]),         \
                     A + (size_t)aro[i] * K + (k0) + aco[i]);                      \
            cp16(smem_u32(&Bs[(sidx) * BSZ + brw * BSPH + bcl]),                   \
                 Bp + (size_t)((k0) + brw) * HW + bcl);                            \
        }

    PF16(0, 0); cp_commit();
    PF16(1, BK); cp_commit();

    for (int kt = 0; kt < KT; kt++) {
        cp_wait1();
        __syncthreads();
        int st = kt % ST;
        uint32_t abase = as_base + (uint32_t)(st * ASZ + (wm * 64 + arow_l) * ASPH + acol_l) * 2;
        uint32_t bbase = bs_base + (uint32_t)(st * BSZ + brow_l * BSPH + wn * 32) * 2;
        #pragma unroll
        for (int s16 = 0; s16 < 2; s16++) {
            uint32_t a[4][4], b[4][2];
            #pragma unroll
            for (int mt = 0; mt < 4; mt++)
                ldsm4(a[mt], abase + (uint32_t)(mt * 16 * ASPH + s16 * 16) * 2);
            #pragma unroll
            for (int nt = 0; nt < 4; nt++)
                ldsm2t(b[nt], bbase + (uint32_t)(s16 * 16 * BSPH + nt * 8) * 2);
            #pragma unroll
            for (int mt = 0; mt < 4; mt++)
                #pragma unroll
                for (int nt = 0; nt < 4; nt++)
                    mma_f16(acc[mt][nt], a[mt], b[nt]);
        }
        if (kt + 2 < KT) PF16((kt + 2) % ST, (kt + 2) * BK);
        cp_commit();
    }
    #undef PF16

    #pragma unroll
    for (int mt = 0; mt < 4; mt++) {
        #pragma unroll
        for (int half = 0; half < 2; half++) {
            int row = wm * 64 + mt * 16 + (lane >> 2) + half * 8;
            float br2 = bias[row];
            #pragma unroll
            for (int nt = 0; nt < 4; nt++) {
                int p0 = n0 + wn * 32 + nt * 8 + (lane & 3) * 2;
                size_t idx = ((size_t)u * 256 + row) * HW + p0;
                float v0 = acc[mt][nt][half * 2]     + br2;
                float v1 = acc[mt][nt][half * 2 + 1] + br2;
                v0 = v0 / (1.f + __expf(-v0));
                v1 = v1 / (1.f + __expf(-v1));
                __half2 yp = *(const __half2*)&Yh[idx];
                v0 += __low2float(yp);
                v1 += __high2float(yp);
                *(uint32_t*)&Y2h[idx] = packh2(v0, v1);
            }
        }
    }
}

// ---------------- fp16 GEMM: generic WxB, fp32 accumulate-out ---------------
// MODE 1: wo (K=128), dout = v + bias + residual(feats)
// MODE 4: w_out (K=256, B = Y2h), dout += v + bias
template<int K, int MODE>
__global__ void __launch_bounds__(256)
gemm_f16o(const __half* __restrict__ A, const __half* __restrict__ B,
          float* __restrict__ O0,
          const float* __restrict__ X1, const float* __restrict__ X2,
          const float* __restrict__ bias) {
    constexpr int BM = 128, BN = 128, BK = 32, ST = 3;
    constexpr int KT = K / BK;
    constexpr int ASPH = 40;
    constexpr int BSPH = BN + 8;
    constexpr int ASZ = BM * ASPH;
    constexpr int BSZ = BK * BSPH;
    extern __shared__ __half smh[];
    __half* As = smh;
    __half* Bs = smh + ST * ASZ;

    int tid = threadIdx.x, lane = tid & 31, wid = tid >> 5;
    int wm = wid >> 2, wn = wid & 3;
    int n0 = blockIdx.x * BN, u = blockIdx.z;
    const __half* Bp = B + (size_t)u * K * HW + n0;

    float acc[4][4][4];
    #pragma unroll
    for (int i = 0; i < 4; i++)
        #pragma unroll
        for (int j = 0; j < 4; j++)
            #pragma unroll
            for (int e = 0; e < 4; e++) acc[i][j][e] = 0.f;

    int aro[2], aco[2];
    #pragma unroll
    for (int i = 0; i < 2; i++) {
        int idx = tid + i * 256;
        aro[i] = idx >> 2; aco[i] = (idx & 3) << 3;
    }
    int brw[2], bcl[2];
    #pragma unroll
    for (int i = 0; i < 2; i++) {
        int idx = tid + i * 256;
        brw[i] = idx >> 4; bcl[i] = (idx & 15) << 3;
    }

    int arow_l = lane & 15, acol_l = (lane >> 4) << 3;
    int brow_l = (lane & 7) + ((lane >> 3) & 1) * 8;
    uint32_t as_base = smem_u32(As);
    uint32_t bs_base = smem_u32(Bs);

    #define PFW(sidx, k0)                                                          \
        {   _Pragma("unroll")                                                      \
            for (int i = 0; i < 2; i++)                                            \
                cp16(smem_u32(&As[(sidx) * ASZ + aro[i] * ASPH + aco[i]]),         \
                     A + (size_t)aro[i] * K + (k0) + aco[i]);                      \
            _Pragma("unroll")                                                      \
            for (int i = 0; i < 2; i++)                                            \
                cp16(smem_u32(&Bs[(sidx) * BSZ + brw[i] * BSPH + bcl[i]]),         \
                     Bp + (size_t)((k0) + brw[i]) * HW + bcl[i]);                  \
        }

    PFW(0, 0); cp_commit();
    if (KT > 1) PFW(1, BK);
    cp_commit();

    for (int kt = 0; kt < KT; kt++) {
        cp_wait1();
        __syncthreads();
        int st = kt % ST;
        uint32_t abase = as_base + (uint32_t)(st * ASZ + (wm * 64 + arow_l) * ASPH + acol_l) * 2;
        uint32_t bbase = bs_base + (uint32_t)(st * BSZ + brow_l * BSPH + wn * 32) * 2;
        #pragma unroll
        for (int s16 = 0; s16 < 2; s16++) {
            uint32_t a[4][4], b[4][2];
            #pragma unroll
            for (int mt = 0; mt < 4; mt++)
                ldsm4(a[mt], abase + (uint32_t)(mt * 16 * ASPH + s16 * 16) * 2);
            #pragma unroll
            for (int nt = 0; nt < 4; nt++)
                ldsm2t(b[nt], bbase + (uint32_t)(s16 * 16 * BSPH + nt * 8) * 2);
            #pragma unroll
            for (int mt = 0; mt < 4; mt++)
                #pragma unroll
                for (int nt = 0; nt < 4; nt++)
                    mma_f16(acc[mt][nt], a[mt], b[nt]);
        }
        if (kt + 2 < KT) PFW((kt + 2) % ST, (kt + 2) * BK);
        cp_commit();
    }
    #undef PFW

    #pragma unroll
    for (int mt = 0; mt < 4; mt++) {
        #pragma unroll
        for (int half = 0; half < 2; half++) {
            int row = wm * 64 + mt * 16 + (lane >> 2) + half * 8;
            float br2 = bias[row];
            #pragma unroll
            for (int nt = 0; nt < 4; nt++) {
                #pragma unroll
                for (int e = 0; e < 2; e++) {
                    int p = n0 + wn * 32 + nt * 8 + (lane & 3) * 2 + e;
                    float v = acc[mt][nt][half * 2 + e] + br2;
                    size_t idx = ((size_t)u * 128 + row) * HW + p;
                    if (MODE == 1) {
                        float res = ((u < 2 ? X1 : X2))[((size_t)(u & 1) * 128 + row) * HW + p];
                        O0[idx] = v + res;
                    } else {
                        O0[idx] += v;
                    }
                }
            }
        }
    }
}

// ---------------- fp16 flash attention (register-direct P reuse) -------------
#define AT2_QS 0
#define AT2_VS 10240
#define AT2_KT 20480
#define AT2_HALVES 28928
#define ATTN2_SMEM (AT2_HALVES * 2 + 256 * 4 + 32 * 4)

__global__ void __launch_bounds__(256, 2)
attn_f16(const __half* __restrict__ Q, const __half* __restrict__ K,
         const __half* __restrict__ V, __half* __restrict__ O) {
    int blk = blockIdx.x;                  // b*256 + n*64 + h
    int h = blk & 63, n = (blk >> 6) & 3, b = blk >> 8;
    size_t base = ((size_t)(b * 128 + n * 32) * 64 + h) * 256;
    extern __shared__ __half smh2[];
    __half* Qs = smh2 + AT2_QS;
    __half* Vs = smh2 + AT2_VS;
    __half* Kt = smh2 + AT2_KT;
    float* V2 = (float*)(smh2 + AT2_HALVES);
    float* Vsum = V2 + 256;
    int tid = threadIdx.x, lane = tid & 31, w = tid >> 5;

    #pragma unroll 4
    for (int dd = 0; dd < 32; dd++) {
        Qs[tid * 40 + dd] = Q[base + (size_t)dd * HW + tid];
        Vs[tid * 40 + dd] = V[base + (size_t)dd * HW + tid];
    }
    #pragma unroll
    for (int i = 0; i < 4; i++) {
        int idx = tid + i * 256;
        int row = idx >> 5, seg = idx & 31;
        *(uint4*)&Kt[row * 264 + seg * 8] =
            *(const uint4*)&K[base + (size_t)row * HW + seg * 8];
    }
    __syncthreads();
    {
        float s = 0.f;
        #pragma unroll 8
        for (int jj = 0; jj < 32; jj++) s += __half2float(Vs[(w * 32 + jj) * 40 + lane]);
        V2[w * 32 + lane] = s;
    }

    int i0 = w * 32;
    uint32_t qa[2][2][4];
    #pragma unroll
    for (int mt = 0; mt < 2; mt++)
        #pragma unroll
        for (int dk = 0; dk < 2; dk++)
            ldsm4(qa[mt][dk],
                  smem_u32(&Qs[(i0 + mt * 16 + (lane & 15)) * 40 + dk * 16 + ((lane >> 4) << 3)]));
    int brow = (lane & 7) + ((lane >> 3) & 1) * 8;

    float l0[2] = {0.f, 0.f}, l1[2] = {0.f, 0.f};
    float o[2][4][4];
    #pragma unroll
    for (int mt = 0; mt < 2; mt++)
        #pragma unroll
        for (int dt = 0; dt < 4; dt++)
            #pragma unroll
            for (int e = 0; e < 4; e++) o[mt][dt][e] = 0.f;

    for (int j0 = 0; j0 < 256; j0 += 16) {
        float s[2][2][4];
        #pragma unroll
        for (int mt = 0; mt < 2; mt++)
            #pragma unroll
            for (int jh = 0; jh < 2; jh++)
                #pragma unroll
                for (int e = 0; e < 4; e++) s[mt][jh][e] = 0.f;
        uint32_t bS[2][2][2];
        #pragma unroll
        for (int dk = 0; dk < 2; dk++)
            #pragma unroll
            for (int jh = 0; jh < 2; jh++)
                ldsm2t(bS[dk][jh], smem_u32(&Kt[(dk * 16 + brow) * 264 + j0 + jh * 8]));
        #pragma unroll
        for (int mt = 0; mt < 2; mt++)
            #pragma unroll
            for (int jh = 0; jh < 2; jh++)
                #pragma unroll
                for (int dk = 0; dk < 2; dk++)
                    mma_f16(s[mt][jh], qa[mt][dk], bS[dk][jh]);
        uint32_t pa[2][4];
        #pragma unroll
        for (int mt = 0; mt < 2; mt++) {
            float p00 = fexp2(s[mt][0][0]), p01 = fexp2(s[mt][0][1]);
            float p02 = fexp2(s[mt][0][2]), p03 = fexp2(s[mt][0][3]);
            float p10 = fexp2(s[mt][1][0]), p11 = fexp2(s[mt][1][1]);
            float p12 = fexp2(s[mt][1][2]), p13 = fexp2(s[mt][1][3]);
            l0[mt] += p00 + p01 + p10 + p11;
            l1[mt] += p02 + p03 + p12 + p13;
            pa[mt][0] = packh2(p00, p01);
            pa[mt][1] = packh2(p02, p03);
            pa[mt][2] = packh2(p10, p11);
            pa[mt][3] = packh2(p12, p13);
        }
        uint32_t bV[4][2];
        #pragma unroll
        for (int dt = 0; dt < 4; dt++)
            ldsm2t(bV[dt], smem_u32(&Vs[(j0 + brow) * 40 + dt * 8]));
        #pragma unroll
        for (int mt = 0; mt < 2; mt++)
            #pragma unroll
            for (int dt = 0; dt < 4; dt++)
                mma_f16(o[mt][dt], pa[mt], bV[dt]);
    }
    #pragma unroll
    for (int mt = 0; mt < 2; mt++) {
        l0[mt] += __shfl_xor_sync(0xffffffffu, l0[mt], 1);
        l0[mt] += __shfl_xor_sync(0xffffffffu, l0[mt], 2);
        l1[mt] += __shfl_xor_sync(0xffffffffu, l1[mt], 1);
        l1[mt] += __shfl_xor_sync(0xffffffffu, l1[mt], 2);
    }

    __syncthreads();
    float* Ow = (float*)smh2 + w * 32 * 36;
    #pragma unroll
    for (int mt = 0; mt < 2; mt++)
        #pragma unroll
        for (int hf = 0; hf < 2; hf++) {
            float inv = 1.f / (hf == 0 ? l0[mt] : l1[mt]);
            int row = mt * 16 + (lane >> 2) + hf * 8;
            #pragma unroll
            for (int dt = 0; dt < 4; dt++) {
                Ow[row * 36 + dt * 8 + (lane & 3) * 2]     = o[mt][dt][hf * 2]     * inv;
                Ow[row * 36 + dt * 8 + (lane & 3) * 2 + 1] = o[mt][dt][hf * 2 + 1] * inv;
            }
        }
    if (tid < 32) {
        float s = 0.f;
        #pragma unroll
        for (int ww = 0; ww < 8; ww++) s += V2[ww * 32 + tid];
        Vsum[tid] = s;
    }
    __syncthreads();
    const float eps = 1e-6f;
    const float norm = 1.f / (1.f + 256.f * eps);
    #pragma unroll 4
    for (int d = 0; d < 32; d++) {
        float val = (Ow[lane * 36 + d] + eps * Vsum[d]) * norm;
        O[base + (size_t)d * HW + i0 + lane] = __float2half(val);
    }
}

// ---------------- depthwise 3/5/7, register-blocked 2x2, fp16 in/out --------
// 16x64 tiles; thread = (col pair tx, row pair ty); window 8x8 in registers.
__global__ void __launch_bounds__(256)
dw_kernel(const __half* __restrict__ Y,
          const float* __restrict__ w3, const float* __restrict__ b3,
          const float* __restrict__ w5, const float* __restrict__ b5,
          const float* __restrict__ w7, const float* __restrict__ b7,
          __half* __restrict__ F) {
    __shared__ float S[22][72];
    __shared__ float wgt[84];
    int z = blockIdx.z; int ch = z & 255; int u = z >> 8;
    int w0 = blockIdx.x * 64, h0 = blockIdx.y * 16;
    int tid = threadIdx.x;
    if (tid < 9)       wgt[tid] = w3[ch * 9 + tid];
    else if (tid < 34) wgt[tid] = w5[ch * 25 + tid - 9];
    else if (tid < 83) wgt[tid] = w7[ch * 49 + tid - 34];
    const __half* Yp = Y + ((size_t)u * 256 + ch) * HW;
    for (int i = tid; i < 22 * 70; i += 256) {
        int r = i / 70, c = i % 70;
        int gh = h0 - 3 + r, gw = w0 - 3 + c;
        float v = 0.f;
        if ((unsigned)gh < 64u && (unsigned)gw < 256u) v = __half2float(Yp[gh * 256 + gw]);
        S[r][c] = v;
    }
    __syncthreads();
    int tx = tid & 31, ty = tid >> 5;        // col pair 0..31, row pair 0..7
    int r0 = ty * 2, c0 = tx * 2;
    // load 8x8 window (S rows r0..r0+7, cols c0..c0+7) via aligned float2
    float wv[8][8];
    #pragma unroll
    for (int r = 0; r < 8; r++)
        #pragma unroll
        for (int c = 0; c < 4; c++) {
            float2 v2 = *(const float2*)&S[r0 + r][c0 + c * 2];
            wv[r][c * 2] = v2.x; wv[r][c * 2 + 1] = v2.y;
        }
    float bb3 = b3[ch], bb5 = b5[ch], bb7 = b7[ch];
    float f3a[2][2], f5a[2][2], f7a[2][2];
    #pragma unroll
    for (int i = 0; i < 2; i++)
        #pragma unroll
        for (int j = 0; j < 2; j++) { f3a[i][j] = bb3; f5a[i][j] = bb5; f7a[i][j] = bb7; }
    #pragma unroll
    for (int dy = 0; dy < 8; dy++) {
        #pragma unroll
        for (int dx = 0; dx < 8; dx++) {
            float v = wv[dy][dx];
            #pragma unroll
            for (int i = 0; i < 2; i++) {
                int ky = dy - 3 - i;
                if (ky < -3 || ky > 3) continue;
                #pragma unroll
                for (int j = 0; j < 2; j++) {
                    int kx = dx - 3 - j;
                    if (kx < -3 || kx > 3) continue;
                    f7a[i][j] += v * wgt[34 + (ky + 3) * 7 + (kx + 3)];
                    if (ky >= -2 && ky <= 2 && kx >= -2 && kx <= 2)
                        f5a[i][j] += v * wgt[9 + (ky + 2) * 5 + (kx + 2)];
                    if (ky >= -1 && ky <= 1 && kx >= -1 && kx <= 1)
                        f3a[i][j] += v * wgt[(ky + 1) * 3 + (kx + 1)];
                }
            }
        }
    }
    #pragma unroll
    for (int i = 0; i < 2; i++) {
        size_t pix = (size_t)(h0 + r0 + i) * 256 + (w0 + c0);
        size_t ob = (size_t)u * 768 * HW + pix;
        *(uint32_t*)&F[ob + (size_t) ch        * HW] = packh2(f3a[i][0], f3a[i][1]);
        *(uint32_t*)&F[ob + (size_t)(256 + ch) * HW] = packh2(f5a[i][0], f5a[i][1]);
        *(uint32_t*)&F[ob + (size_t)(512 + ch) * HW] = packh2(f7a[i][0], f7a[i][1]);
    }
}

// ---------------- host launcher --------------------------------------------
extern "C" void kernel_launch(void* const* d_in, const int* in_sizes, int n_in,
                              void* d_out, int out_size) {
    const float* feats1 = (const float*)d_in[0];
    const float* feats2 = (const float*)d_in[1];
    const float* an_g  = (const float*)d_in[2];
    const float* an_b  = (const float*)d_in[3];
    const float* anc_g = (const float*)d_in[4];
    const float* anc_b = (const float*)d_in[5];
    const float* wq    = (const float*)d_in[6];
    const float* bq    = (const float*)d_in[7];
    const float* wkv   = (const float*)d_in[8];
    const float* bkv   = (const float*)d_in[9];
    const float* wo    = (const float*)d_in[10];
    const float* bo    = (const float*)d_in[11];
    const float* fn_g  = (const float*)d_in[12];
    const float* fn_b  = (const float*)d_in[13];
    const float* w_in  = (const float*)d_in[14];
    const float* b_in  = (const float*)d_in[15];
    const float* w_dw3 = (const float*)d_in[16];
    const float* b_dw3 = (const float*)d_in[17];
    const float* w_dw5 = (const float*)d_in[18];
    const float* b_dw5 = (const float*)d_in[19];
    const float* w_dw7 = (const float*)d_in[20];
    const float* b_dw7 = (const float*)d_in[21];
    const float* w_pw  = (const float*)d_in[22];
    const float* b_pw  = (const float*)d_in[23];
    const float* w_out = (const float*)d_in[24];
    const float* b_out = (const float*)d_in[25];
    float* dout = (float*)d_out;

    float *WA, *SgA, *CA, *WIN, *SgI, *CI;
    __half *Qh, *Kh, *Vh, *Oh, *Yh, *Y2h, *Fh, *WPWh, *WOh, *WOUTh, *WAh, *X1h, *X2h;
    cudaGetSymbolAddress((void**)&Qh, g_Qh);
    cudaGetSymbolAddress((void**)&Kh, g_Kh);
    cudaGetSymbolAddress((void**)&Vh, g_Vh);
    cudaGetSymbolAddress((void**)&Oh, g_Oh);
    cudaGetSymbolAddress((void**)&Yh, g_Yh);
    cudaGetSymbolAddress((void**)&Y2h, g_Y2h);
    cudaGetSymbolAddress((void**)&Fh, g_Fh);
    cudaGetSymbolAddress((void**)&WPWh, g_WPWh);
    cudaGetSymbolAddress((void**)&WOh, g_WOh);
    cudaGetSymbolAddress((void**)&WOUTh, g_WOUTh);
    cudaGetSymbolAddress((void**)&WAh, g_WAh);
    cudaGetSymbolAddress((void**)&X1h, g_X1h);
    cudaGetSymbolAddress((void**)&X2h, g_X2h);
    cudaGetSymbolAddress((void**)&WA, g_WA);
    cudaGetSymbolAddress((void**)&SgA, g_SgA);
    cudaGetSymbolAddress((void**)&CA, g_CA);
    cudaGetSymbolAddress((void**)&WIN, g_WIN);
    cudaGetSymbolAddress((void**)&SgI, g_SgI);
    cudaGetSymbolAddress((void**)&CI, g_CI);

    const int smB  = 3 * (256 * 20 + 16 * 72)  * 4;   // tf32 BM=256/BN=64
    const int smH  = 3 * (256 * 40 + 32 * 72)  * 2;   // f16 pw
    const int smW  = 3 * (128 * 40 + 32 * 136) * 2;   // f16 BM=128/BN=128
    cudaFuncSetAttribute((const void*)gemm_qkv_f16, cudaFuncAttributeMaxDynamicSharedMemorySize, smW);
    cudaFuncSetAttribute((const void*)gemm_win_tc<128, 256, 64>, cudaFuncAttributeMaxDynamicSharedMemorySize, smB);
    cudaFuncSetAttribute((const void*)gemm_pw_f16, cudaFuncAttributeMaxDynamicSharedMemorySize, smH);
    cudaFuncSetAttribute((const void*)gemm_f16o<128, 1>, cudaFuncAttributeMaxDynamicSharedMemorySize, smW);
    cudaFuncSetAttribute((const void*)gemm_f16o<256, 4>, cudaFuncAttributeMaxDynamicSharedMemorySize, smW);
    cudaFuncSetAttribute((const void*)attn_f16, cudaFuncAttributeMaxDynamicSharedMemorySize, ATTN2_SMEM);

    // 1. weight prep + fp16 conversions (weights + feats)
    prep_kernel<<<640, 128>>>(wq, bq, wkv, bkv, an_g, an_b, anc_g, anc_b,
                              w_in, b_in, fn_g, fn_b);
    convh_kernel<<<768, 256>>>(w_pw, WPWh, 256 * 768);
    convh_kernel<<<64, 256>>>(wo, WOh, 128 * 128);
    convh_kernel<<<128, 256>>>(w_out, WOUTh, 128 * 256);
    convfeats_kernel<<<4096, 256>>>((const float4*)feats1, (const float4*)feats2,
                                    (uint2*)X1h, (uint2*)X2h, 2 * 128 * HW / 4);
    // 2. fp16 fused LN + q/kv projection -> fp16 Q (pre-scaled), K, V
    gemm_qkv_f16<<<dim3(128, 3, 4), 256, smW>>>(WAh, Qh, Kh, Vh, SgA, CA, X1h, X2h, 1e-6f);
    // 3. fp16 flash attention -> fp16 O
    attn_f16<<<1024, 256, ATTN2_SMEM>>>(Qh, Kh, Vh, Oh);
    // 4. fp16 wo projection + residual(feats fp32) -> d_out
    gemm_f16o<128, 1><<<dim3(128, 1, 4), 256, smW>>>(WOh, Oh, dout, feats1, feats2, bo);
    // 5. fused LN + w_in + SiLU -> Yh (fp16, packed stores)
    gemm_win_tc<128, 256, 64><<<dim3(256, 1, 4), 256, smB>>>(WIN, dout, Yh, SgI, CI, 1e-5f);
    // 6. depthwise 3/5/7 (register-blocked 2x2) -> Fh (fp16, packed stores)
    dw_kernel<<<dim3(4, 4, 1024), 256>>>(Yh, w_dw3, b_dw3, w_dw5, b_dw5, w_dw7, b_dw7, Fh);
    // 7. fp16 pointwise GEMM + SiLU + residual(Yh) -> Y2h (fp16, no RMW)
    gemm_pw_f16<<<dim3(256, 1, 4), 256, smH>>>(WPWh, Fh, Yh, Y2h, b_pw);
    // 8. fp16 w_out GEMM (K=256, reads Y2h), d_out +=
    gemm_f16o<256, 4><<<dim3(128, 1, 4), 256, smW>>>(WOUTh, Y2h, dout, nullptr, nullptr, b_out);
}